// round 1
// baseline (speedup 1.0000x reference)
#include <cuda_runtime.h>
#include <cuda_bf16.h>
#include <math.h>

// ---- model constants ----
#define Vv   32000
#define Dd   512
#define Ll   8
#define Hh   4
#define Dh   128
#define Ff   2048
#define Bb   2
#define Tt   1024
#define Nrows (Bb*Tt)          // 2048
#define ND   (Nrows*Dd)        // 1048576
#define NF   (Nrows*Ff)        // 4194304
#define DDm  (Dd*Dd)

// ---- scratch (no allocations allowed; __device__ globals) ----
__device__ float g_h [ND];
__device__ float g_hn[ND];
__device__ float g_x5[5*ND];
__device__ float g_r [ND];
__device__ float g_k [ND];
__device__ float g_v [ND];
__device__ float g_w [ND];
__device__ float g_g [ND];
__device__ float g_y [ND];
__device__ float g_ffn[NF];

// =========================================================================
// embedding gather: h[b,t,:] = embed[tok[b,t],:]   (float4 vectorized)
// =========================================================================
__global__ void embed_kernel(const int* __restrict__ tok,
                             const float* __restrict__ emb,
                             float* __restrict__ h) {
    int idx = blockIdx.x * blockDim.x + threadIdx.x;      // over ND/4
    int row = idx >> 7;                                   // D/4 = 128 per row
    int c4  = idx & 127;
    ((float4*)h)[idx] = ((const float4*)emb)[(size_t)tok[row] * 128 + c4];
}

// =========================================================================
// rmsnorm: o = w * x * rsqrt(mean(x^2)+eps), one block per row, 128 thr
// =========================================================================
__global__ void rmsnorm_kernel(const float* __restrict__ x,
                               const float* __restrict__ w,
                               float* __restrict__ o) {
    int row = blockIdx.x;
    int tid = threadIdx.x;                       // 0..127, float4 each
    float4 a = ((const float4*)(x + (size_t)row * Dd))[tid];
    float ss = a.x*a.x + a.y*a.y + a.z*a.z + a.w*a.w;
    #pragma unroll
    for (int s = 16; s > 0; s >>= 1) ss += __shfl_xor_sync(0xffffffffu, ss, s);
    __shared__ float sred[4];
    if ((tid & 31) == 0) sred[tid >> 5] = ss;
    __syncthreads();
    float tot = sred[0] + sred[1] + sred[2] + sred[3];
    float sc  = rsqrtf(tot * (1.0f / Dd) + 1e-6f);
    float4 wv = ((const float4*)w)[tid];
    float4 r;
    r.x = a.x * sc * wv.x; r.y = a.y * sc * wv.y;
    r.z = a.z * sc * wv.z; r.w = a.w * sc * wv.w;
    ((float4*)(o + (size_t)row * Dd))[tid] = r;
}

// =========================================================================
// token shift + 5-way lerp:  x_j = hn + (shift(hn)-hn) * mix_j
// =========================================================================
__global__ void mix5_kernel(const float* __restrict__ hn,
                            const float* __restrict__ mix,     // [5,D]
                            float* __restrict__ x5) {
    int idx = blockIdx.x * blockDim.x + threadIdx.x;   // over ND
    int row = idx >> 9;
    int c   = idx & 511;
    int t   = row & (Tt - 1);
    float cur  = hn[idx];
    float prev = (t == 0) ? 0.0f : hn[idx - Dd];
    float d    = prev - cur;
    #pragma unroll
    for (int j = 0; j < 5; j++)
        x5[(size_t)j * ND + idx] = fmaf(d, mix[j * Dd + c], cur);
}

// =========================================================================
// activations
// =========================================================================
__global__ void wact_kernel(float* __restrict__ w, const float* __restrict__ w0) {
    int idx = blockIdx.x * blockDim.x + threadIdx.x;   // over ND
    int c = idx & 511;
    w[idx] = expf(-expf(w[idx] + w0[c]));
}
__global__ void silu_kernel(float* __restrict__ g) {
    int idx = blockIdx.x * blockDim.x + threadIdx.x;   // over ND
    float z = g[idx];
    g[idx] = z / (1.0f + expf(-z));
}
__global__ void gelu_kernel(float* __restrict__ x) {
    int idx = blockIdx.x * blockDim.x + threadIdx.x;   // over NF
    float v = x[idx];
    x[idx] = 0.5f * v * (1.0f + erff(v * 0.70710678118654752f));
}

// =========================================================================
// RWKV-6 WKV scan. One block per (b,h). Thread j owns S[:,j] (128 regs).
//   y_t[j] = sum_i r[i]*(S[i][j] + u[i]*k[i]*v[j]) ; S[i][j] = w[i]*S + k[i]*v[j]
// =========================================================================
__global__ void __launch_bounds__(128, 1)
wkv_kernel(const float* __restrict__ r, const float* __restrict__ k,
           const float* __restrict__ v, const float* __restrict__ w,
           const float* __restrict__ u, float* __restrict__ y) {
    int bh = blockIdx.x;
    int b  = bh >> 2;
    int h  = bh & 3;
    int j  = threadIdx.x;
    __shared__ float4 s[Dh];     // (r,k,w,u) per channel i
    float uj = u[h * Dh + j];
    float S[Dh];
    #pragma unroll
    for (int i = 0; i < Dh; i++) S[i] = 0.0f;
    size_t off = (size_t)b * Tt * Dd + h * Dh + j;
    for (int t = 0; t < Tt; t++, off += Dd) {
        float rv = r[off], kv_ = k[off], wv = w[off], vv = v[off];
        __syncthreads();
        s[j] = make_float4(rv, kv_, wv, uj);
        __syncthreads();
        float acc = 0.0f;
        #pragma unroll
        for (int i = 0; i < Dh; i++) {
            float4 q = s[i];
            float kv = q.y * vv;
            acc  = fmaf(q.x, fmaf(q.w, kv, S[i]), acc);
            S[i] = fmaf(q.z, S[i], kv);
        }
        y[off] = acc;
    }
}

// =========================================================================
// per-head GroupNorm + gate: o = (norm(y)*gw + gb) * g ; block per (row,head)
// =========================================================================
__global__ void gn_gate_kernel(const float* __restrict__ y,
                               const float* __restrict__ g,
                               const float* __restrict__ gw,
                               const float* __restrict__ gb,
                               float* __restrict__ o) {
    int grp = blockIdx.x;           // row*4 + h
    int row = grp >> 2, h = grp & 3;
    int j = threadIdx.x;            // 0..127
    size_t off = (size_t)row * Dd + h * Dh + j;
    float yv = y[off];
    float s1 = yv, s2 = yv * yv;
    #pragma unroll
    for (int s = 16; s > 0; s >>= 1) {
        s1 += __shfl_xor_sync(0xffffffffu, s1, s);
        s2 += __shfl_xor_sync(0xffffffffu, s2, s);
    }
    __shared__ float r1[4], r2[4];
    if ((j & 31) == 0) { r1[j >> 5] = s1; r2[j >> 5] = s2; }
    __syncthreads();
    s1 = r1[0] + r1[1] + r1[2] + r1[3];
    s2 = r2[0] + r2[1] + r2[2] + r2[3];
    float mu  = s1 * (1.0f / Dh);
    float var = s2 * (1.0f / Dh) - mu * mu;
    float nrm = (yv - mu) * rsqrtf(var + 1e-5f);
    int c = h * Dh + j;
    o[off] = fmaf(nrm, gw[c], gb[c]) * g[off];
}

// =========================================================================
// tiled fp32 GEMM: C[M,N] (+)= A[M,K] @ B            (all dims divide tiles)
//   BT=false: B is [K,N] row-major.  BT=true: B is [N,K] row-major (NT).
// BM=128 BN=64 BK=16, 256 threads, 8x4 microtile.
// =========================================================================
#define BM 128
#define BN 64
#define BK 16
template<bool ACC, bool BT>
__global__ void __launch_bounds__(256)
gemm_kernel(const float* __restrict__ A, const float* __restrict__ B,
            float* __restrict__ C, int M, int Nn, int K) {
    __shared__ float As[BK][BM];
    __shared__ float Bs[BK][BN];
    int tid = threadIdx.x;
    int m0 = blockIdx.y * BM, n0 = blockIdx.x * BN;
    int tx = tid & 15, ty = tid >> 4;
    float acc[8][4] = {};
    int arow = tid >> 2;           // 0..63 (+64)
    int ak4  = (tid & 3) * 4;
    for (int k0 = 0; k0 < K; k0 += BK) {
        #pragma unroll
        for (int rr = 0; rr < 2; rr++) {
            int r_ = arow + rr * 64;
            float4 av = *(const float4*)(A + (size_t)(m0 + r_) * K + k0 + ak4);
            As[ak4 + 0][r_] = av.x; As[ak4 + 1][r_] = av.y;
            As[ak4 + 2][r_] = av.z; As[ak4 + 3][r_] = av.w;
        }
        if (!BT) {
            int brow = tid >> 4, bc4 = (tid & 15) * 4;
            float4 bv = *(const float4*)(B + (size_t)(k0 + brow) * Nn + n0 + bc4);
            *(float4*)&Bs[brow][bc4] = bv;
        } else {
            int bnr = tid >> 2, bk4 = (tid & 3) * 4;
            float4 bv = *(const float4*)(B + (size_t)(n0 + bnr) * K + k0 + bk4);
            Bs[bk4 + 0][bnr] = bv.x; Bs[bk4 + 1][bnr] = bv.y;
            Bs[bk4 + 2][bnr] = bv.z; Bs[bk4 + 3][bnr] = bv.w;
        }
        __syncthreads();
        #pragma unroll
        for (int kk = 0; kk < BK; kk++) {
            float a[8], b[4];
            #pragma unroll
            for (int i = 0; i < 8; i++) a[i] = As[kk][ty * 8 + i];
            #pragma unroll
            for (int j = 0; j < 4; j++) b[j] = Bs[kk][tx * 4 + j];
            #pragma unroll
            for (int i = 0; i < 8; i++)
                #pragma unroll
                for (int j = 0; j < 4; j++)
                    acc[i][j] = fmaf(a[i], b[j], acc[i][j]);
        }
        __syncthreads();
    }
    #pragma unroll
    for (int i = 0; i < 8; i++) {
        float* crow = C + (size_t)(m0 + ty * 8 + i) * Nn + n0 + tx * 4;
        float4 r;
        if (ACC) {
            float4 cv = *(const float4*)crow;
            r.x = cv.x + acc[i][0]; r.y = cv.y + acc[i][1];
            r.z = cv.z + acc[i][2]; r.w = cv.w + acc[i][3];
        } else {
            r.x = acc[i][0]; r.y = acc[i][1];
            r.z = acc[i][2]; r.w = acc[i][3];
        }
        *(float4*)crow = r;
    }
}

// =========================================================================
// host driver (graph-capturable: kernel launches only)
// =========================================================================
extern "C" void kernel_launch(void* const* d_in, const int* in_sizes, int n_in,
                              void* d_out, int out_size) {
    const int*   tokens = (const int*)  d_in[0];
    const float* embed  = (const float*)d_in[1];
    const float* ln1    = (const float*)d_in[2];
    const float* ln2    = (const float*)d_in[3];
    const float* lno    = (const float*)d_in[4];
    const float* mix    = (const float*)d_in[5];
    const float* Wr     = (const float*)d_in[6];
    const float* Wk     = (const float*)d_in[7];
    const float* Wv     = (const float*)d_in[8];
    const float* Wg     = (const float*)d_in[9];
    const float* Ww     = (const float*)d_in[10];
    const float* w0     = (const float*)d_in[11];
    const float* Wo     = (const float*)d_in[12];
    const float* u      = (const float*)d_in[13];
    const float* gnw    = (const float*)d_in[14];
    const float* gnb    = (const float*)d_in[15];
    const float* W1     = (const float*)d_in[16];
    const float* W2     = (const float*)d_in[17];
    float* out = (float*)d_out;

    float *h, *hn, *x5, *r, *k, *v, *w, *g, *y, *ffn;
    cudaGetSymbolAddress((void**)&h,   g_h);
    cudaGetSymbolAddress((void**)&hn,  g_hn);
    cudaGetSymbolAddress((void**)&x5,  g_x5);
    cudaGetSymbolAddress((void**)&r,   g_r);
    cudaGetSymbolAddress((void**)&k,   g_k);
    cudaGetSymbolAddress((void**)&v,   g_v);
    cudaGetSymbolAddress((void**)&w,   g_w);
    cudaGetSymbolAddress((void**)&g,   g_g);
    cudaGetSymbolAddress((void**)&y,   g_y);
    cudaGetSymbolAddress((void**)&ffn, g_ffn);

    embed_kernel<<<(ND / 4) / 256, 256>>>(tokens, embed, h);

    dim3 grid512(Dd / BN, Nrows / BM);    // N=512 projections / Wo / W2
    dim3 gridF  (Ff / BN, Nrows / BM);    // N=2048 (W1)
    dim3 gridV  (Vv / BN, Nrows / BM);    // logits

    for (int l = 0; l < Ll; l++) {
        rmsnorm_kernel<<<Nrows, 128>>>(h, ln1 + l * Dd, hn);
        mix5_kernel<<<ND / 256, 256>>>(hn, mix + (size_t)l * 5 * Dd, x5);

        gemm_kernel<false, false><<<grid512, 256>>>(x5 + 0 * (size_t)ND, Wr + (size_t)l * DDm, r, Nrows, Dd, Dd);
        gemm_kernel<false, false><<<grid512, 256>>>(x5 + 1 * (size_t)ND, Wk + (size_t)l * DDm, k, Nrows, Dd, Dd);
        gemm_kernel<false, false><<<grid512, 256>>>(x5 + 2 * (size_t)ND, Wv + (size_t)l * DDm, v, Nrows, Dd, Dd);
        gemm_kernel<false, false><<<grid512, 256>>>(x5 + 3 * (size_t)ND, Ww + (size_t)l * DDm, w, Nrows, Dd, Dd);
        gemm_kernel<false, false><<<grid512, 256>>>(x5 + 4 * (size_t)ND, Wg + (size_t)l * DDm, g, Nrows, Dd, Dd);

        wact_kernel<<<ND / 256, 256>>>(w, w0 + l * Dd);
        silu_kernel<<<ND / 256, 256>>>(g);

        wkv_kernel<<<Bb * Hh, 128>>>(r, k, v, w, u + l * Hh * Dh, y);

        gn_gate_kernel<<<Nrows * Hh, 128>>>(y, g, gnw + l * Dd, gnb + l * Dd, hn);
        gemm_kernel<true, false><<<grid512, 256>>>(hn, Wo + (size_t)l * DDm, h, Nrows, Dd, Dd);

        rmsnorm_kernel<<<Nrows, 128>>>(h, ln2 + l * Dd, hn);
        gemm_kernel<false, false><<<gridF, 256>>>(hn, W1 + (size_t)l * Dd * Ff, ffn, Nrows, Ff, Dd);
        gelu_kernel<<<NF / 256, 256>>>(ffn);
        gemm_kernel<true, false><<<grid512, 256>>>(ffn, W2 + (size_t)l * Ff * Dd, h, Nrows, Dd, Ff);
    }

    rmsnorm_kernel<<<Nrows, 128>>>(h, lno, hn);
    gemm_kernel<false, true><<<gridV, 256>>>(hn, embed, out, Nrows, Vv, Dd);
}

// round 2
// speedup vs baseline: 2.0693x; 2.0693x over previous
#include <cuda_runtime.h>
#include <cuda_bf16.h>
#include <math.h>

// ---- model constants ----
#define Vv   32000
#define Dd   512
#define Ll   8
#define Hh   4
#define Dh   128
#define Ff   2048
#define Bb   2
#define Tt   1024
#define Nrows (Bb*Tt)          // 2048
#define ND   (Nrows*Dd)        // 1048576
#define NF   (Nrows*Ff)        // 4194304
#define DDm  (Dd*Dd)
#define CSZ  16                // wkv chunk length
#define NCH  (Tt/CSZ)          // 64 chunks

// ---- scratch (no allocations allowed; __device__ globals) ----
__device__ float g_h [ND];
__device__ float g_hn[ND];
__device__ float g_x5[5*ND];
__device__ float g_r [ND];
__device__ float g_k [ND];
__device__ float g_v [ND];
__device__ float g_w [ND];
__device__ float g_g [ND];
__device__ float g_y [ND];
__device__ float g_ffn[NF];
__device__ float g_Sb[(size_t)Bb*Hh*NCH*Dh*Dh];   // per-chunk state matrices
__device__ float g_wt[Bb*Hh*NCH*Dh];              // per-chunk total decay

// =========================================================================
// embedding gather
// =========================================================================
__global__ void embed_kernel(const int* __restrict__ tok,
                             const float* __restrict__ emb,
                             float* __restrict__ h) {
    int idx = blockIdx.x * blockDim.x + threadIdx.x;      // over ND/4
    int row = idx >> 7;
    int c4  = idx & 127;
    ((float4*)h)[idx] = ((const float4*)emb)[(size_t)tok[row] * 128 + c4];
}

// =========================================================================
// rmsnorm
// =========================================================================
__global__ void rmsnorm_kernel(const float* __restrict__ x,
                               const float* __restrict__ w,
                               float* __restrict__ o) {
    int row = blockIdx.x;
    int tid = threadIdx.x;
    float4 a = ((const float4*)(x + (size_t)row * Dd))[tid];
    float ss = a.x*a.x + a.y*a.y + a.z*a.z + a.w*a.w;
    #pragma unroll
    for (int s = 16; s > 0; s >>= 1) ss += __shfl_xor_sync(0xffffffffu, ss, s);
    __shared__ float sred[4];
    if ((tid & 31) == 0) sred[tid >> 5] = ss;
    __syncthreads();
    float tot = sred[0] + sred[1] + sred[2] + sred[3];
    float sc  = rsqrtf(tot * (1.0f / Dd) + 1e-6f);
    float4 wv = ((const float4*)w)[tid];
    float4 r;
    r.x = a.x * sc * wv.x; r.y = a.y * sc * wv.y;
    r.z = a.z * sc * wv.z; r.w = a.w * sc * wv.w;
    ((float4*)(o + (size_t)row * Dd))[tid] = r;
}

// =========================================================================
// token shift + 5-way lerp
// =========================================================================
__global__ void mix5_kernel(const float* __restrict__ hn,
                            const float* __restrict__ mix,
                            float* __restrict__ x5) {
    int idx = blockIdx.x * blockDim.x + threadIdx.x;
    int row = idx >> 9;
    int c   = idx & 511;
    int t   = row & (Tt - 1);
    float cur  = hn[idx];
    float prev = (t == 0) ? 0.0f : hn[idx - Dd];
    float d    = prev - cur;
    #pragma unroll
    for (int j = 0; j < 5; j++)
        x5[(size_t)j * ND + idx] = fmaf(d, mix[j * Dd + c], cur);
}

// =========================================================================
// WKV phase 1: per-chunk local recurrence (parallel over B*H*NCH blocks).
// Outputs: y (local part), r overwritten with r~ = r * prod(w before t),
//          Sb[chunk] = local end state, wt[chunk] = total decay per channel.
// =========================================================================
__global__ void __launch_bounds__(128, 3)
wkv_chunk_kernel(float* __restrict__ r, const float* __restrict__ k,
                 const float* __restrict__ v, const float* __restrict__ w,
                 const float* __restrict__ u, float* __restrict__ y,
                 float* __restrict__ Sb, float* __restrict__ wt) {
    int blk = blockIdx.x;
    int bh  = blk / NCH;
    int ch  = blk % NCH;
    int b = bh >> 2, h = bh & 3;
    int j = threadIdx.x;
    __shared__ float4 s[Dh];
    float uj = u[h * Dh + j];
    float S[Dh];
    #pragma unroll
    for (int i = 0; i < Dh; i++) S[i] = 0.0f;
    float p = 1.0f;
    size_t off = (size_t)b * Tt * Dd + (size_t)(ch * CSZ) * Dd + h * Dh + j;
    for (int t = 0; t < CSZ; t++, off += Dd) {
        float rv = r[off], kv_ = k[off], wv = w[off], vv = v[off];
        __syncthreads();
        s[j] = make_float4(rv, kv_, wv, uj);
        __syncthreads();
        r[off] = rv * p;        // r~ for inter-chunk pass
        p *= wv;
        float acc = 0.0f;
        #pragma unroll
        for (int i = 0; i < Dh; i++) {
            float4 q = s[i];
            float kv = q.y * vv;
            acc  = fmaf(q.x, fmaf(q.w, kv, S[i]), acc);
            S[i] = fmaf(q.z, S[i], kv);
        }
        y[off] = acc;
    }
    wt[blk * Dh + j] = p;
    size_t base = (size_t)blk * Dh * Dh;
    #pragma unroll
    for (int i = 0; i < Dh; i++) Sb[base + (size_t)i * Dh + j] = S[i];
}

// =========================================================================
// WKV phase 2: sequential combine over chunks (8 blocks).
// In-place: Sb[chunk] := state at chunk START; run := D(wt)*run + M.
// =========================================================================
__global__ void __launch_bounds__(128, 1)
wkv_combine_kernel(float* __restrict__ Sb, const float* __restrict__ wt) {
    int bh = blockIdx.x;
    int j  = threadIdx.x;
    __shared__ float sw[Dh];
    float run[Dh];
    #pragma unroll
    for (int i = 0; i < Dh; i++) run[i] = 0.0f;
    for (int ch = 0; ch < NCH; ch++) {
        int blk = bh * NCH + ch;
        __syncthreads();
        sw[j] = wt[blk * Dh + j];
        __syncthreads();
        size_t base = (size_t)blk * Dh * Dh;
        #pragma unroll
        for (int i = 0; i < Dh; i++) {
            float m = Sb[base + (size_t)i * Dh + j];
            Sb[base + (size_t)i * Dh + j] = run[i];
            run[i] = fmaf(run[i], sw[i], m);
        }
    }
}

// =========================================================================
// WKV phase 3: y += r~_t . S_chunkstart  (parallel over B*H*NCH blocks)
// =========================================================================
__global__ void __launch_bounds__(128, 3)
wkv_inter_kernel(const float* __restrict__ rt, const float* __restrict__ Sb,
                 float* __restrict__ y) {
    int blk = blockIdx.x;
    int bh  = blk / NCH;
    int ch  = blk % NCH;
    int b = bh >> 2, h = bh & 3;
    int j = threadIdx.x;
    float Scol[Dh];
    size_t base = (size_t)blk * Dh * Dh;
    #pragma unroll
    for (int i = 0; i < Dh; i++) Scol[i] = Sb[base + (size_t)i * Dh + j];
    __shared__ float sr[Dh];
    size_t off = (size_t)b * Tt * Dd + (size_t)(ch * CSZ) * Dd + h * Dh + j;
    for (int t = 0; t < CSZ; t++, off += Dd) {
        __syncthreads();
        sr[j] = rt[off];
        __syncthreads();
        float acc = y[off];
        #pragma unroll
        for (int i = 0; i < Dh; i++) acc = fmaf(sr[i], Scol[i], acc);
        y[off] = acc;
    }
}

// =========================================================================
// per-head GroupNorm + gate
// =========================================================================
__global__ void gn_gate_kernel(const float* __restrict__ y,
                               const float* __restrict__ g,
                               const float* __restrict__ gw,
                               const float* __restrict__ gb,
                               float* __restrict__ o) {
    int grp = blockIdx.x;
    int row = grp >> 2, h = grp & 3;
    int j = threadIdx.x;
    size_t off = (size_t)row * Dd + h * Dh + j;
    float yv = y[off];
    float s1 = yv, s2 = yv * yv;
    #pragma unroll
    for (int s = 16; s > 0; s >>= 1) {
        s1 += __shfl_xor_sync(0xffffffffu, s1, s);
        s2 += __shfl_xor_sync(0xffffffffu, s2, s);
    }
    __shared__ float r1[4], r2[4];
    if ((j & 31) == 0) { r1[j >> 5] = s1; r2[j >> 5] = s2; }
    __syncthreads();
    s1 = r1[0] + r1[1] + r1[2] + r1[3];
    s2 = r2[0] + r2[1] + r2[2] + r2[3];
    float mu  = s1 * (1.0f / Dh);
    float var = s2 * (1.0f / Dh) - mu * mu;
    float nrm = (yv - mu) * rsqrtf(var + 1e-5f);
    int c = h * Dh + j;
    o[off] = fmaf(nrm, gw[c], gb[c]) * g[off];
}

// =========================================================================
// GEMM core: 128x128x16 tiles, 256 threads, 8x8 microtile, double-buffered.
// =========================================================================
#define BM 128
#define BN 128
#define BK 16

struct GemmRegs {
    float4 a0, a1;   // A prefetch (two rows)
    float4 b0, b1;   // B prefetch
};

// EPI: 0 = store, 1 = accumulate-store, 2 = gelu-store
template<int EPI, bool BT>
__global__ void __launch_bounds__(256)
gemm128(const float* __restrict__ A, const float* __restrict__ B,
        float* __restrict__ C, int M, int N, int K) {
    __shared__ float As[2][BK][BM];
    __shared__ float Bs[2][BK][BN];
    int tid = threadIdx.x;
    int m0 = blockIdx.y * BM, n0 = blockIdx.x * BN;
    int tx = tid & 15, ty = tid >> 4;

    int ar  = tid >> 2;            // 0..63 (A rows, +64)
    int ak4 = (tid & 3) * 4;
    int bkb = tid >> 4;            // 0..15 (B NN row)
    int bnc = (tid & 15) * 8;

    float acc[8][8];
    #pragma unroll
    for (int i = 0; i < 8; i++)
        #pragma unroll
        for (int jj = 0; jj < 8; jj++) acc[i][jj] = 0.0f;

    GemmRegs rg;
    int kt = K / BK;

    // --- prologue: load tile 0 ---
    {
        int k0 = 0;
        rg.a0 = *(const float4*)(A + (size_t)(m0 + ar) * K + k0 + ak4);
        rg.a1 = *(const float4*)(A + (size_t)(m0 + ar + 64) * K + k0 + ak4);
        if (!BT) {
            rg.b0 = *(const float4*)(B + (size_t)(k0 + bkb) * N + n0 + bnc);
            rg.b1 = *(const float4*)(B + (size_t)(k0 + bkb) * N + n0 + bnc + 4);
        } else {
            rg.b0 = *(const float4*)(B + (size_t)(n0 + ar) * K + k0 + ak4);
            rg.b1 = *(const float4*)(B + (size_t)(n0 + ar + 64) * K + k0 + ak4);
        }
        As[0][ak4 + 0][ar] = rg.a0.x; As[0][ak4 + 1][ar] = rg.a0.y;
        As[0][ak4 + 2][ar] = rg.a0.z; As[0][ak4 + 3][ar] = rg.a0.w;
        As[0][ak4 + 0][ar + 64] = rg.a1.x; As[0][ak4 + 1][ar + 64] = rg.a1.y;
        As[0][ak4 + 2][ar + 64] = rg.a1.z; As[0][ak4 + 3][ar + 64] = rg.a1.w;
        if (!BT) {
            *(float4*)&Bs[0][bkb][bnc]     = rg.b0;
            *(float4*)&Bs[0][bkb][bnc + 4] = rg.b1;
        } else {
            Bs[0][ak4 + 0][ar] = rg.b0.x; Bs[0][ak4 + 1][ar] = rg.b0.y;
            Bs[0][ak4 + 2][ar] = rg.b0.z; Bs[0][ak4 + 3][ar] = rg.b0.w;
            Bs[0][ak4 + 0][ar + 64] = rg.b1.x; Bs[0][ak4 + 1][ar + 64] = rg.b1.y;
            Bs[0][ak4 + 2][ar + 64] = rg.b1.z; Bs[0][ak4 + 3][ar + 64] = rg.b1.w;
        }
    }
    __syncthreads();

    for (int t = 0; t < kt; t++) {
        int cur = t & 1, nxt = cur ^ 1;
        if (t + 1 < kt) {
            int k0 = (t + 1) * BK;
            rg.a0 = *(const float4*)(A + (size_t)(m0 + ar) * K + k0 + ak4);
            rg.a1 = *(const float4*)(A + (size_t)(m0 + ar + 64) * K + k0 + ak4);
            if (!BT) {
                rg.b0 = *(const float4*)(B + (size_t)(k0 + bkb) * N + n0 + bnc);
                rg.b1 = *(const float4*)(B + (size_t)(k0 + bkb) * N + n0 + bnc + 4);
            } else {
                rg.b0 = *(const float4*)(B + (size_t)(n0 + ar) * K + k0 + ak4);
                rg.b1 = *(const float4*)(B + (size_t)(n0 + ar + 64) * K + k0 + ak4);
            }
        }
        #pragma unroll
        for (int kk = 0; kk < BK; kk++) {
            float4 a0 = *(const float4*)&As[cur][kk][ty * 8];
            float4 a1 = *(const float4*)&As[cur][kk][ty * 8 + 4];
            float4 b0 = *(const float4*)&Bs[cur][kk][tx * 8];
            float4 b1 = *(const float4*)&Bs[cur][kk][tx * 8 + 4];
            float av[8] = {a0.x, a0.y, a0.z, a0.w, a1.x, a1.y, a1.z, a1.w};
            float bv[8] = {b0.x, b0.y, b0.z, b0.w, b1.x, b1.y, b1.z, b1.w};
            #pragma unroll
            for (int i = 0; i < 8; i++)
                #pragma unroll
                for (int jj = 0; jj < 8; jj++)
                    acc[i][jj] = fmaf(av[i], bv[jj], acc[i][jj]);
        }
        if (t + 1 < kt) {
            As[nxt][ak4 + 0][ar] = rg.a0.x; As[nxt][ak4 + 1][ar] = rg.a0.y;
            As[nxt][ak4 + 2][ar] = rg.a0.z; As[nxt][ak4 + 3][ar] = rg.a0.w;
            As[nxt][ak4 + 0][ar + 64] = rg.a1.x; As[nxt][ak4 + 1][ar + 64] = rg.a1.y;
            As[nxt][ak4 + 2][ar + 64] = rg.a1.z; As[nxt][ak4 + 3][ar + 64] = rg.a1.w;
            if (!BT) {
                *(float4*)&Bs[nxt][bkb][bnc]     = rg.b0;
                *(float4*)&Bs[nxt][bkb][bnc + 4] = rg.b1;
            } else {
                Bs[nxt][ak4 + 0][ar] = rg.b0.x; Bs[nxt][ak4 + 1][ar] = rg.b0.y;
                Bs[nxt][ak4 + 2][ar] = rg.b0.z; Bs[nxt][ak4 + 3][ar] = rg.b0.w;
                Bs[nxt][ak4 + 0][ar + 64] = rg.b1.x; Bs[nxt][ak4 + 1][ar + 64] = rg.b1.y;
                Bs[nxt][ak4 + 2][ar + 64] = rg.b1.z; Bs[nxt][ak4 + 3][ar + 64] = rg.b1.w;
            }
        }
        __syncthreads();
    }

    #pragma unroll
    for (int i = 0; i < 8; i++) {
        float* crow = C + (size_t)(m0 + ty * 8 + i) * N + n0 + tx * 8;
        #pragma unroll
        for (int half = 0; half < 2; half++) {
            float4 rv;
            rv.x = acc[i][half * 4 + 0]; rv.y = acc[i][half * 4 + 1];
            rv.z = acc[i][half * 4 + 2]; rv.w = acc[i][half * 4 + 3];
            if (EPI == 1) {
                float4 cv = *(const float4*)(crow + half * 4);
                rv.x += cv.x; rv.y += cv.y; rv.z += cv.z; rv.w += cv.w;
            } else if (EPI == 2) {
                rv.x = 0.5f * rv.x * (1.0f + erff(rv.x * 0.70710678118654752f));
                rv.y = 0.5f * rv.y * (1.0f + erff(rv.y * 0.70710678118654752f));
                rv.z = 0.5f * rv.z * (1.0f + erff(rv.z * 0.70710678118654752f));
                rv.w = 0.5f * rv.w * (1.0f + erff(rv.w * 0.70710678118654752f));
            }
            *(float4*)(crow + half * 4) = rv;
        }
    }
}

// =========================================================================
// batched 5-projection GEMM: z selects (A slice, B, C, epilogue). K=N=512.
// =========================================================================
__global__ void __launch_bounds__(256)
proj_gemm(const float* __restrict__ x5,
          const float* __restrict__ Wr, const float* __restrict__ Wk,
          const float* __restrict__ Wv, const float* __restrict__ Ww,
          const float* __restrict__ Wg, const float* __restrict__ w0,
          float* __restrict__ Cr, float* __restrict__ Ck,
          float* __restrict__ Cv, float* __restrict__ Cw,
          float* __restrict__ Cg) {
    const int K = Dd, N = Dd;
    int z = blockIdx.z;
    const float* A = x5 + (size_t)z * ND;
    const float* B = (z == 0) ? Wr : (z == 1) ? Wk : (z == 2) ? Wv :
                     (z == 3) ? Ww : Wg;
    float* C = (z == 0) ? Cr : (z == 1) ? Ck : (z == 2) ? Cv :
               (z == 3) ? Cw : Cg;

    __shared__ float As[2][BK][BM];
    __shared__ float Bs[2][BK][BN];
    int tid = threadIdx.x;
    int m0 = blockIdx.y * BM, n0 = blockIdx.x * BN;
    int tx = tid & 15, ty = tid >> 4;
    int ar  = tid >> 2;
    int ak4 = (tid & 3) * 4;
    int bkb = tid >> 4;
    int bnc = (tid & 15) * 8;

    float acc[8][8];
    #pragma unroll
    for (int i = 0; i < 8; i++)
        #pragma unroll
        for (int jj = 0; jj < 8; jj++) acc[i][jj] = 0.0f;

    float4 ra0, ra1, rb0, rb1;
    const int kt = K / BK;
    ra0 = *(const float4*)(A + (size_t)(m0 + ar) * K + ak4);
    ra1 = *(const float4*)(A + (size_t)(m0 + ar + 64) * K + ak4);
    rb0 = *(const float4*)(B + (size_t)bkb * N + n0 + bnc);
    rb1 = *(const float4*)(B + (size_t)bkb * N + n0 + bnc + 4);
    As[0][ak4 + 0][ar] = ra0.x; As[0][ak4 + 1][ar] = ra0.y;
    As[0][ak4 + 2][ar] = ra0.z; As[0][ak4 + 3][ar] = ra0.w;
    As[0][ak4 + 0][ar + 64] = ra1.x; As[0][ak4 + 1][ar + 64] = ra1.y;
    As[0][ak4 + 2][ar + 64] = ra1.z; As[0][ak4 + 3][ar + 64] = ra1.w;
    *(float4*)&Bs[0][bkb][bnc]     = rb0;
    *(float4*)&Bs[0][bkb][bnc + 4] = rb1;
    __syncthreads();

    for (int t = 0; t < kt; t++) {
        int cur = t & 1, nxt = cur ^ 1;
        if (t + 1 < kt) {
            int k0 = (t + 1) * BK;
            ra0 = *(const float4*)(A + (size_t)(m0 + ar) * K + k0 + ak4);
            ra1 = *(const float4*)(A + (size_t)(m0 + ar + 64) * K + k0 + ak4);
            rb0 = *(const float4*)(B + (size_t)(k0 + bkb) * N + n0 + bnc);
            rb1 = *(const float4*)(B + (size_t)(k0 + bkb) * N + n0 + bnc + 4);
        }
        #pragma unroll
        for (int kk = 0; kk < BK; kk++) {
            float4 a0 = *(const float4*)&As[cur][kk][ty * 8];
            float4 a1 = *(const float4*)&As[cur][kk][ty * 8 + 4];
            float4 b0 = *(const float4*)&Bs[cur][kk][tx * 8];
            float4 b1 = *(const float4*)&Bs[cur][kk][tx * 8 + 4];
            float av[8] = {a0.x, a0.y, a0.z, a0.w, a1.x, a1.y, a1.z, a1.w};
            float bv[8] = {b0.x, b0.y, b0.z, b0.w, b1.x, b1.y, b1.z, b1.w};
            #pragma unroll
            for (int i = 0; i < 8; i++)
                #pragma unroll
                for (int jj = 0; jj < 8; jj++)
                    acc[i][jj] = fmaf(av[i], bv[jj], acc[i][jj]);
        }
        if (t + 1 < kt) {
            As[nxt][ak4 + 0][ar] = ra0.x; As[nxt][ak4 + 1][ar] = ra0.y;
            As[nxt][ak4 + 2][ar] = ra0.z; As[nxt][ak4 + 3][ar] = ra0.w;
            As[nxt][ak4 + 0][ar + 64] = ra1.x; As[nxt][ak4 + 1][ar + 64] = ra1.y;
            As[nxt][ak4 + 2][ar + 64] = ra1.z; As[nxt][ak4 + 3][ar + 64] = ra1.w;
            *(float4*)&Bs[nxt][bkb][bnc]     = rb0;
            *(float4*)&Bs[nxt][bkb][bnc + 4] = rb1;
        }
        __syncthreads();
    }

    #pragma unroll
    for (int i = 0; i < 8; i++) {
        float* crow = C + (size_t)(m0 + ty * 8 + i) * N + n0 + tx * 8;
        #pragma unroll
        for (int half = 0; half < 2; half++) {
            float4 rv;
            rv.x = acc[i][half * 4 + 0]; rv.y = acc[i][half * 4 + 1];
            rv.z = acc[i][half * 4 + 2]; rv.w = acc[i][half * 4 + 3];
            if (z == 3) {                 // w decay activation
                int c = n0 + tx * 8 + half * 4;
                rv.x = expf(-expf(rv.x + w0[c + 0]));
                rv.y = expf(-expf(rv.y + w0[c + 1]));
                rv.z = expf(-expf(rv.z + w0[c + 2]));
                rv.w = expf(-expf(rv.w + w0[c + 3]));
            } else if (z == 4) {          // silu
                rv.x = rv.x / (1.0f + expf(-rv.x));
                rv.y = rv.y / (1.0f + expf(-rv.y));
                rv.z = rv.z / (1.0f + expf(-rv.z));
                rv.w = rv.w / (1.0f + expf(-rv.w));
            }
            *(float4*)(crow + half * 4) = rv;
        }
    }
}

// =========================================================================
// host driver
// =========================================================================
extern "C" void kernel_launch(void* const* d_in, const int* in_sizes, int n_in,
                              void* d_out, int out_size) {
    const int*   tokens = (const int*)  d_in[0];
    const float* embed  = (const float*)d_in[1];
    const float* ln1    = (const float*)d_in[2];
    const float* ln2    = (const float*)d_in[3];
    const float* lno    = (const float*)d_in[4];
    const float* mix    = (const float*)d_in[5];
    const float* Wr     = (const float*)d_in[6];
    const float* Wk     = (const float*)d_in[7];
    const float* Wv     = (const float*)d_in[8];
    const float* Wg     = (const float*)d_in[9];
    const float* Ww     = (const float*)d_in[10];
    const float* w0     = (const float*)d_in[11];
    const float* Wo     = (const float*)d_in[12];
    const float* u      = (const float*)d_in[13];
    const float* gnw    = (const float*)d_in[14];
    const float* gnb    = (const float*)d_in[15];
    const float* W1     = (const float*)d_in[16];
    const float* W2     = (const float*)d_in[17];
    float* out = (float*)d_out;

    float *h, *hn, *x5, *r, *k, *v, *w, *g, *y, *ffn, *Sb, *wt;
    cudaGetSymbolAddress((void**)&h,   g_h);
    cudaGetSymbolAddress((void**)&hn,  g_hn);
    cudaGetSymbolAddress((void**)&x5,  g_x5);
    cudaGetSymbolAddress((void**)&r,   g_r);
    cudaGetSymbolAddress((void**)&k,   g_k);
    cudaGetSymbolAddress((void**)&v,   g_v);
    cudaGetSymbolAddress((void**)&w,   g_w);
    cudaGetSymbolAddress((void**)&g,   g_g);
    cudaGetSymbolAddress((void**)&y,   g_y);
    cudaGetSymbolAddress((void**)&ffn, g_ffn);
    cudaGetSymbolAddress((void**)&Sb,  g_Sb);
    cudaGetSymbolAddress((void**)&wt,  g_wt);

    embed_kernel<<<(ND / 4) / 256, 256>>>(tokens, embed, h);

    dim3 gridProj(Dd / BN, Nrows / BM, 5);   // 4 x 16 x 5
    dim3 grid512 (Dd / BN, Nrows / BM);      // 4 x 16
    dim3 gridF   (Ff / BN, Nrows / BM);      // 16 x 16
    dim3 gridV   (Vv / BN, Nrows / BM);      // 250 x 16

    for (int l = 0; l < Ll; l++) {
        rmsnorm_kernel<<<Nrows, 128>>>(h, ln1 + l * Dd, hn);
        mix5_kernel<<<ND / 256, 256>>>(hn, mix + (size_t)l * 5 * Dd, x5);

        proj_gemm<<<gridProj, 256>>>(x5,
            Wr + (size_t)l * DDm, Wk + (size_t)l * DDm, Wv + (size_t)l * DDm,
            Ww + (size_t)l * DDm, Wg + (size_t)l * DDm, w0 + l * Dd,
            r, k, v, w, g);

        wkv_chunk_kernel  <<<Bb * Hh * NCH, 128>>>(r, k, v, w, u + l * Hh * Dh, y, Sb, wt);
        wkv_combine_kernel<<<Bb * Hh,       128>>>(Sb, wt);
        wkv_inter_kernel  <<<Bb * Hh * NCH, 128>>>(r, Sb, y);

        gn_gate_kernel<<<Nrows * Hh, 128>>>(y, g, gnw + l * Dd, gnb + l * Dd, hn);
        gemm128<1, false><<<grid512, 256>>>(hn, Wo + (size_t)l * DDm, h, Nrows, Dd, Dd);

        rmsnorm_kernel<<<Nrows, 128>>>(h, ln2 + l * Dd, hn);
        gemm128<2, false><<<gridF, 256>>>(hn, W1 + (size_t)l * Dd * Ff, ffn, Nrows, Ff, Dd);
        gemm128<1, false><<<grid512, 256>>>(ffn, W2 + (size_t)l * Ff * Dd, h, Nrows, Dd, Ff);
    }

    rmsnorm_kernel<<<Nrows, 128>>>(h, lno, hn);
    gemm128<0, true><<<gridV, 256>>>(hn, embed, out, Nrows, Vv, Dd);
}

// round 4
// speedup vs baseline: 3.6928x; 1.7846x over previous
#include <cuda_runtime.h>
#include <cuda_bf16.h>
#include <math.h>
#include <stdint.h>

// ---- model constants ----
#define Vv   32000
#define Dd   512
#define Ll   8
#define Hh   4
#define Dh   128
#define Ff   2048
#define Bb   2
#define Tt   1024
#define Nrows (Bb*Tt)          // 2048
#define ND   (Nrows*Dd)        // 1048576
#define NF   (Nrows*Ff)        // 4194304
#define DDm  (Dd*Dd)
#define CSZ  16                // wkv chunk length
#define NCH  (Tt/CSZ)          // 64 chunks

// ---- fp32 scratch ----
__device__ float g_h [ND];
__device__ float g_hn[ND];
__device__ float g_r [ND];
__device__ float g_k [ND];
__device__ float g_v [ND];
__device__ float g_w [ND];
__device__ float g_g [ND];
__device__ float g_y [ND];
__device__ float g_Sb[(size_t)Bb*Hh*NCH*Dh*Dh];
__device__ float g_wt[Bb*Hh*NCH*Dh];

// ---- bf16 hi/lo activation buffers ([M][K] row-major) ----
__device__ __nv_bfloat16 g_x5h[5*ND], g_x5l[5*ND];
__device__ __nv_bfloat16 g_ffh[NF],  g_ffl[NF];
__device__ __nv_bfloat16 g_hnh[ND],  g_hnl[ND];
__device__ __nv_bfloat16 g_gnh[ND],  g_gnl[ND];

// ---- bf16 hi/lo transposed weight caches ([N][K] row-major) ----
__device__ __nv_bfloat16 g_pTh[(size_t)Ll*5*DDm], g_pTl[(size_t)Ll*5*DDm];
__device__ __nv_bfloat16 g_oTh[(size_t)Ll*DDm],   g_oTl[(size_t)Ll*DDm];
__device__ __nv_bfloat16 g_1Th[(size_t)Ll*Dd*Ff], g_1Tl[(size_t)Ll*Dd*Ff];
__device__ __nv_bfloat16 g_2Th[(size_t)Ll*Ff*Dd], g_2Tl[(size_t)Ll*Ff*Dd];
__device__ __nv_bfloat16 g_eh[(size_t)Vv*Dd],     g_el[(size_t)Vv*Dd];

// =========================================================================
// PTX helpers (all baseline sm_80+ features — legal on compute_103)
// =========================================================================
__device__ __forceinline__ uint32_t s2u(const void* p) {
    uint32_t a;
    asm("{ .reg .u64 t; cvta.to.shared.u64 t, %1; cvt.u32.u64 %0, t; }"
        : "=r"(a) : "l"(p));
    return a;
}
__device__ __forceinline__ void cp16(uint32_t d, const void* s) {
    asm volatile("cp.async.cg.shared.global [%0], [%1], 16;" :: "r"(d), "l"(s));
}
__device__ __forceinline__ void ldm_x4(uint32_t* r, uint32_t addr) {
    asm volatile("ldmatrix.sync.aligned.m8n8.x4.shared.b16 {%0,%1,%2,%3}, [%4];"
        : "=r"(r[0]), "=r"(r[1]), "=r"(r[2]), "=r"(r[3]) : "r"(addr));
}
__device__ __forceinline__ void mma16816(float* d, const uint32_t* a, const uint32_t* b) {
    asm volatile(
        "mma.sync.aligned.m16n8k16.row.col.f32.bf16.bf16.f32 "
        "{%0,%1,%2,%3}, {%4,%5,%6,%7}, {%8,%9}, {%0,%1,%2,%3};"
        : "+f"(d[0]), "+f"(d[1]), "+f"(d[2]), "+f"(d[3])
        : "r"(a[0]), "r"(a[1]), "r"(a[2]), "r"(a[3]), "r"(b[0]), "r"(b[1]));
}

#define STAGE_BYTES 40960
#define AH_OFF 0
#define AL_OFF 10240
#define BH_OFF 20480
#define BL_OFF 30720
#define SROWB  80           // padded row stride in bytes (32 bf16 + 8 pad)
#define MM_SMEM (2*STAGE_BYTES)

// =========================================================================
// hi/lo 3-pass bf16 mma GEMM body. C[M,N] = A @ B^T (logical fp32).
// A given hi/lo bf16 [M][K]; B hi/lo bf16 [N][K]. CTA 128x128, K-step 32.
// epi: 0=store fp32, 1=add fp32, 2=gelu->hi/lo bf16, 3=wact, 4=silu
// =========================================================================
__device__ __forceinline__ void mma_gemm_body(
    const __nv_bfloat16* __restrict__ Ah, const __nv_bfloat16* __restrict__ Al,
    const __nv_bfloat16* __restrict__ Bh, const __nv_bfloat16* __restrict__ Bl,
    float* __restrict__ C, __nv_bfloat16* __restrict__ Ch, __nv_bfloat16* __restrict__ Cl,
    int N, int K, int epi, const float* __restrict__ aux)
{
    extern __shared__ char sm[];
    uint32_t sb = s2u(sm);
    int tid = threadIdx.x, lane = tid & 31, wid = tid >> 5;
    int m0 = blockIdx.y * 128, n0 = blockIdx.x * 128;
    int m0w = (wid & 1) * 64, n0w = (wid >> 1) * 32;

    float acc[4][4][4];
    #pragma unroll
    for (int a = 0; a < 4; a++)
        #pragma unroll
        for (int b = 0; b < 4; b++)
            #pragma unroll
            for (int c = 0; c < 4; c++) acc[a][b][c] = 0.0f;

    const int nt = K >> 5;

    // per-thread copy indices (2 rows x 16B chunk each for all 4 arrays)
    int id0 = tid, id1 = tid + 256;

    // prologue: stage 0
    {
        int k0 = 0;
        uint32_t base = sb;
        #pragma unroll
        for (int i = 0; i < 2; i++) {
            int id = (i == 0) ? id0 : id1;
            int row = id >> 2, c8 = (id & 3) * 8;
            uint32_t so = row * SROWB + c8 * 2;
            size_t ga = (size_t)(m0 + row) * K + k0 + c8;
            size_t gb = (size_t)(n0 + row) * K + k0 + c8;
            cp16(base + AH_OFF + so, Ah + ga);
            cp16(base + AL_OFF + so, Al + ga);
            cp16(base + BH_OFF + so, Bh + gb);
            cp16(base + BL_OFF + so, Bl + gb);
        }
        asm volatile("cp.async.commit_group;" ::: "memory");
    }

    for (int t = 0; t < nt; t++) {
        if (t + 1 < nt) {
            int k0 = (t + 1) << 5;
            uint32_t base = sb + ((t + 1) & 1) * STAGE_BYTES;
            #pragma unroll
            for (int i = 0; i < 2; i++) {
                int id = (i == 0) ? id0 : id1;
                int row = id >> 2, c8 = (id & 3) * 8;
                uint32_t so = row * SROWB + c8 * 2;
                size_t ga = (size_t)(m0 + row) * K + k0 + c8;
                size_t gb = (size_t)(n0 + row) * K + k0 + c8;
                cp16(base + AH_OFF + so, Ah + ga);
                cp16(base + AL_OFF + so, Al + ga);
                cp16(base + BH_OFF + so, Bh + gb);
                cp16(base + BL_OFF + so, Bl + gb);
            }
            asm volatile("cp.async.commit_group;" ::: "memory");
            asm volatile("cp.async.wait_group 1;" ::: "memory");
        } else {
            asm volatile("cp.async.wait_group 0;" ::: "memory");
        }
        __syncthreads();

        uint32_t base = sb + (t & 1) * STAGE_BYTES;
        #pragma unroll
        for (int kk = 0; kk < 2; kk++) {
            uint32_t aoff = (uint32_t)((m0w + (lane & 15)) * SROWB
                           + (kk * 16 + (lane >> 4) * 8) * 2);
            uint32_t boff = (uint32_t)((n0w + (lane & 7) + ((lane >> 4) << 3)) * SROWB
                           + (kk * 16 + ((lane >> 3) & 1) * 8) * 2);
            uint32_t aH[4][4], aL[4][4], bH[2][4], bL[2][4];
            #pragma unroll
            for (int mf = 0; mf < 4; mf++)
                ldm_x4(aH[mf], base + AH_OFF + aoff + mf * 16 * SROWB);
            #pragma unroll
            for (int bb = 0; bb < 2; bb++)
                ldm_x4(bH[bb], base + BH_OFF + boff + bb * 16 * SROWB);
            #pragma unroll
            for (int mf = 0; mf < 4; mf++)
                #pragma unroll
                for (int nf = 0; nf < 4; nf++)
                    mma16816(acc[mf][nf], aH[mf], &bH[nf >> 1][(nf & 1) * 2]);
            #pragma unroll
            for (int mf = 0; mf < 4; mf++)
                ldm_x4(aL[mf], base + AL_OFF + aoff + mf * 16 * SROWB);
            #pragma unroll
            for (int mf = 0; mf < 4; mf++)
                #pragma unroll
                for (int nf = 0; nf < 4; nf++)
                    mma16816(acc[mf][nf], aL[mf], &bH[nf >> 1][(nf & 1) * 2]);
            #pragma unroll
            for (int bb = 0; bb < 2; bb++)
                ldm_x4(bL[bb], base + BL_OFF + boff + bb * 16 * SROWB);
            #pragma unroll
            for (int mf = 0; mf < 4; mf++)
                #pragma unroll
                for (int nf = 0; nf < 4; nf++)
                    mma16816(acc[mf][nf], aH[mf], &bL[nf >> 1][(nf & 1) * 2]);
        }
        __syncthreads();
    }

    // ---- epilogue ----
    int qr = lane >> 2, qc = (lane & 3) * 2;
    #pragma unroll
    for (int mf = 0; mf < 4; mf++) {
        #pragma unroll
        for (int nf = 0; nf < 4; nf++) {
            #pragma unroll
            for (int half = 0; half < 2; half++) {
                int row = m0 + m0w + mf * 16 + qr + half * 8;
                int col = n0 + n0w + nf * 8 + qc;
                float x = acc[mf][nf][half * 2 + 0];
                float y = acc[mf][nf][half * 2 + 1];
                size_t o = (size_t)row * N + col;
                if (epi == 0) {
                    *(float2*)(C + o) = make_float2(x, y);
                } else if (epi == 1) {
                    float2 old = *(const float2*)(C + o);
                    *(float2*)(C + o) = make_float2(old.x + x, old.y + y);
                } else if (epi == 2) {
                    x = 0.5f * x * (1.0f + erff(x * 0.70710678118654752f));
                    y = 0.5f * y * (1.0f + erff(y * 0.70710678118654752f));
                    __nv_bfloat162 hv = __floats2bfloat162_rn(x, y);
                    float lx = x - __bfloat162float(__low2bfloat16(hv));
                    float ly = y - __bfloat162float(__high2bfloat16(hv));
                    *(__nv_bfloat162*)(Ch + o) = hv;
                    *(__nv_bfloat162*)(Cl + o) = __floats2bfloat162_rn(lx, ly);
                } else if (epi == 3) {
                    x = expf(-expf(x + aux[col]));
                    y = expf(-expf(y + aux[col + 1]));
                    *(float2*)(C + o) = make_float2(x, y);
                } else {
                    x = x / (1.0f + expf(-x));
                    y = y / (1.0f + expf(-y));
                    *(float2*)(C + o) = make_float2(x, y);
                }
            }
        }
    }
}

__global__ void __launch_bounds__(256)
mma_gemm(const __nv_bfloat16* __restrict__ Ah, const __nv_bfloat16* __restrict__ Al,
         const __nv_bfloat16* __restrict__ Bh, const __nv_bfloat16* __restrict__ Bl,
         float* __restrict__ C, __nv_bfloat16* __restrict__ Ch,
         __nv_bfloat16* __restrict__ Cl, int N, int K, int epi,
         const float* __restrict__ aux) {
    mma_gemm_body(Ah, Al, Bh, Bl, C, Ch, Cl, N, K, epi, aux);
}

// batched 5-projection: z selects A slice / weight / output / epilogue
__global__ void __launch_bounds__(256)
proj_mma(const __nv_bfloat16* __restrict__ x5h, const __nv_bfloat16* __restrict__ x5l,
         const __nv_bfloat16* __restrict__ Ph, const __nv_bfloat16* __restrict__ Pl,
         int l, const float* __restrict__ w0,
         float* __restrict__ Cr, float* __restrict__ Ck, float* __restrict__ Cv,
         float* __restrict__ Cw, float* __restrict__ Cg) {
    int z = blockIdx.z;
    size_t wo = ((size_t)l * 5 + z) * DDm;
    float* C = (z == 0) ? Cr : (z == 1) ? Ck : (z == 2) ? Cv : (z == 3) ? Cw : Cg;
    int epi = (z == 3) ? 3 : (z == 4) ? 4 : 0;
    mma_gemm_body(x5h + (size_t)z * ND, x5l + (size_t)z * ND,
                  Ph + wo, Pl + wo, C, nullptr, nullptr, Dd, Dd, epi, w0);
}

// =========================================================================
// weight prep: transpose [K,N] -> [N,K] with bf16 hi/lo split
// =========================================================================
__global__ void tsplit(const float* __restrict__ W, __nv_bfloat16* __restrict__ oh,
                       __nv_bfloat16* __restrict__ ol, int K, int N) {
    __shared__ float ts[32][33];
    size_t mo = (size_t)blockIdx.z * K * N;
    int n0 = blockIdx.x * 32, k0 = blockIdx.y * 32;
    int tx = threadIdx.x, ty = threadIdx.y;
    #pragma unroll
    for (int r = 0; r < 4; r++)
        ts[ty + 8 * r][tx] = W[mo + (size_t)(k0 + ty + 8 * r) * N + n0 + tx];
    __syncthreads();
    #pragma unroll
    for (int r = 0; r < 4; r++) {
        float a = ts[tx][ty + 8 * r];
        float h = __bfloat162float(__float2bfloat16(a));
        size_t o = mo + (size_t)(n0 + ty + 8 * r) * K + k0 + tx;
        oh[o] = __float2bfloat16(a);
        ol[o] = __float2bfloat16(a - h);
    }
}

__global__ void tsplit_proj(const float* __restrict__ Wr, const float* __restrict__ Wk,
                            const float* __restrict__ Wv, const float* __restrict__ Ww,
                            const float* __restrict__ Wg,
                            __nv_bfloat16* __restrict__ oh, __nv_bfloat16* __restrict__ ol) {
    __shared__ float ts[32][33];
    int z = blockIdx.z, p = z % 5, l = z / 5;
    const float* W = ((p == 0) ? Wr : (p == 1) ? Wk : (p == 2) ? Wv :
                      (p == 3) ? Ww : Wg) + (size_t)l * DDm;
    size_t mo = (size_t)z * DDm;
    int n0 = blockIdx.x * 32, k0 = blockIdx.y * 32;
    int tx = threadIdx.x, ty = threadIdx.y;
    #pragma unroll
    for (int r = 0; r < 4; r++)
        ts[ty + 8 * r][tx] = W[(size_t)(k0 + ty + 8 * r) * Dd + n0 + tx];
    __syncthreads();
    #pragma unroll
    for (int r = 0; r < 4; r++) {
        float a = ts[tx][ty + 8 * r];
        float h = __bfloat162float(__float2bfloat16(a));
        size_t o = mo + (size_t)(n0 + ty + 8 * r) * Dd + k0 + tx;
        oh[o] = __float2bfloat16(a);
        ol[o] = __float2bfloat16(a - h);
    }
}

__global__ void esplit(const float* __restrict__ e, __nv_bfloat16* __restrict__ eh,
                       __nv_bfloat16* __restrict__ el) {
    int idx = blockIdx.x * blockDim.x + threadIdx.x;
    float a = e[idx];
    float h = __bfloat162float(__float2bfloat16(a));
    eh[idx] = __float2bfloat16(a);
    el[idx] = __float2bfloat16(a - h);
}

// =========================================================================
// elementwise / norm kernels
// =========================================================================
__global__ void embed_kernel(const int* __restrict__ tok,
                             const float* __restrict__ emb,
                             float* __restrict__ h) {
    int idx = blockIdx.x * blockDim.x + threadIdx.x;
    int row = idx >> 7;
    int c4  = idx & 127;
    ((float4*)h)[idx] = ((const float4*)emb)[(size_t)tok[row] * 128 + c4];
}

// fp32-out rmsnorm (feeds mix5)
__global__ void rmsnorm_kernel(const float* __restrict__ x,
                               const float* __restrict__ w,
                               float* __restrict__ o) {
    int row = blockIdx.x;
    int tid = threadIdx.x;
    float4 a = ((const float4*)(x + (size_t)row * Dd))[tid];
    float ss = a.x*a.x + a.y*a.y + a.z*a.z + a.w*a.w;
    #pragma unroll
    for (int s = 16; s > 0; s >>= 1) ss += __shfl_xor_sync(0xffffffffu, ss, s);
    __shared__ float sred[4];
    if ((tid & 31) == 0) sred[tid >> 5] = ss;
    __syncthreads();
    float tot = sred[0] + sred[1] + sred[2] + sred[3];
    float sc  = rsqrtf(tot * (1.0f / Dd) + 1e-6f);
    float4 wv = ((const float4*)w)[tid];
    float4 r;
    r.x = a.x * sc * wv.x; r.y = a.y * sc * wv.y;
    r.z = a.z * sc * wv.z; r.w = a.w * sc * wv.w;
    ((float4*)(o + (size_t)row * Dd))[tid] = r;
}

// hi/lo-out rmsnorm (feeds GEMMs)
__global__ void rmsnorm_split_kernel(const float* __restrict__ x,
                                     const float* __restrict__ w,
                                     __nv_bfloat16* __restrict__ oh,
                                     __nv_bfloat16* __restrict__ ol) {
    int row = blockIdx.x;
    int tid = threadIdx.x;
    float4 a = ((const float4*)(x + (size_t)row * Dd))[tid];
    float ss = a.x*a.x + a.y*a.y + a.z*a.z + a.w*a.w;
    #pragma unroll
    for (int s = 16; s > 0; s >>= 1) ss += __shfl_xor_sync(0xffffffffu, ss, s);
    __shared__ float sred[4];
    if ((tid & 31) == 0) sred[tid >> 5] = ss;
    __syncthreads();
    float tot = sred[0] + sred[1] + sred[2] + sred[3];
    float sc  = rsqrtf(tot * (1.0f / Dd) + 1e-6f);
    float4 wv = ((const float4*)w)[tid];
    float vv[4] = {a.x * sc * wv.x, a.y * sc * wv.y, a.z * sc * wv.z, a.w * sc * wv.w};
    size_t o = (size_t)row * Dd + tid * 4;
    #pragma unroll
    for (int i = 0; i < 4; i++) {
        float h = __bfloat162float(__float2bfloat16(vv[i]));
        oh[o + i] = __float2bfloat16(vv[i]);
        ol[o + i] = __float2bfloat16(vv[i] - h);
    }
}

// token shift + 5-way lerp -> hi/lo bf16
__global__ void mix5_kernel(const float* __restrict__ hn,
                            const float* __restrict__ mix,
                            __nv_bfloat16* __restrict__ xh,
                            __nv_bfloat16* __restrict__ xl) {
    int idx = blockIdx.x * blockDim.x + threadIdx.x;
    int row = idx >> 9;
    int c   = idx & 511;
    int t   = row & (Tt - 1);
    float cur  = hn[idx];
    float prev = (t == 0) ? 0.0f : hn[idx - Dd];
    float d    = prev - cur;
    #pragma unroll
    for (int j = 0; j < 5; j++) {
        float v = fmaf(d, mix[j * Dd + c], cur);
        float h = __bfloat162float(__float2bfloat16(v));
        xh[(size_t)j * ND + idx] = __float2bfloat16(v);
        xl[(size_t)j * ND + idx] = __float2bfloat16(v - h);
    }
}

// =========================================================================
// WKV (chunked scan, unchanged)
// =========================================================================
__global__ void __launch_bounds__(128, 3)
wkv_chunk_kernel(float* __restrict__ r, const float* __restrict__ k,
                 const float* __restrict__ v, const float* __restrict__ w,
                 const float* __restrict__ u, float* __restrict__ y,
                 float* __restrict__ Sb, float* __restrict__ wt) {
    int blk = blockIdx.x;
    int bh  = blk / NCH;
    int ch  = blk % NCH;
    int b = bh >> 2, h = bh & 3;
    int j = threadIdx.x;
    __shared__ float4 s[Dh];
    float uj = u[h * Dh + j];
    float S[Dh];
    #pragma unroll
    for (int i = 0; i < Dh; i++) S[i] = 0.0f;
    float p = 1.0f;
    size_t off = (size_t)b * Tt * Dd + (size_t)(ch * CSZ) * Dd + h * Dh + j;
    for (int t = 0; t < CSZ; t++, off += Dd) {
        float rv = r[off], kv_ = k[off], wv = w[off], vv = v[off];
        __syncthreads();
        s[j] = make_float4(rv, kv_, wv, uj);
        __syncthreads();
        r[off] = rv * p;
        p *= wv;
        float acc = 0.0f;
        #pragma unroll
        for (int i = 0; i < Dh; i++) {
            float4 q = s[i];
            float kv = q.y * vv;
            acc  = fmaf(q.x, fmaf(q.w, kv, S[i]), acc);
            S[i] = fmaf(q.z, S[i], kv);
        }
        y[off] = acc;
    }
    wt[blk * Dh + j] = p;
    size_t base = (size_t)blk * Dh * Dh;
    #pragma unroll
    for (int i = 0; i < Dh; i++) Sb[base + (size_t)i * Dh + j] = S[i];
}

__global__ void __launch_bounds__(128, 1)
wkv_combine_kernel(float* __restrict__ Sb, const float* __restrict__ wt) {
    int bh = blockIdx.x;
    int j  = threadIdx.x;
    __shared__ float sw[Dh];
    float run[Dh];
    #pragma unroll
    for (int i = 0; i < Dh; i++) run[i] = 0.0f;
    for (int ch = 0; ch < NCH; ch++) {
        int blk = bh * NCH + ch;
        __syncthreads();
        sw[j] = wt[blk * Dh + j];
        __syncthreads();
        size_t base = (size_t)blk * Dh * Dh;
        #pragma unroll
        for (int i = 0; i < Dh; i++) {
            float m = Sb[base + (size_t)i * Dh + j];
            Sb[base + (size_t)i * Dh + j] = run[i];
            run[i] = fmaf(run[i], sw[i], m);
        }
    }
}

__global__ void __launch_bounds__(128, 3)
wkv_inter_kernel(const float* __restrict__ rt, const float* __restrict__ Sb,
                 float* __restrict__ y) {
    int blk = blockIdx.x;
    int bh  = blk / NCH;
    int ch  = blk % NCH;
    int b = bh >> 2, h = bh & 3;
    int j = threadIdx.x;
    float Scol[Dh];
    size_t base = (size_t)blk * Dh * Dh;
    #pragma unroll
    for (int i = 0; i < Dh; i++) Scol[i] = Sb[base + (size_t)i * Dh + j];
    __shared__ float sr[Dh];
    size_t off = (size_t)b * Tt * Dd + (size_t)(ch * CSZ) * Dd + h * Dh + j;
    for (int t = 0; t < CSZ; t++, off += Dd) {
        __syncthreads();
        sr[j] = rt[off];
        __syncthreads();
        float acc = y[off];
        #pragma unroll
        for (int i = 0; i < Dh; i++) acc = fmaf(sr[i], Scol[i], acc);
        y[off] = acc;
    }
}

// per-head GroupNorm + gate -> hi/lo bf16 (input to Wo GEMM)
__global__ void gn_gate_kernel(const float* __restrict__ y,
                               const float* __restrict__ g,
                               const float* __restrict__ gw,
                               const float* __restrict__ gb,
                               __nv_bfloat16* __restrict__ oh,
                               __nv_bfloat16* __restrict__ ol) {
    int grp = blockIdx.x;
    int row = grp >> 2, h = grp & 3;
    int j = threadIdx.x;
    size_t off = (size_t)row * Dd + h * Dh + j;
    float yv = y[off];
    float s1 = yv, s2 = yv * yv;
    #pragma unroll
    for (int s = 16; s > 0; s >>= 1) {
        s1 += __shfl_xor_sync(0xffffffffu, s1, s);
        s2 += __shfl_xor_sync(0xffffffffu, s2, s);
    }
    __shared__ float r1[4], r2[4];
    if ((j & 31) == 0) { r1[j >> 5] = s1; r2[j >> 5] = s2; }
    __syncthreads();
    s1 = r1[0] + r1[1] + r1[2] + r1[3];
    s2 = r2[0] + r2[1] + r2[2] + r2[3];
    float mu  = s1 * (1.0f / Dh);
    float var = s2 * (1.0f / Dh) - mu * mu;
    float nrm = (yv - mu) * rsqrtf(var + 1e-5f);
    int c = h * Dh + j;
    float val = fmaf(nrm, gw[c], gb[c]) * g[off];
    float hv = __bfloat162float(__float2bfloat16(val));
    oh[off] = __float2bfloat16(val);
    ol[off] = __float2bfloat16(val - hv);
}

// =========================================================================
// host driver
// =========================================================================
extern "C" void kernel_launch(void* const* d_in, const int* in_sizes, int n_in,
                              void* d_out, int out_size) {
    const int*   tokens = (const int*)  d_in[0];
    const float* embed  = (const float*)d_in[1];
    const float* ln1    = (const float*)d_in[2];
    const float* ln2    = (const float*)d_in[3];
    const float* lno    = (const float*)d_in[4];
    const float* mix    = (const float*)d_in[5];
    const float* Wr     = (const float*)d_in[6];
    const float* Wk     = (const float*)d_in[7];
    const float* Wv     = (const float*)d_in[8];
    const float* Wg     = (const float*)d_in[9];
    const float* Ww     = (const float*)d_in[10];
    const float* w0     = (const float*)d_in[11];
    const float* Wo     = (const float*)d_in[12];
    const float* u      = (const float*)d_in[13];
    const float* gnw    = (const float*)d_in[14];
    const float* gnb    = (const float*)d_in[15];
    const float* W1     = (const float*)d_in[16];
    const float* W2     = (const float*)d_in[17];
    float* out = (float*)d_out;

    float *h, *hn, *r, *k, *v, *w, *g, *y, *Sb, *wt;
    cudaGetSymbolAddress((void**)&h,  g_h);
    cudaGetSymbolAddress((void**)&hn, g_hn);
    cudaGetSymbolAddress((void**)&r,  g_r);
    cudaGetSymbolAddress((void**)&k,  g_k);
    cudaGetSymbolAddress((void**)&v,  g_v);
    cudaGetSymbolAddress((void**)&w,  g_w);
    cudaGetSymbolAddress((void**)&g,  g_g);
    cudaGetSymbolAddress((void**)&y,  g_y);
    cudaGetSymbolAddress((void**)&Sb, g_Sb);
    cudaGetSymbolAddress((void**)&wt, g_wt);

    __nv_bfloat16 *x5h, *x5l, *ffh, *ffl, *hnh, *hnl, *gnh, *gnl;
    __nv_bfloat16 *pTh, *pTl, *oTh, *oTl, *t1h, *t1l, *t2h, *t2l, *eh, *el;
    cudaGetSymbolAddress((void**)&x5h, g_x5h);
    cudaGetSymbolAddress((void**)&x5l, g_x5l);
    cudaGetSymbolAddress((void**)&ffh, g_ffh);
    cudaGetSymbolAddress((void**)&ffl, g_ffl);
    cudaGetSymbolAddress((void**)&hnh, g_hnh);
    cudaGetSymbolAddress((void**)&hnl, g_hnl);
    cudaGetSymbolAddress((void**)&gnh, g_gnh);
    cudaGetSymbolAddress((void**)&gnl, g_gnl);
    cudaGetSymbolAddress((void**)&pTh, g_pTh);
    cudaGetSymbolAddress((void**)&pTl, g_pTl);
    cudaGetSymbolAddress((void**)&oTh, g_oTh);
    cudaGetSymbolAddress((void**)&oTl, g_oTl);
    cudaGetSymbolAddress((void**)&t1h, g_1Th);
    cudaGetSymbolAddress((void**)&t1l, g_1Tl);
    cudaGetSymbolAddress((void**)&t2h, g_2Th);
    cudaGetSymbolAddress((void**)&t2l, g_2Tl);
    cudaGetSymbolAddress((void**)&eh,  g_eh);
    cudaGetSymbolAddress((void**)&el,  g_el);

    cudaFuncSetAttribute(mma_gemm, cudaFuncAttributeMaxDynamicSharedMemorySize, MM_SMEM);
    cudaFuncSetAttribute(proj_mma, cudaFuncAttributeMaxDynamicSharedMemorySize, MM_SMEM);

    // ---- weight prep (replayed every call; deterministic) ----
    dim3 tb(32, 8);
    tsplit_proj<<<dim3(16, 16, 40), tb>>>(Wr, Wk, Wv, Ww, Wg, pTh, pTl);
    tsplit<<<dim3(16, 16, Ll), tb>>>(Wo, oTh, oTl, Dd, Dd);
    tsplit<<<dim3(Ff / 32, 16, Ll), tb>>>(W1, t1h, t1l, Dd, Ff);
    tsplit<<<dim3(16, Ff / 32, Ll), tb>>>(W2, t2h, t2l, Ff, Dd);
    esplit<<<(Vv * Dd) / 256, 256>>>(embed, eh, el);

    embed_kernel<<<(ND / 4) / 256, 256>>>(tokens, embed, h);

    dim3 gridProj(4, 16, 5);
    dim3 grid512 (4, 16);
    dim3 gridF   (16, 16);
    dim3 gridV   (250, 16);

    for (int l = 0; l < Ll; l++) {
        rmsnorm_kernel<<<Nrows, 128>>>(h, ln1 + l * Dd, hn);
        mix5_kernel<<<ND / 256, 256>>>(hn, mix + (size_t)l * 5 * Dd, x5h, x5l);

        proj_mma<<<gridProj, 256, MM_SMEM>>>(x5h, x5l, pTh, pTl, l, w0 + l * Dd,
                                             r, k, v, w, g);

        wkv_chunk_kernel  <<<Bb * Hh * NCH, 128>>>(r, k, v, w, u + l * Hh * Dh, y, Sb, wt);
        wkv_combine_kernel<<<Bb * Hh,       128>>>(Sb, wt);
        wkv_inter_kernel  <<<Bb * Hh * NCH, 128>>>(r, Sb, y);

        gn_gate_kernel<<<Nrows * Hh, 128>>>(y, g, gnw + l * Dd, gnb + l * Dd, gnh, gnl);
        mma_gemm<<<grid512, 256, MM_SMEM>>>(gnh, gnl, oTh + (size_t)l * DDm,
                                            oTl + (size_t)l * DDm, h, nullptr, nullptr,
                                            Dd, Dd, 1, nullptr);

        rmsnorm_split_kernel<<<Nrows, 128>>>(h, ln2 + l * Dd, hnh, hnl);
        mma_gemm<<<gridF, 256, MM_SMEM>>>(hnh, hnl, t1h + (size_t)l * Dd * Ff,
                                          t1l + (size_t)l * Dd * Ff, nullptr, ffh, ffl,
                                          Ff, Dd, 2, nullptr);
        mma_gemm<<<grid512, 256, MM_SMEM>>>(ffh, ffl, t2h + (size_t)l * Ff * Dd,
                                            t2l + (size_t)l * Ff * Dd, h, nullptr, nullptr,
                                            Dd, Ff, 1, nullptr);
    }

    rmsnorm_split_kernel<<<Nrows, 128>>>(h, lno, hnh, hnl);
    mma_gemm<<<gridV, 256, MM_SMEM>>>(hnh, hnl, eh, el, out, nullptr, nullptr,
                                      Vv, Dd, 0, nullptr);
}

// round 5
// speedup vs baseline: 4.9978x; 1.3534x over previous
#include <cuda_runtime.h>
#include <cuda_bf16.h>
#include <math.h>
#include <stdint.h>

// ---- model constants ----
#define Vv   32000
#define Dd   512
#define Ll   8
#define Hh   4
#define Dh   128
#define Ff   2048
#define Bb   2
#define Tt   1024
#define Nrows (Bb*Tt)          // 2048
#define ND   (Nrows*Dd)        // 1048576
#define NF   (Nrows*Ff)        // 4194304
#define DDm  (Dd*Dd)
#define CSZ  32                // wkv chunk length
#define NCH  (Tt/CSZ)          // 32 chunks

// ---- fp32 scratch ----
__device__ float g_h [ND];
__device__ float g_r [ND];
__device__ float g_k [ND];
__device__ float g_v [ND];
__device__ float g_w [ND];
__device__ float g_g [ND];
__device__ float g_y [ND];
__device__ float g_Sb[(size_t)Bb*Hh*NCH*Dh*Dh];
__device__ float g_wt[Bb*Hh*NCH*Dh];

// ---- bf16 hi/lo activation buffers ([M][K] row-major) ----
__device__ __nv_bfloat16 g_x5h[5*ND], g_x5l[5*ND];
__device__ __nv_bfloat16 g_ffh[NF],  g_ffl[NF];
__device__ __nv_bfloat16 g_hnh[ND],  g_hnl[ND];
__device__ __nv_bfloat16 g_gnh[ND],  g_gnl[ND];

// ---- bf16 hi/lo transposed weight caches ([N][K] row-major) ----
__device__ __nv_bfloat16 g_pTh[(size_t)Ll*5*DDm], g_pTl[(size_t)Ll*5*DDm];
__device__ __nv_bfloat16 g_oTh[(size_t)Ll*DDm],   g_oTl[(size_t)Ll*DDm];
__device__ __nv_bfloat16 g_1Th[(size_t)Ll*Dd*Ff], g_1Tl[(size_t)Ll*Dd*Ff];
__device__ __nv_bfloat16 g_2Th[(size_t)Ll*Ff*Dd], g_2Tl[(size_t)Ll*Ff*Dd];
__device__ __nv_bfloat16 g_eh[(size_t)Vv*Dd],     g_el[(size_t)Vv*Dd];

// =========================================================================
// PTX helpers (baseline sm_80+ — legal on compute_103)
// =========================================================================
__device__ __forceinline__ uint32_t s2u(const void* p) {
    uint32_t a;
    asm("{ .reg .u64 t; cvta.to.shared.u64 t, %1; cvt.u32.u64 %0, t; }"
        : "=r"(a) : "l"(p));
    return a;
}
__device__ __forceinline__ void cp16(uint32_t d, const void* s) {
    asm volatile("cp.async.cg.shared.global [%0], [%1], 16;" :: "r"(d), "l"(s));
}
__device__ __forceinline__ void ldm_x4(uint32_t* r, uint32_t addr) {
    asm volatile("ldmatrix.sync.aligned.m8n8.x4.shared.b16 {%0,%1,%2,%3}, [%4];"
        : "=r"(r[0]), "=r"(r[1]), "=r"(r[2]), "=r"(r[3]) : "r"(addr));
}
__device__ __forceinline__ void mma16816(float* d, const uint32_t* a, const uint32_t* b) {
    asm volatile(
        "mma.sync.aligned.m16n8k16.row.col.f32.bf16.bf16.f32 "
        "{%0,%1,%2,%3}, {%4,%5,%6,%7}, {%8,%9}, {%0,%1,%2,%3};"
        : "+f"(d[0]), "+f"(d[1]), "+f"(d[2]), "+f"(d[3])
        : "r"(a[0]), "r"(a[1]), "r"(a[2]), "r"(a[3]), "r"(b[0]), "r"(b[1]));
}

#define STAGE_BYTES 40960
#define AH_OFF 0
#define AL_OFF 10240
#define BH_OFF 20480
#define BL_OFF 30720
#define SROWB  80           // padded row stride in bytes (32 bf16 + 8 pad)
#define MM_SMEM (2*STAGE_BYTES)

// =========================================================================
// hi/lo 3-pass bf16 mma GEMM. CTA tile (MF*32) x 128, K-step 32.
// epi: 0=store fp32, 1=add fp32, 2=gelu->hi/lo bf16, 3=wact, 4=silu
// =========================================================================
template<int MF>
__device__ __forceinline__ void mma_gemm_body(
    const __nv_bfloat16* __restrict__ Ah, const __nv_bfloat16* __restrict__ Al,
    const __nv_bfloat16* __restrict__ Bh, const __nv_bfloat16* __restrict__ Bl,
    float* __restrict__ C, __nv_bfloat16* __restrict__ Ch, __nv_bfloat16* __restrict__ Cl,
    int N, int K, int epi, const float* __restrict__ aux)
{
    extern __shared__ char sm[];
    uint32_t sb = s2u(sm);
    int tid = threadIdx.x, lane = tid & 31, wid = tid >> 5;
    const int BM = MF * 32;
    int m0 = blockIdx.y * BM, n0 = blockIdx.x * 128;
    int m0w = (wid & 1) * (MF * 16), n0w = (wid >> 1) * 32;

    float acc[MF][4][4];
    #pragma unroll
    for (int a = 0; a < MF; a++)
        #pragma unroll
        for (int b = 0; b < 4; b++)
            #pragma unroll
            for (int c = 0; c < 4; c++) acc[a][b][c] = 0.0f;

    const int nt = K >> 5;

    // prologue: stage 0
    {
        uint32_t base = sb;
        #pragma unroll
        for (int i = 0; i < MF / 2; i++) {
            int id = tid + i * 256;
            int row = id >> 2, c8 = (id & 3) * 8;
            uint32_t so = row * SROWB + c8 * 2;
            size_t ga = (size_t)(m0 + row) * K + c8;
            cp16(base + AH_OFF + so, Ah + ga);
            cp16(base + AL_OFF + so, Al + ga);
        }
        #pragma unroll
        for (int i = 0; i < 2; i++) {
            int id = tid + i * 256;
            int row = id >> 2, c8 = (id & 3) * 8;
            uint32_t so = row * SROWB + c8 * 2;
            size_t gb = (size_t)(n0 + row) * K + c8;
            cp16(base + BH_OFF + so, Bh + gb);
            cp16(base + BL_OFF + so, Bl + gb);
        }
        asm volatile("cp.async.commit_group;" ::: "memory");
    }

    for (int t = 0; t < nt; t++) {
        if (t + 1 < nt) {
            int k0 = (t + 1) << 5;
            uint32_t base = sb + ((t + 1) & 1) * STAGE_BYTES;
            #pragma unroll
            for (int i = 0; i < MF / 2; i++) {
                int id = tid + i * 256;
                int row = id >> 2, c8 = (id & 3) * 8;
                uint32_t so = row * SROWB + c8 * 2;
                size_t ga = (size_t)(m0 + row) * K + k0 + c8;
                cp16(base + AH_OFF + so, Ah + ga);
                cp16(base + AL_OFF + so, Al + ga);
            }
            #pragma unroll
            for (int i = 0; i < 2; i++) {
                int id = tid + i * 256;
                int row = id >> 2, c8 = (id & 3) * 8;
                uint32_t so = row * SROWB + c8 * 2;
                size_t gb = (size_t)(n0 + row) * K + k0 + c8;
                cp16(base + BH_OFF + so, Bh + gb);
                cp16(base + BL_OFF + so, Bl + gb);
            }
            asm volatile("cp.async.commit_group;" ::: "memory");
            asm volatile("cp.async.wait_group 1;" ::: "memory");
        } else {
            asm volatile("cp.async.wait_group 0;" ::: "memory");
        }
        __syncthreads();

        uint32_t base = sb + (t & 1) * STAGE_BYTES;
        #pragma unroll
        for (int kk = 0; kk < 2; kk++) {
            uint32_t aoff = (uint32_t)((m0w + (lane & 15)) * SROWB
                           + (kk * 16 + (lane >> 4) * 8) * 2);
            uint32_t boff = (uint32_t)((n0w + (lane & 7) + ((lane >> 4) << 3)) * SROWB
                           + (kk * 16 + ((lane >> 3) & 1) * 8) * 2);
            uint32_t aH[MF][4], aL[MF][4], bH[2][4], bL[2][4];
            #pragma unroll
            for (int mf = 0; mf < MF; mf++)
                ldm_x4(aH[mf], base + AH_OFF + aoff + mf * 16 * SROWB);
            #pragma unroll
            for (int bb = 0; bb < 2; bb++)
                ldm_x4(bH[bb], base + BH_OFF + boff + bb * 16 * SROWB);
            #pragma unroll
            for (int mf = 0; mf < MF; mf++)
                #pragma unroll
                for (int nf = 0; nf < 4; nf++)
                    mma16816(acc[mf][nf], aH[mf], &bH[nf >> 1][(nf & 1) * 2]);
            #pragma unroll
            for (int mf = 0; mf < MF; mf++)
                ldm_x4(aL[mf], base + AL_OFF + aoff + mf * 16 * SROWB);
            #pragma unroll
            for (int mf = 0; mf < MF; mf++)
                #pragma unroll
                for (int nf = 0; nf < 4; nf++)
                    mma16816(acc[mf][nf], aL[mf], &bH[nf >> 1][(nf & 1) * 2]);
            #pragma unroll
            for (int bb = 0; bb < 2; bb++)
                ldm_x4(bL[bb], base + BL_OFF + boff + bb * 16 * SROWB);
            #pragma unroll
            for (int mf = 0; mf < MF; mf++)
                #pragma unroll
                for (int nf = 0; nf < 4; nf++)
                    mma16816(acc[mf][nf], aH[mf], &bL[nf >> 1][(nf & 1) * 2]);
        }
        __syncthreads();
    }

    // ---- epilogue ----
    int qr = lane >> 2, qc = (lane & 3) * 2;
    #pragma unroll
    for (int mf = 0; mf < MF; mf++) {
        #pragma unroll
        for (int nf = 0; nf < 4; nf++) {
            #pragma unroll
            for (int half = 0; half < 2; half++) {
                int row = m0 + m0w + mf * 16 + qr + half * 8;
                int col = n0 + n0w + nf * 8 + qc;
                float x = acc[mf][nf][half * 2 + 0];
                float y = acc[mf][nf][half * 2 + 1];
                size_t o = (size_t)row * N + col;
                if (epi == 0) {
                    *(float2*)(C + o) = make_float2(x, y);
                } else if (epi == 1) {
                    float2 old = *(const float2*)(C + o);
                    *(float2*)(C + o) = make_float2(old.x + x, old.y + y);
                } else if (epi == 2) {
                    x = 0.5f * x * (1.0f + erff(x * 0.70710678118654752f));
                    y = 0.5f * y * (1.0f + erff(y * 0.70710678118654752f));
                    __nv_bfloat162 hv = __floats2bfloat162_rn(x, y);
                    float lx = x - __bfloat162float(__low2bfloat16(hv));
                    float ly = y - __bfloat162float(__high2bfloat16(hv));
                    *(__nv_bfloat162*)(Ch + o) = hv;
                    *(__nv_bfloat162*)(Cl + o) = __floats2bfloat162_rn(lx, ly);
                } else if (epi == 3) {
                    x = expf(-expf(x + aux[col]));
                    y = expf(-expf(y + aux[col + 1]));
                    *(float2*)(C + o) = make_float2(x, y);
                } else {
                    x = x / (1.0f + expf(-x));
                    y = y / (1.0f + expf(-y));
                    *(float2*)(C + o) = make_float2(x, y);
                }
            }
        }
    }
}

__global__ void __launch_bounds__(256)
mma_gemm4(const __nv_bfloat16* __restrict__ Ah, const __nv_bfloat16* __restrict__ Al,
          const __nv_bfloat16* __restrict__ Bh, const __nv_bfloat16* __restrict__ Bl,
          float* __restrict__ C, __nv_bfloat16* __restrict__ Ch,
          __nv_bfloat16* __restrict__ Cl, int N, int K, int epi,
          const float* __restrict__ aux) {
    mma_gemm_body<4>(Ah, Al, Bh, Bl, C, Ch, Cl, N, K, epi, aux);
}
__global__ void __launch_bounds__(256)
mma_gemm2(const __nv_bfloat16* __restrict__ Ah, const __nv_bfloat16* __restrict__ Al,
          const __nv_bfloat16* __restrict__ Bh, const __nv_bfloat16* __restrict__ Bl,
          float* __restrict__ C, __nv_bfloat16* __restrict__ Ch,
          __nv_bfloat16* __restrict__ Cl, int N, int K, int epi,
          const float* __restrict__ aux) {
    mma_gemm_body<2>(Ah, Al, Bh, Bl, C, Ch, Cl, N, K, epi, aux);
}

// batched 5-projection: z selects A slice / weight / output / epilogue
__global__ void __launch_bounds__(256)
proj_mma(const __nv_bfloat16* __restrict__ x5h, const __nv_bfloat16* __restrict__ x5l,
         const __nv_bfloat16* __restrict__ Ph, const __nv_bfloat16* __restrict__ Pl,
         int l, const float* __restrict__ w0,
         float* __restrict__ Cr, float* __restrict__ Ck, float* __restrict__ Cv,
         float* __restrict__ Cw, float* __restrict__ Cg) {
    int z = blockIdx.z;
    size_t wo = ((size_t)l * 5 + z) * DDm;
    float* C = (z == 0) ? Cr : (z == 1) ? Ck : (z == 2) ? Cv : (z == 3) ? Cw : Cg;
    int epi = (z == 3) ? 3 : (z == 4) ? 4 : 0;
    mma_gemm_body<4>(x5h + (size_t)z * ND, x5l + (size_t)z * ND,
                     Ph + wo, Pl + wo, C, nullptr, nullptr, Dd, Dd, epi, w0);
}

// =========================================================================
// weight prep: transpose [K,N] -> [N,K] with bf16 hi/lo split
// =========================================================================
__global__ void tsplit(const float* __restrict__ W, __nv_bfloat16* __restrict__ oh,
                       __nv_bfloat16* __restrict__ ol, int K, int N) {
    __shared__ float ts[32][33];
    size_t mo = (size_t)blockIdx.z * K * N;
    int n0 = blockIdx.x * 32, k0 = blockIdx.y * 32;
    int tx = threadIdx.x, ty = threadIdx.y;
    #pragma unroll
    for (int r = 0; r < 4; r++)
        ts[ty + 8 * r][tx] = W[mo + (size_t)(k0 + ty + 8 * r) * N + n0 + tx];
    __syncthreads();
    #pragma unroll
    for (int r = 0; r < 4; r++) {
        float a = ts[tx][ty + 8 * r];
        float h = __bfloat162float(__float2bfloat16(a));
        size_t o = mo + (size_t)(n0 + ty + 8 * r) * K + k0 + tx;
        oh[o] = __float2bfloat16(a);
        ol[o] = __float2bfloat16(a - h);
    }
}

__global__ void tsplit_proj(const float* __restrict__ Wr, const float* __restrict__ Wk,
                            const float* __restrict__ Wv, const float* __restrict__ Ww,
                            const float* __restrict__ Wg,
                            __nv_bfloat16* __restrict__ oh, __nv_bfloat16* __restrict__ ol) {
    __shared__ float ts[32][33];
    int z = blockIdx.z, p = z % 5, l = z / 5;
    const float* W = ((p == 0) ? Wr : (p == 1) ? Wk : (p == 2) ? Wv :
                      (p == 3) ? Ww : Wg) + (size_t)l * DDm;
    size_t mo = (size_t)z * DDm;
    int n0 = blockIdx.x * 32, k0 = blockIdx.y * 32;
    int tx = threadIdx.x, ty = threadIdx.y;
    #pragma unroll
    for (int r = 0; r < 4; r++)
        ts[ty + 8 * r][tx] = W[(size_t)(k0 + ty + 8 * r) * Dd + n0 + tx];
    __syncthreads();
    #pragma unroll
    for (int r = 0; r < 4; r++) {
        float a = ts[tx][ty + 8 * r];
        float h = __bfloat162float(__float2bfloat16(a));
        size_t o = mo + (size_t)(n0 + ty + 8 * r) * Dd + k0 + tx;
        oh[o] = __float2bfloat16(a);
        ol[o] = __float2bfloat16(a - h);
    }
}

__global__ void esplit(const float* __restrict__ e, __nv_bfloat16* __restrict__ eh,
                       __nv_bfloat16* __restrict__ el) {
    int idx = blockIdx.x * blockDim.x + threadIdx.x;
    float a = e[idx];
    float h = __bfloat162float(__float2bfloat16(a));
    eh[idx] = __float2bfloat16(a);
    el[idx] = __float2bfloat16(a - h);
}

// =========================================================================
// embedding gather
// =========================================================================
__global__ void embed_kernel(const int* __restrict__ tok,
                             const float* __restrict__ emb,
                             float* __restrict__ h) {
    int idx = blockIdx.x * blockDim.x + threadIdx.x;
    int row = idx >> 7;
    int c4  = idx & 127;
    ((float4*)h)[idx] = ((const float4*)emb)[(size_t)tok[row] * 128 + c4];
}

// =========================================================================
// fused rmsnorm + token-shift + 5-way lerp -> hi/lo bf16. Block per row.
// =========================================================================
__global__ void __launch_bounds__(128)
rms_mix5(const float* __restrict__ h, const float* __restrict__ lnw,
         const float* __restrict__ mix,
         __nv_bfloat16* __restrict__ xh, __nv_bfloat16* __restrict__ xl) {
    int row = blockIdx.x, tid = threadIdx.x;
    int t = row & (Tt - 1);
    float4 a = ((const float4*)(h + (size_t)row * Dd))[tid];
    float4 p = (t == 0) ? make_float4(0, 0, 0, 0)
                        : ((const float4*)(h + (size_t)(row - 1) * Dd))[tid];
    float sc_ = a.x*a.x + a.y*a.y + a.z*a.z + a.w*a.w;
    float sp_ = p.x*p.x + p.y*p.y + p.z*p.z + p.w*p.w;
    #pragma unroll
    for (int s = 16; s > 0; s >>= 1) {
        sc_ += __shfl_xor_sync(0xffffffffu, sc_, s);
        sp_ += __shfl_xor_sync(0xffffffffu, sp_, s);
    }
    __shared__ float rc[4], rp[4];
    if ((tid & 31) == 0) { rc[tid >> 5] = sc_; rp[tid >> 5] = sp_; }
    __syncthreads();
    float totc = rc[0] + rc[1] + rc[2] + rc[3];
    float totp = rp[0] + rp[1] + rp[2] + rp[3];
    float scc = rsqrtf(totc * (1.0f / Dd) + 1e-6f);
    float scp = (t == 0) ? 0.0f : rsqrtf(totp * (1.0f / Dd) + 1e-6f);
    float4 wv = ((const float4*)lnw)[tid];
    float cn[4] = {a.x * scc * wv.x, a.y * scc * wv.y, a.z * scc * wv.z, a.w * scc * wv.w};
    float pn[4] = {p.x * scp * wv.x, p.y * scp * wv.y, p.z * scp * wv.z, p.w * scp * wv.w};
    int c0 = tid * 4;
    size_t ro = (size_t)row * Dd + c0;
    #pragma unroll
    for (int j = 0; j < 5; j++) {
        #pragma unroll
        for (int i = 0; i < 4; i++) {
            float v = fmaf(pn[i] - cn[i], mix[j * Dd + c0 + i], cn[i]);
            float hv = __bfloat162float(__float2bfloat16(v));
            xh[(size_t)j * ND + ro + i] = __float2bfloat16(v);
            xl[(size_t)j * ND + ro + i] = __float2bfloat16(v - hv);
        }
    }
}

// hi/lo-out rmsnorm (feeds FFN GEMM / logits)
__global__ void rmsnorm_split_kernel(const float* __restrict__ x,
                                     const float* __restrict__ w,
                                     __nv_bfloat16* __restrict__ oh,
                                     __nv_bfloat16* __restrict__ ol) {
    int row = blockIdx.x;
    int tid = threadIdx.x;
    float4 a = ((const float4*)(x + (size_t)row * Dd))[tid];
    float ss = a.x*a.x + a.y*a.y + a.z*a.z + a.w*a.w;
    #pragma unroll
    for (int s = 16; s > 0; s >>= 1) ss += __shfl_xor_sync(0xffffffffu, ss, s);
    __shared__ float sred[4];
    if ((tid & 31) == 0) sred[tid >> 5] = ss;
    __syncthreads();
    float tot = sred[0] + sred[1] + sred[2] + sred[3];
    float sc  = rsqrtf(tot * (1.0f / Dd) + 1e-6f);
    float4 wv = ((const float4*)w)[tid];
    float vv[4] = {a.x * sc * wv.x, a.y * sc * wv.y, a.z * sc * wv.z, a.w * sc * wv.w};
    size_t o = (size_t)row * Dd + tid * 4;
    #pragma unroll
    for (int i = 0; i < 4; i++) {
        float h = __bfloat162float(__float2bfloat16(vv[i]));
        oh[o + i] = __float2bfloat16(vv[i]);
        ol[o + i] = __float2bfloat16(vv[i] - h);
    }
}

// =========================================================================
// WKV phase 1: per-chunk local recurrence
// =========================================================================
__global__ void __launch_bounds__(128, 3)
wkv_chunk_kernel(float* __restrict__ r, const float* __restrict__ k,
                 const float* __restrict__ v, const float* __restrict__ w,
                 const float* __restrict__ u, float* __restrict__ y,
                 float* __restrict__ Sb, float* __restrict__ wt) {
    int blk = blockIdx.x;
    int bh  = blk / NCH;
    int ch  = blk % NCH;
    int b = bh >> 2, h = bh & 3;
    int j = threadIdx.x;
    __shared__ float4 s[Dh];
    float uj = u[h * Dh + j];
    float S[Dh];
    #pragma unroll
    for (int i = 0; i < Dh; i++) S[i] = 0.0f;
    float p = 1.0f;
    size_t off = (size_t)b * Tt * Dd + (size_t)(ch * CSZ) * Dd + h * Dh + j;
    for (int t = 0; t < CSZ; t++, off += Dd) {
        float rv = r[off], kv_ = k[off], wv = w[off], vv = v[off];
        __syncthreads();
        s[j] = make_float4(rv, kv_, wv, uj);
        __syncthreads();
        r[off] = rv * p;
        p *= wv;
        float acc = 0.0f;
        #pragma unroll
        for (int i = 0; i < Dh; i++) {
            float4 q = s[i];
            float kv = q.y * vv;
            acc  = fmaf(q.x, fmaf(q.w, kv, S[i]), acc);
            S[i] = fmaf(q.z, S[i], kv);
        }
        y[off] = acc;
    }
    wt[blk * Dh + j] = p;
    size_t base = (size_t)blk * Dh * Dh;
    #pragma unroll
    for (int i = 0; i < Dh; i++) Sb[base + (size_t)i * Dh + j] = S[i];
}

// =========================================================================
// WKV phase 2: parallel elementwise scan over chunks. One thread per (bh,i,j).
// =========================================================================
__global__ void __launch_bounds__(256)
wkv_combine_kernel(float* __restrict__ Sb, const float* __restrict__ wt) {
    int idx = blockIdx.x * blockDim.x + threadIdx.x;   // over Bb*Hh*Dh*Dh
    int bh  = idx >> 14;
    int rem = idx & 16383;
    int i   = rem >> 7;
    float run = 0.0f;
    #pragma unroll 4
    for (int ch = 0; ch < NCH; ch++) {
        int blk = bh * NCH + ch;
        size_t o = ((size_t)blk << 14) + rem;
        float m = Sb[o];
        Sb[o] = run;
        run = fmaf(run, wt[blk * Dh + i], m);
    }
}

// =========================================================================
// WKV phase 3 + GroupNorm + gate fused. Block per (bh,chunk), 128 threads.
// y_tot = y_local + r~ . S_start; then per-token per-head groupnorm,
// gate with g, split-write bf16 hi/lo -> gnh/gnl.
// =========================================================================
__global__ void __launch_bounds__(128, 3)
wkv_inter_gn_kernel(const float* __restrict__ rt, const float* __restrict__ Sb,
                    const float* __restrict__ y, const float* __restrict__ g,
                    const float* __restrict__ gw, const float* __restrict__ gb,
                    __nv_bfloat16* __restrict__ oh, __nv_bfloat16* __restrict__ ol) {
    int blk = blockIdx.x;
    int bh  = blk / NCH;
    int ch  = blk % NCH;
    int b = bh >> 2, h = bh & 3;
    int j = threadIdx.x;
    int lane = j & 31, wid = j >> 5;
    float Scol[Dh];
    size_t base = (size_t)blk * Dh * Dh;
    #pragma unroll
    for (int i = 0; i < Dh; i++) Scol[i] = Sb[base + (size_t)i * Dh + j];
    __shared__ float sr[Dh];
    __shared__ float r1[4], r2[4];
    int c = h * Dh + j;
    float gwj = gw[c], gbj = gb[c];
    size_t off = (size_t)b * Tt * Dd + (size_t)(ch * CSZ) * Dd + h * Dh + j;
    for (int t = 0; t < CSZ; t++, off += Dd) {
        __syncthreads();                     // protects sr, r1, r2 reuse
        sr[j] = rt[off];
        __syncthreads();
        float acc = y[off];
        #pragma unroll
        for (int i = 0; i < Dh; i++) acc = fmaf(sr[i], Scol[i], acc);
        // groupnorm over the 128 channels of this head (this block's threads)
        float s1 = acc, s2 = acc * acc;
        #pragma unroll
        for (int s = 16; s > 0; s >>= 1) {
            s1 += __shfl_xor_sync(0xffffffffu, s1, s);
            s2 += __shfl_xor_sync(0xffffffffu, s2, s);
        }
        if (lane == 0) { r1[wid] = s1; r2[wid] = s2; }
        __syncthreads();
        s1 = r1[0] + r1[1] + r1[2] + r1[3];
        s2 = r2[0] + r2[1] + r2[2] + r2[3];
        float mu  = s1 * (1.0f / Dh);
        float var = s2 * (1.0f / Dh) - mu * mu;
        float nrm = (acc - mu) * rsqrtf(var + 1e-5f);
        float val = fmaf(nrm, gwj, gbj) * g[off];
        float hv = __bfloat162float(__float2bfloat16(val));
        oh[off] = __float2bfloat16(val);
        ol[off] = __float2bfloat16(val - hv);
    }
}

// =========================================================================
// host driver
// =========================================================================
extern "C" void kernel_launch(void* const* d_in, const int* in_sizes, int n_in,
                              void* d_out, int out_size) {
    const int*   tokens = (const int*)  d_in[0];
    const float* embed  = (const float*)d_in[1];
    const float* ln1    = (const float*)d_in[2];
    const float* ln2    = (const float*)d_in[3];
    const float* lno    = (const float*)d_in[4];
    const float* mix    = (const float*)d_in[5];
    const float* Wr     = (const float*)d_in[6];
    const float* Wk     = (const float*)d_in[7];
    const float* Wv     = (const float*)d_in[8];
    const float* Wg     = (const float*)d_in[9];
    const float* Ww     = (const float*)d_in[10];
    const float* w0     = (const float*)d_in[11];
    const float* Wo     = (const float*)d_in[12];
    const float* u      = (const float*)d_in[13];
    const float* gnw    = (const float*)d_in[14];
    const float* gnb    = (const float*)d_in[15];
    const float* W1     = (const float*)d_in[16];
    const float* W2     = (const float*)d_in[17];
    float* out = (float*)d_out;

    float *h, *r, *k, *v, *w, *g, *y, *Sb, *wt;
    cudaGetSymbolAddress((void**)&h,  g_h);
    cudaGetSymbolAddress((void**)&r,  g_r);
    cudaGetSymbolAddress((void**)&k,  g_k);
    cudaGetSymbolAddress((void**)&v,  g_v);
    cudaGetSymbolAddress((void**)&w,  g_w);
    cudaGetSymbolAddress((void**)&g,  g_g);
    cudaGetSymbolAddress((void**)&y,  g_y);
    cudaGetSymbolAddress((void**)&Sb, g_Sb);
    cudaGetSymbolAddress((void**)&wt, g_wt);

    __nv_bfloat16 *x5h, *x5l, *ffh, *ffl, *hnh, *hnl, *gnh, *gnl;
    __nv_bfloat16 *pTh, *pTl, *oTh, *oTl, *t1h, *t1l, *t2h, *t2l, *eh, *el;
    cudaGetSymbolAddress((void**)&x5h, g_x5h);
    cudaGetSymbolAddress((void**)&x5l, g_x5l);
    cudaGetSymbolAddress((void**)&ffh, g_ffh);
    cudaGetSymbolAddress((void**)&ffl, g_ffl);
    cudaGetSymbolAddress((void**)&hnh, g_hnh);
    cudaGetSymbolAddress((void**)&hnl, g_hnl);
    cudaGetSymbolAddress((void**)&gnh, g_gnh);
    cudaGetSymbolAddress((void**)&gnl, g_gnl);
    cudaGetSymbolAddress((void**)&pTh, g_pTh);
    cudaGetSymbolAddress((void**)&pTl, g_pTl);
    cudaGetSymbolAddress((void**)&oTh, g_oTh);
    cudaGetSymbolAddress((void**)&oTl, g_oTl);
    cudaGetSymbolAddress((void**)&t1h, g_1Th);
    cudaGetSymbolAddress((void**)&t1l, g_1Tl);
    cudaGetSymbolAddress((void**)&t2h, g_2Th);
    cudaGetSymbolAddress((void**)&t2l, g_2Tl);
    cudaGetSymbolAddress((void**)&eh,  g_eh);
    cudaGetSymbolAddress((void**)&el,  g_el);

    cudaFuncSetAttribute(mma_gemm4, cudaFuncAttributeMaxDynamicSharedMemorySize, MM_SMEM);
    cudaFuncSetAttribute(mma_gemm2, cudaFuncAttributeMaxDynamicSharedMemorySize, MM_SMEM);
    cudaFuncSetAttribute(proj_mma,  cudaFuncAttributeMaxDynamicSharedMemorySize, MM_SMEM);

    // ---- weight prep (replayed every call; deterministic) ----
    dim3 tb(32, 8);
    tsplit_proj<<<dim3(16, 16, 40), tb>>>(Wr, Wk, Wv, Ww, Wg, pTh, pTl);
    tsplit<<<dim3(16, 16, Ll), tb>>>(Wo, oTh, oTl, Dd, Dd);
    tsplit<<<dim3(Ff / 32, 16, Ll), tb>>>(W1, t1h, t1l, Dd, Ff);
    tsplit<<<dim3(16, Ff / 32, Ll), tb>>>(W2, t2h, t2l, Ff, Dd);
    esplit<<<(Vv * Dd) / 256, 256>>>(embed, eh, el);

    embed_kernel<<<(ND / 4) / 256, 256>>>(tokens, embed, h);

    dim3 gridProj(4, 16, 5);          // 128x128 tiles, 5 projections
    dim3 grid512n(4, 32);             // 64x128 tiles for N=512 GEMMs
    dim3 gridF   (16, 16);            // W1 (N=2048)
    dim3 gridV   (250, 16);           // logits

    for (int l = 0; l < Ll; l++) {
        rms_mix5<<<Nrows, 128>>>(h, ln1 + l * Dd, mix + (size_t)l * 5 * Dd, x5h, x5l);

        proj_mma<<<gridProj, 256, MM_SMEM>>>(x5h, x5l, pTh, pTl, l, w0 + l * Dd,
                                             r, k, v, w, g);

        wkv_chunk_kernel  <<<Bb * Hh * NCH, 128>>>(r, k, v, w, u + l * Hh * Dh, y, Sb, wt);
        wkv_combine_kernel<<<(Bb * Hh * Dh * Dh) / 256, 256>>>(Sb, wt);
        wkv_inter_gn_kernel<<<Bb * Hh * NCH, 128>>>(r, Sb, y, g,
                                                    gnw + l * Dd, gnb + l * Dd, gnh, gnl);

        mma_gemm2<<<grid512n, 256, MM_SMEM>>>(gnh, gnl, oTh + (size_t)l * DDm,
                                              oTl + (size_t)l * DDm, h, nullptr, nullptr,
                                              Dd, Dd, 1, nullptr);

        rmsnorm_split_kernel<<<Nrows, 128>>>(h, ln2 + l * Dd, hnh, hnl);
        mma_gemm4<<<gridF, 256, MM_SMEM>>>(hnh, hnl, t1h + (size_t)l * Dd * Ff,
                                           t1l + (size_t)l * Dd * Ff, nullptr, ffh, ffl,
                                           Ff, Dd, 2, nullptr);
        mma_gemm2<<<grid512n, 256, MM_SMEM>>>(ffh, ffl, t2h + (size_t)l * Ff * Dd,
                                              t2l + (size_t)l * Ff * Dd, h, nullptr, nullptr,
                                              Dd, Ff, 1, nullptr);
    }

    rmsnorm_split_kernel<<<Nrows, 128>>>(h, lno, hnh, hnl);
    mma_gemm4<<<gridV, 256, MM_SMEM>>>(hnh, hnl, eh, el, out, nullptr, nullptr,
                                       Vv, Dd, 0, nullptr);
}

// round 6
// speedup vs baseline: 5.7351x; 1.1475x over previous
#include <cuda_runtime.h>
#include <cuda_bf16.h>
#include <math.h>
#include <stdint.h>

// ---- model constants ----
#define Vv   32000
#define Dd   512
#define Ll   8
#define Hh   4
#define Dh   128
#define Ff   2048
#define Bb   2
#define Tt   1024
#define Nrows (Bb*Tt)          // 2048
#define ND   (Nrows*Dd)        // 1048576
#define NF   (Nrows*Ff)        // 4194304
#define DDm  (Dd*Dd)
#define CSZ  32                // wkv chunk length
#define NCH  (Tt/CSZ)          // 32 chunks

// ---- fp32 scratch ----
__device__ float g_h [ND];
__device__ float g_r [ND];
__device__ float g_k [ND];
__device__ float g_v [ND];
__device__ float g_w [ND];
__device__ float g_g [ND];
__device__ float g_y [ND];
__device__ float g_Sb[(size_t)Bb*Hh*NCH*Dh*Dh];
__device__ float g_wt[Bb*Hh*NCH*Dh];

// ---- bf16 hi/lo activation buffers ([M][K] row-major) ----
__device__ __nv_bfloat16 g_x5h[5*ND], g_x5l[5*ND];
__device__ __nv_bfloat16 g_ffh[NF],  g_ffl[NF];
__device__ __nv_bfloat16 g_hnh[ND],  g_hnl[ND];
__device__ __nv_bfloat16 g_gnh[ND],  g_gnl[ND];

// ---- bf16 hi/lo transposed weight caches ([N][K] row-major) ----
__device__ __nv_bfloat16 g_pTh[(size_t)Ll*5*DDm], g_pTl[(size_t)Ll*5*DDm];
__device__ __nv_bfloat16 g_oTh[(size_t)Ll*DDm],   g_oTl[(size_t)Ll*DDm];
__device__ __nv_bfloat16 g_1Th[(size_t)Ll*Dd*Ff], g_1Tl[(size_t)Ll*Dd*Ff];
__device__ __nv_bfloat16 g_2Th[(size_t)Ll*Ff*Dd], g_2Tl[(size_t)Ll*Ff*Dd];
__device__ __nv_bfloat16 g_eh[(size_t)Vv*Dd],     g_el[(size_t)Vv*Dd];

// =========================================================================
// PTX helpers (baseline sm_80+ — legal on compute_103)
// =========================================================================
__device__ __forceinline__ uint32_t s2u(const void* p) {
    uint32_t a;
    asm("{ .reg .u64 t; cvta.to.shared.u64 t, %1; cvt.u32.u64 %0, t; }"
        : "=r"(a) : "l"(p));
    return a;
}
__device__ __forceinline__ void cp16(uint32_t d, const void* s) {
    asm volatile("cp.async.cg.shared.global [%0], [%1], 16;" :: "r"(d), "l"(s));
}
__device__ __forceinline__ void ldm_x4(uint32_t* r, uint32_t addr) {
    asm volatile("ldmatrix.sync.aligned.m8n8.x4.shared.b16 {%0,%1,%2,%3}, [%4];"
        : "=r"(r[0]), "=r"(r[1]), "=r"(r[2]), "=r"(r[3]) : "r"(addr));
}
__device__ __forceinline__ void mma16816(float* d, const uint32_t* a, const uint32_t* b) {
    asm volatile(
        "mma.sync.aligned.m16n8k16.row.col.f32.bf16.bf16.f32 "
        "{%0,%1,%2,%3}, {%4,%5,%6,%7}, {%8,%9}, {%0,%1,%2,%3};"
        : "+f"(d[0]), "+f"(d[1]), "+f"(d[2]), "+f"(d[3])
        : "r"(a[0]), "r"(a[1]), "r"(a[2]), "r"(a[3]), "r"(b[0]), "r"(b[1]));
}

#define SROWB  144          // padded row stride (64 bf16 = 128B data + 16B pad)
#define MM_SMEM4 147456     // 2 stages * (2*128 + 2*128) rows * 144B
#define MM_SMEM2 110592     // 2 stages * (2*64  + 2*128) rows * 144B

// =========================================================================
// hi/lo 3-pass bf16 mma GEMM. CTA tile (MF*32) x 128, K-step 64, 2 stages.
// epi: 0=store fp32, 1=add fp32, 2=gelu->hi/lo bf16, 3=wact, 4=silu
// =========================================================================
template<int MF>
__device__ __forceinline__ void mma_gemm_body(
    const __nv_bfloat16* __restrict__ Ah, const __nv_bfloat16* __restrict__ Al,
    const __nv_bfloat16* __restrict__ Bh, const __nv_bfloat16* __restrict__ Bl,
    float* __restrict__ C, __nv_bfloat16* __restrict__ Ch, __nv_bfloat16* __restrict__ Cl,
    int N, int K, int epi, const float* __restrict__ aux)
{
    extern __shared__ char sm[];
    uint32_t sb = s2u(sm);
    const int BM  = MF * 32;
    const int AB  = BM * SROWB;          // bytes per A array
    const int BB  = 128 * SROWB;         // bytes per B array
    const int STG = 2 * AB + 2 * BB;     // stage bytes
    const int AH_OFF = 0, AL_OFF = AB, BH_OFF = 2 * AB, BL_OFF = 2 * AB + BB;

    int tid = threadIdx.x, lane = tid & 31, wid = tid >> 5;
    int m0 = blockIdx.y * BM, n0 = blockIdx.x * 128;
    int m0w = (wid & 1) * (MF * 16), n0w = (wid >> 1) * 32;

    float acc[MF][4][4];
    #pragma unroll
    for (int a = 0; a < MF; a++)
        #pragma unroll
        for (int b = 0; b < 4; b++)
            #pragma unroll
            for (int c = 0; c < 4; c++) acc[a][b][c] = 0.0f;

    const int nt = K >> 6;               // K / 64

    // prologue: stage 0
    {
        uint32_t base = sb;
        #pragma unroll
        for (int i = 0; i < MF; i++) {   // A: BM*8 chunks
            int id = tid + i * 256;
            int row = id >> 3, c = id & 7;
            uint32_t so = row * SROWB + c * 16;
            size_t ga = (size_t)(m0 + row) * K + c * 8;
            cp16(base + AH_OFF + so, Ah + ga);
            cp16(base + AL_OFF + so, Al + ga);
        }
        #pragma unroll
        for (int i = 0; i < 4; i++) {    // B: 128*8 chunks
            int id = tid + i * 256;
            int row = id >> 3, c = id & 7;
            uint32_t so = row * SROWB + c * 16;
            size_t gb = (size_t)(n0 + row) * K + c * 8;
            cp16(base + BH_OFF + so, Bh + gb);
            cp16(base + BL_OFF + so, Bl + gb);
        }
        asm volatile("cp.async.commit_group;" ::: "memory");
    }

    for (int t = 0; t < nt; t++) {
        if (t + 1 < nt) {
            int k0 = (t + 1) << 6;
            uint32_t base = sb + ((t + 1) & 1) * STG;
            #pragma unroll
            for (int i = 0; i < MF; i++) {
                int id = tid + i * 256;
                int row = id >> 3, c = id & 7;
                uint32_t so = row * SROWB + c * 16;
                size_t ga = (size_t)(m0 + row) * K + k0 + c * 8;
                cp16(base + AH_OFF + so, Ah + ga);
                cp16(base + AL_OFF + so, Al + ga);
            }
            #pragma unroll
            for (int i = 0; i < 4; i++) {
                int id = tid + i * 256;
                int row = id >> 3, c = id & 7;
                uint32_t so = row * SROWB + c * 16;
                size_t gb = (size_t)(n0 + row) * K + k0 + c * 8;
                cp16(base + BH_OFF + so, Bh + gb);
                cp16(base + BL_OFF + so, Bl + gb);
            }
            asm volatile("cp.async.commit_group;" ::: "memory");
            asm volatile("cp.async.wait_group 1;" ::: "memory");
        } else {
            asm volatile("cp.async.wait_group 0;" ::: "memory");
        }
        __syncthreads();

        uint32_t base = sb + (t & 1) * STG;
        #pragma unroll
        for (int kk = 0; kk < 4; kk++) {
            uint32_t aoff = (uint32_t)((m0w + (lane & 15)) * SROWB
                           + kk * 32 + (lane >> 4) * 16);
            uint32_t boff = (uint32_t)((n0w + (lane & 7) + ((lane >> 4) << 3)) * SROWB
                           + kk * 32 + ((lane >> 3) & 1) * 16);
            uint32_t aH[MF][4], aL[MF][4], bH[2][4], bL[2][4];
            #pragma unroll
            for (int mf = 0; mf < MF; mf++)
                ldm_x4(aH[mf], base + AH_OFF + aoff + mf * 16 * SROWB);
            #pragma unroll
            for (int bb = 0; bb < 2; bb++)
                ldm_x4(bH[bb], base + BH_OFF + boff + bb * 16 * SROWB);
            #pragma unroll
            for (int mf = 0; mf < MF; mf++)
                #pragma unroll
                for (int nf = 0; nf < 4; nf++)
                    mma16816(acc[mf][nf], aH[mf], &bH[nf >> 1][(nf & 1) * 2]);
            #pragma unroll
            for (int mf = 0; mf < MF; mf++)
                ldm_x4(aL[mf], base + AL_OFF + aoff + mf * 16 * SROWB);
            #pragma unroll
            for (int mf = 0; mf < MF; mf++)
                #pragma unroll
                for (int nf = 0; nf < 4; nf++)
                    mma16816(acc[mf][nf], aL[mf], &bH[nf >> 1][(nf & 1) * 2]);
            #pragma unroll
            for (int bb = 0; bb < 2; bb++)
                ldm_x4(bL[bb], base + BL_OFF + boff + bb * 16 * SROWB);
            #pragma unroll
            for (int mf = 0; mf < MF; mf++)
                #pragma unroll
                for (int nf = 0; nf < 4; nf++)
                    mma16816(acc[mf][nf], aH[mf], &bL[nf >> 1][(nf & 1) * 2]);
        }
        __syncthreads();
    }

    // ---- epilogue ----
    int qr = lane >> 2, qc = (lane & 3) * 2;
    #pragma unroll
    for (int mf = 0; mf < MF; mf++) {
        #pragma unroll
        for (int nf = 0; nf < 4; nf++) {
            #pragma unroll
            for (int half = 0; half < 2; half++) {
                int row = m0 + m0w + mf * 16 + qr + half * 8;
                int col = n0 + n0w + nf * 8 + qc;
                float x = acc[mf][nf][half * 2 + 0];
                float y = acc[mf][nf][half * 2 + 1];
                size_t o = (size_t)row * N + col;
                if (epi == 0) {
                    *(float2*)(C + o) = make_float2(x, y);
                } else if (epi == 1) {
                    float2 old = *(const float2*)(C + o);
                    *(float2*)(C + o) = make_float2(old.x + x, old.y + y);
                } else if (epi == 2) {
                    x = 0.5f * x * (1.0f + erff(x * 0.70710678118654752f));
                    y = 0.5f * y * (1.0f + erff(y * 0.70710678118654752f));
                    __nv_bfloat162 hv = __floats2bfloat162_rn(x, y);
                    float lx = x - __bfloat162float(__low2bfloat16(hv));
                    float ly = y - __bfloat162float(__high2bfloat16(hv));
                    *(__nv_bfloat162*)(Ch + o) = hv;
                    *(__nv_bfloat162*)(Cl + o) = __floats2bfloat162_rn(lx, ly);
                } else if (epi == 3) {
                    x = expf(-expf(x + aux[col]));
                    y = expf(-expf(y + aux[col + 1]));
                    *(float2*)(C + o) = make_float2(x, y);
                } else {
                    x = x / (1.0f + expf(-x));
                    y = y / (1.0f + expf(-y));
                    *(float2*)(C + o) = make_float2(x, y);
                }
            }
        }
    }
}

__global__ void __launch_bounds__(256, 1)
mma_gemm4(const __nv_bfloat16* __restrict__ Ah, const __nv_bfloat16* __restrict__ Al,
          const __nv_bfloat16* __restrict__ Bh, const __nv_bfloat16* __restrict__ Bl,
          float* __restrict__ C, __nv_bfloat16* __restrict__ Ch,
          __nv_bfloat16* __restrict__ Cl, int N, int K, int epi,
          const float* __restrict__ aux) {
    mma_gemm_body<4>(Ah, Al, Bh, Bl, C, Ch, Cl, N, K, epi, aux);
}
__global__ void __launch_bounds__(256, 2)
mma_gemm2(const __nv_bfloat16* __restrict__ Ah, const __nv_bfloat16* __restrict__ Al,
          const __nv_bfloat16* __restrict__ Bh, const __nv_bfloat16* __restrict__ Bl,
          float* __restrict__ C, __nv_bfloat16* __restrict__ Ch,
          __nv_bfloat16* __restrict__ Cl, int N, int K, int epi,
          const float* __restrict__ aux) {
    mma_gemm_body<2>(Ah, Al, Bh, Bl, C, Ch, Cl, N, K, epi, aux);
}

// batched 5-projection: z selects A slice / weight / output / epilogue
__global__ void __launch_bounds__(256, 2)
proj_mma(const __nv_bfloat16* __restrict__ x5h, const __nv_bfloat16* __restrict__ x5l,
         const __nv_bfloat16* __restrict__ Ph, const __nv_bfloat16* __restrict__ Pl,
         int l, const float* __restrict__ w0,
         float* __restrict__ Cr, float* __restrict__ Ck, float* __restrict__ Cv,
         float* __restrict__ Cw, float* __restrict__ Cg) {
    int z = blockIdx.z;
    size_t wo = ((size_t)l * 5 + z) * DDm;
    float* C = (z == 0) ? Cr : (z == 1) ? Ck : (z == 2) ? Cv : (z == 3) ? Cw : Cg;
    int epi = (z == 3) ? 3 : (z == 4) ? 4 : 0;
    mma_gemm_body<2>(x5h + (size_t)z * ND, x5l + (size_t)z * ND,
                     Ph + wo, Pl + wo, C, nullptr, nullptr, Dd, Dd, epi, w0);
}

// =========================================================================
// weight prep: transpose [K,N] -> [N,K] with bf16 hi/lo split
// =========================================================================
__global__ void tsplit(const float* __restrict__ W, __nv_bfloat16* __restrict__ oh,
                       __nv_bfloat16* __restrict__ ol, int K, int N) {
    __shared__ float ts[32][33];
    size_t mo = (size_t)blockIdx.z * K * N;
    int n0 = blockIdx.x * 32, k0 = blockIdx.y * 32;
    int tx = threadIdx.x, ty = threadIdx.y;
    #pragma unroll
    for (int r = 0; r < 4; r++)
        ts[ty + 8 * r][tx] = W[mo + (size_t)(k0 + ty + 8 * r) * N + n0 + tx];
    __syncthreads();
    #pragma unroll
    for (int r = 0; r < 4; r++) {
        float a = ts[tx][ty + 8 * r];
        float h = __bfloat162float(__float2bfloat16(a));
        size_t o = mo + (size_t)(n0 + ty + 8 * r) * K + k0 + tx;
        oh[o] = __float2bfloat16(a);
        ol[o] = __float2bfloat16(a - h);
    }
}

__global__ void tsplit_proj(const float* __restrict__ Wr, const float* __restrict__ Wk,
                            const float* __restrict__ Wv, const float* __restrict__ Ww,
                            const float* __restrict__ Wg,
                            __nv_bfloat16* __restrict__ oh, __nv_bfloat16* __restrict__ ol) {
    __shared__ float ts[32][33];
    int z = blockIdx.z, p = z % 5, l = z / 5;
    const float* W = ((p == 0) ? Wr : (p == 1) ? Wk : (p == 2) ? Wv :
                      (p == 3) ? Ww : Wg) + (size_t)l * DDm;
    size_t mo = (size_t)z * DDm;
    int n0 = blockIdx.x * 32, k0 = blockIdx.y * 32;
    int tx = threadIdx.x, ty = threadIdx.y;
    #pragma unroll
    for (int r = 0; r < 4; r++)
        ts[ty + 8 * r][tx] = W[(size_t)(k0 + ty + 8 * r) * Dd + n0 + tx];
    __syncthreads();
    #pragma unroll
    for (int r = 0; r < 4; r++) {
        float a = ts[tx][ty + 8 * r];
        float h = __bfloat162float(__float2bfloat16(a));
        size_t o = mo + (size_t)(n0 + ty + 8 * r) * Dd + k0 + tx;
        oh[o] = __float2bfloat16(a);
        ol[o] = __float2bfloat16(a - h);
    }
}

__global__ void esplit(const float* __restrict__ e, __nv_bfloat16* __restrict__ eh,
                       __nv_bfloat16* __restrict__ el) {
    int idx = blockIdx.x * blockDim.x + threadIdx.x;
    float a = e[idx];
    float h = __bfloat162float(__float2bfloat16(a));
    eh[idx] = __float2bfloat16(a);
    el[idx] = __float2bfloat16(a - h);
}

// =========================================================================
// embedding gather
// =========================================================================
__global__ void embed_kernel(const int* __restrict__ tok,
                             const float* __restrict__ emb,
                             float* __restrict__ h) {
    int idx = blockIdx.x * blockDim.x + threadIdx.x;
    int row = idx >> 7;
    int c4  = idx & 127;
    ((float4*)h)[idx] = ((const float4*)emb)[(size_t)tok[row] * 128 + c4];
}

// =========================================================================
// fused rmsnorm + token-shift + 5-way lerp -> hi/lo bf16. Block per row.
// =========================================================================
__global__ void __launch_bounds__(128)
rms_mix5(const float* __restrict__ h, const float* __restrict__ lnw,
         const float* __restrict__ mix,
         __nv_bfloat16* __restrict__ xh, __nv_bfloat16* __restrict__ xl) {
    int row = blockIdx.x, tid = threadIdx.x;
    int t = row & (Tt - 1);
    float4 a = ((const float4*)(h + (size_t)row * Dd))[tid];
    float4 p = (t == 0) ? make_float4(0, 0, 0, 0)
                        : ((const float4*)(h + (size_t)(row - 1) * Dd))[tid];
    float sc_ = a.x*a.x + a.y*a.y + a.z*a.z + a.w*a.w;
    float sp_ = p.x*p.x + p.y*p.y + p.z*p.z + p.w*p.w;
    #pragma unroll
    for (int s = 16; s > 0; s >>= 1) {
        sc_ += __shfl_xor_sync(0xffffffffu, sc_, s);
        sp_ += __shfl_xor_sync(0xffffffffu, sp_, s);
    }
    __shared__ float rc[4], rp[4];
    if ((tid & 31) == 0) { rc[tid >> 5] = sc_; rp[tid >> 5] = sp_; }
    __syncthreads();
    float totc = rc[0] + rc[1] + rc[2] + rc[3];
    float totp = rp[0] + rp[1] + rp[2] + rp[3];
    float scc = rsqrtf(totc * (1.0f / Dd) + 1e-6f);
    float scp = (t == 0) ? 0.0f : rsqrtf(totp * (1.0f / Dd) + 1e-6f);
    float4 wv = ((const float4*)lnw)[tid];
    float cn[4] = {a.x * scc * wv.x, a.y * scc * wv.y, a.z * scc * wv.z, a.w * scc * wv.w};
    float pn[4] = {p.x * scp * wv.x, p.y * scp * wv.y, p.z * scp * wv.z, p.w * scp * wv.w};
    int c0 = tid * 4;
    size_t ro = (size_t)row * Dd + c0;
    #pragma unroll
    for (int j = 0; j < 5; j++) {
        #pragma unroll
        for (int i = 0; i < 4; i++) {
            float v = fmaf(pn[i] - cn[i], mix[j * Dd + c0 + i], cn[i]);
            float hv = __bfloat162float(__float2bfloat16(v));
            xh[(size_t)j * ND + ro + i] = __float2bfloat16(v);
            xl[(size_t)j * ND + ro + i] = __float2bfloat16(v - hv);
        }
    }
}

// hi/lo-out rmsnorm (feeds FFN GEMM / logits)
__global__ void rmsnorm_split_kernel(const float* __restrict__ x,
                                     const float* __restrict__ w,
                                     __nv_bfloat16* __restrict__ oh,
                                     __nv_bfloat16* __restrict__ ol) {
    int row = blockIdx.x;
    int tid = threadIdx.x;
    float4 a = ((const float4*)(x + (size_t)row * Dd))[tid];
    float ss = a.x*a.x + a.y*a.y + a.z*a.z + a.w*a.w;
    #pragma unroll
    for (int s = 16; s > 0; s >>= 1) ss += __shfl_xor_sync(0xffffffffu, ss, s);
    __shared__ float sred[4];
    if ((tid & 31) == 0) sred[tid >> 5] = ss;
    __syncthreads();
    float tot = sred[0] + sred[1] + sred[2] + sred[3];
    float sc  = rsqrtf(tot * (1.0f / Dd) + 1e-6f);
    float4 wv = ((const float4*)w)[tid];
    float vv[4] = {a.x * sc * wv.x, a.y * sc * wv.y, a.z * sc * wv.z, a.w * sc * wv.w};
    size_t o = (size_t)row * Dd + tid * 4;
    #pragma unroll
    for (int i = 0; i < 4; i++) {
        float h = __bfloat162float(__float2bfloat16(vv[i]));
        oh[o + i] = __float2bfloat16(vv[i]);
        ol[o + i] = __float2bfloat16(vv[i] - h);
    }
}

// =========================================================================
// WKV phase 1: per-chunk local recurrence
// =========================================================================
__global__ void __launch_bounds__(128, 3)
wkv_chunk_kernel(float* __restrict__ r, const float* __restrict__ k,
                 const float* __restrict__ v, const float* __restrict__ w,
                 const float* __restrict__ u, float* __restrict__ y,
                 float* __restrict__ Sb, float* __restrict__ wt) {
    int blk = blockIdx.x;
    int bh  = blk / NCH;
    int ch  = blk % NCH;
    int b = bh >> 2, h = bh & 3;
    int j = threadIdx.x;
    __shared__ float4 s[Dh];
    float uj = u[h * Dh + j];
    float S[Dh];
    #pragma unroll
    for (int i = 0; i < Dh; i++) S[i] = 0.0f;
    float p = 1.0f;
    size_t off = (size_t)b * Tt * Dd + (size_t)(ch * CSZ) * Dd + h * Dh + j;
    for (int t = 0; t < CSZ; t++, off += Dd) {
        float rv = r[off], kv_ = k[off], wv = w[off], vv = v[off];
        __syncthreads();
        s[j] = make_float4(rv, kv_, wv, uj);
        __syncthreads();
        r[off] = rv * p;
        p *= wv;
        float acc = 0.0f;
        #pragma unroll
        for (int i = 0; i < Dh; i++) {
            float4 q = s[i];
            float kv = q.y * vv;
            acc  = fmaf(q.x, fmaf(q.w, kv, S[i]), acc);
            S[i] = fmaf(q.z, S[i], kv);
        }
        y[off] = acc;
    }
    wt[blk * Dh + j] = p;
    size_t base = (size_t)blk * Dh * Dh;
    #pragma unroll
    for (int i = 0; i < Dh; i++) Sb[base + (size_t)i * Dh + j] = S[i];
}

// =========================================================================
// WKV phase 2: parallel elementwise scan over chunks. One thread per (bh,i,j).
// =========================================================================
__global__ void __launch_bounds__(256)
wkv_combine_kernel(float* __restrict__ Sb, const float* __restrict__ wt) {
    int idx = blockIdx.x * blockDim.x + threadIdx.x;   // over Bb*Hh*Dh*Dh
    int bh  = idx >> 14;
    int rem = idx & 16383;
    int i   = rem >> 7;
    float run = 0.0f;
    #pragma unroll 4
    for (int ch = 0; ch < NCH; ch++) {
        int blk = bh * NCH + ch;
        size_t o = ((size_t)blk << 14) + rem;
        float m = Sb[o];
        Sb[o] = run;
        run = fmaf(run, wt[blk * Dh + i], m);
    }
}

// =========================================================================
// WKV phase 3 + GroupNorm + gate fused. Block per (bh,chunk), 128 threads.
// =========================================================================
__global__ void __launch_bounds__(128, 3)
wkv_inter_gn_kernel(const float* __restrict__ rt, const float* __restrict__ Sb,
                    const float* __restrict__ y, const float* __restrict__ g,
                    const float* __restrict__ gw, const float* __restrict__ gb,
                    __nv_bfloat16* __restrict__ oh, __nv_bfloat16* __restrict__ ol) {
    int blk = blockIdx.x;
    int bh  = blk / NCH;
    int ch  = blk % NCH;
    int b = bh >> 2, h = bh & 3;
    int j = threadIdx.x;
    int lane = j & 31, wid = j >> 5;
    float Scol[Dh];
    size_t base = (size_t)blk * Dh * Dh;
    #pragma unroll
    for (int i = 0; i < Dh; i++) Scol[i] = Sb[base + (size_t)i * Dh + j];
    __shared__ float sr[Dh];
    __shared__ float r1[4], r2[4];
    int c = h * Dh + j;
    float gwj = gw[c], gbj = gb[c];
    size_t off = (size_t)b * Tt * Dd + (size_t)(ch * CSZ) * Dd + h * Dh + j;
    for (int t = 0; t < CSZ; t++, off += Dd) {
        __syncthreads();
        sr[j] = rt[off];
        __syncthreads();
        float acc = y[off];
        #pragma unroll
        for (int i = 0; i < Dh; i++) acc = fmaf(sr[i], Scol[i], acc);
        float s1 = acc, s2 = acc * acc;
        #pragma unroll
        for (int s = 16; s > 0; s >>= 1) {
            s1 += __shfl_xor_sync(0xffffffffu, s1, s);
            s2 += __shfl_xor_sync(0xffffffffu, s2, s);
        }
        if (lane == 0) { r1[wid] = s1; r2[wid] = s2; }
        __syncthreads();
        s1 = r1[0] + r1[1] + r1[2] + r1[3];
        s2 = r2[0] + r2[1] + r2[2] + r2[3];
        float mu  = s1 * (1.0f / Dh);
        float var = s2 * (1.0f / Dh) - mu * mu;
        float nrm = (acc - mu) * rsqrtf(var + 1e-5f);
        float val = fmaf(nrm, gwj, gbj) * g[off];
        float hv = __bfloat162float(__float2bfloat16(val));
        oh[off] = __float2bfloat16(val);
        ol[off] = __float2bfloat16(val - hv);
    }
}

// =========================================================================
// host driver
// =========================================================================
extern "C" void kernel_launch(void* const* d_in, const int* in_sizes, int n_in,
                              void* d_out, int out_size) {
    const int*   tokens = (const int*)  d_in[0];
    const float* embed  = (const float*)d_in[1];
    const float* ln1    = (const float*)d_in[2];
    const float* ln2    = (const float*)d_in[3];
    const float* lno    = (const float*)d_in[4];
    const float* mix    = (const float*)d_in[5];
    const float* Wr     = (const float*)d_in[6];
    const float* Wk     = (const float*)d_in[7];
    const float* Wv     = (const float*)d_in[8];
    const float* Wg     = (const float*)d_in[9];
    const float* Ww     = (const float*)d_in[10];
    const float* w0     = (const float*)d_in[11];
    const float* Wo     = (const float*)d_in[12];
    const float* u      = (const float*)d_in[13];
    const float* gnw    = (const float*)d_in[14];
    const float* gnb    = (const float*)d_in[15];
    const float* W1     = (const float*)d_in[16];
    const float* W2     = (const float*)d_in[17];
    float* out = (float*)d_out;

    float *h, *r, *k, *v, *w, *g, *y, *Sb, *wt;
    cudaGetSymbolAddress((void**)&h,  g_h);
    cudaGetSymbolAddress((void**)&r,  g_r);
    cudaGetSymbolAddress((void**)&k,  g_k);
    cudaGetSymbolAddress((void**)&v,  g_v);
    cudaGetSymbolAddress((void**)&w,  g_w);
    cudaGetSymbolAddress((void**)&g,  g_g);
    cudaGetSymbolAddress((void**)&y,  g_y);
    cudaGetSymbolAddress((void**)&Sb, g_Sb);
    cudaGetSymbolAddress((void**)&wt, g_wt);

    __nv_bfloat16 *x5h, *x5l, *ffh, *ffl, *hnh, *hnl, *gnh, *gnl;
    __nv_bfloat16 *pTh, *pTl, *oTh, *oTl, *t1h, *t1l, *t2h, *t2l, *eh, *el;
    cudaGetSymbolAddress((void**)&x5h, g_x5h);
    cudaGetSymbolAddress((void**)&x5l, g_x5l);
    cudaGetSymbolAddress((void**)&ffh, g_ffh);
    cudaGetSymbolAddress((void**)&ffl, g_ffl);
    cudaGetSymbolAddress((void**)&hnh, g_hnh);
    cudaGetSymbolAddress((void**)&hnl, g_hnl);
    cudaGetSymbolAddress((void**)&gnh, g_gnh);
    cudaGetSymbolAddress((void**)&gnl, g_gnl);
    cudaGetSymbolAddress((void**)&pTh, g_pTh);
    cudaGetSymbolAddress((void**)&pTl, g_pTl);
    cudaGetSymbolAddress((void**)&oTh, g_oTh);
    cudaGetSymbolAddress((void**)&oTl, g_oTl);
    cudaGetSymbolAddress((void**)&t1h, g_1Th);
    cudaGetSymbolAddress((void**)&t1l, g_1Tl);
    cudaGetSymbolAddress((void**)&t2h, g_2Th);
    cudaGetSymbolAddress((void**)&t2l, g_2Tl);
    cudaGetSymbolAddress((void**)&eh,  g_eh);
    cudaGetSymbolAddress((void**)&el,  g_el);

    cudaFuncSetAttribute(mma_gemm4, cudaFuncAttributeMaxDynamicSharedMemorySize, MM_SMEM4);
    cudaFuncSetAttribute(mma_gemm2, cudaFuncAttributeMaxDynamicSharedMemorySize, MM_SMEM2);
    cudaFuncSetAttribute(proj_mma,  cudaFuncAttributeMaxDynamicSharedMemorySize, MM_SMEM2);

    // ---- weight prep (replayed every call; deterministic) ----
    dim3 tb(32, 8);
    tsplit_proj<<<dim3(16, 16, 40), tb>>>(Wr, Wk, Wv, Ww, Wg, pTh, pTl);
    tsplit<<<dim3(16, 16, Ll), tb>>>(Wo, oTh, oTl, Dd, Dd);
    tsplit<<<dim3(Ff / 32, 16, Ll), tb>>>(W1, t1h, t1l, Dd, Ff);
    tsplit<<<dim3(16, Ff / 32, Ll), tb>>>(W2, t2h, t2l, Ff, Dd);
    esplit<<<(Vv * Dd) / 256, 256>>>(embed, eh, el);

    embed_kernel<<<(ND / 4) / 256, 256>>>(tokens, embed, h);

    dim3 gridProj(4, 32, 5);          // 64x128 tiles, 5 projections
    dim3 grid512n(4, 32);             // 64x128 tiles for N=512 GEMMs
    dim3 gridF   (16, 32);            // W1 (N=2048), 64x128 tiles
    dim3 gridV   (250, 16);           // logits, 128x128 tiles

    for (int l = 0; l < Ll; l++) {
        rms_mix5<<<Nrows, 128>>>(h, ln1 + l * Dd, mix + (size_t)l * 5 * Dd, x5h, x5l);

        proj_mma<<<gridProj, 256, MM_SMEM2>>>(x5h, x5l, pTh, pTl, l, w0 + l * Dd,
                                              r, k, v, w, g);

        wkv_chunk_kernel  <<<Bb * Hh * NCH, 128>>>(r, k, v, w, u + l * Hh * Dh, y, Sb, wt);
        wkv_combine_kernel<<<(Bb * Hh * Dh * Dh) / 256, 256>>>(Sb, wt);
        wkv_inter_gn_kernel<<<Bb * Hh * NCH, 128>>>(r, Sb, y, g,
                                                    gnw + l * Dd, gnb + l * Dd, gnh, gnl);

        mma_gemm2<<<grid512n, 256, MM_SMEM2>>>(gnh, gnl, oTh + (size_t)l * DDm,
                                               oTl + (size_t)l * DDm, h, nullptr, nullptr,
                                               Dd, Dd, 1, nullptr);

        rmsnorm_split_kernel<<<Nrows, 128>>>(h, ln2 + l * Dd, hnh, hnl);
        mma_gemm2<<<gridF, 256, MM_SMEM2>>>(hnh, hnl, t1h + (size_t)l * Dd * Ff,
                                            t1l + (size_t)l * Dd * Ff, nullptr, ffh, ffl,
                                            Ff, Dd, 2, nullptr);
        mma_gemm2<<<grid512n, 256, MM_SMEM2>>>(ffh, ffl, t2h + (size_t)l * Ff * Dd,
                                               t2l + (size_t)l * Ff * Dd, h, nullptr, nullptr,
                                               Dd, Ff, 1, nullptr);
    }

    rmsnorm_split_kernel<<<Nrows, 128>>>(h, lno, hnh, hnl);
    mma_gemm4<<<gridV, 256, MM_SMEM4>>>(hnh, hnl, eh, el, out, nullptr, nullptr,
                                        Vv, Dd, 0, nullptr);
}

// round 7
// speedup vs baseline: 6.1489x; 1.0722x over previous
#include <cuda_runtime.h>
#include <cuda_bf16.h>
#include <cuda_fp16.h>
#include <math.h>
#include <stdint.h>

// ---- model constants ----
#define Vv   32000
#define Dd   512
#define Ll   8
#define Hh   4
#define Dh   128
#define Ff   2048
#define Bb   2
#define Tt   1024
#define Nrows (Bb*Tt)          // 2048
#define ND   (Nrows*Dd)        // 1048576
#define NF   (Nrows*Ff)        // 4194304
#define DDm  (Dd*Dd)
#define CSZ  32                // wkv chunk length
#define NCH  (Tt/CSZ)          // 32 chunks

// ---- fp32 scratch ----
__device__ float g_h [ND];
__device__ float g_r [ND];
__device__ float g_k [ND];
__device__ float g_v [ND];
__device__ float g_w [ND];
__device__ float g_g [ND];
__device__ float g_y [ND];
__device__ float g_Sb[(size_t)Bb*Hh*NCH*Dh*Dh];
__device__ float g_wt[Bb*Hh*NCH*Dh];

// ---- bf16 hi/lo activation buffers ([M][K] row-major) ----
__device__ __nv_bfloat16 g_x5h[5*ND], g_x5l[5*ND];
__device__ __nv_bfloat16 g_ffh[NF],  g_ffl[NF];
__device__ __nv_bfloat16 g_hnh[ND],  g_hnl[ND];
__device__ __nv_bfloat16 g_gnh[ND],  g_gnl[ND];

// ---- fp16 buffers for the 2-pass logits GEMM ----
__device__ __half g_e16[(size_t)Vv*Dd];          // embed hi (fp16)
__device__ __half g_h16h[ND], g_h16l[ND];        // final rmsnorm hi/lo (fp16)

// ---- bf16 hi/lo transposed weight caches ([N][K] row-major) ----
__device__ __nv_bfloat16 g_pTh[(size_t)Ll*5*DDm], g_pTl[(size_t)Ll*5*DDm];
__device__ __nv_bfloat16 g_oTh[(size_t)Ll*DDm],   g_oTl[(size_t)Ll*DDm];
__device__ __nv_bfloat16 g_1Th[(size_t)Ll*Dd*Ff], g_1Tl[(size_t)Ll*Dd*Ff];
__device__ __nv_bfloat16 g_2Th[(size_t)Ll*Ff*Dd], g_2Tl[(size_t)Ll*Ff*Dd];

// =========================================================================
// PTX helpers (baseline sm_80+ — legal on compute_103)
// =========================================================================
__device__ __forceinline__ uint32_t s2u(const void* p) {
    uint32_t a;
    asm("{ .reg .u64 t; cvta.to.shared.u64 t, %1; cvt.u32.u64 %0, t; }"
        : "=r"(a) : "l"(p));
    return a;
}
__device__ __forceinline__ void cp16(uint32_t d, const void* s) {
    asm volatile("cp.async.cg.shared.global [%0], [%1], 16;" :: "r"(d), "l"(s));
}
__device__ __forceinline__ void ldm_x4(uint32_t* r, uint32_t addr) {
    asm volatile("ldmatrix.sync.aligned.m8n8.x4.shared.b16 {%0,%1,%2,%3}, [%4];"
        : "=r"(r[0]), "=r"(r[1]), "=r"(r[2]), "=r"(r[3]) : "r"(addr));
}
__device__ __forceinline__ void mma_bf16(float* d, const uint32_t* a, const uint32_t* b) {
    asm volatile(
        "mma.sync.aligned.m16n8k16.row.col.f32.bf16.bf16.f32 "
        "{%0,%1,%2,%3}, {%4,%5,%6,%7}, {%8,%9}, {%0,%1,%2,%3};"
        : "+f"(d[0]), "+f"(d[1]), "+f"(d[2]), "+f"(d[3])
        : "r"(a[0]), "r"(a[1]), "r"(a[2]), "r"(a[3]), "r"(b[0]), "r"(b[1]));
}
__device__ __forceinline__ void mma_f16(float* d, const uint32_t* a, const uint32_t* b) {
    asm volatile(
        "mma.sync.aligned.m16n8k16.row.col.f32.f16.f16.f32 "
        "{%0,%1,%2,%3}, {%4,%5,%6,%7}, {%8,%9}, {%0,%1,%2,%3};"
        : "+f"(d[0]), "+f"(d[1]), "+f"(d[2]), "+f"(d[3])
        : "r"(a[0]), "r"(a[1]), "r"(a[2]), "r"(a[3]), "r"(b[0]), "r"(b[1]));
}

#define SROWB  144          // padded row stride (64 elems * 2B = 128B + 16B pad)
#define MM_SMEM2 110592     // MF=2 bf16: 2 stages * (2*64 + 2*128) rows * 144B
#define MM_SMEMH 110592     // MF=4 fp16 2-pass: 2 stages * (2*128 + 1*128) * 144B

// =========================================================================
// hi/lo multi-pass mma GEMM. CTA tile (MF*32) x 128, K-step 64, 2 stages.
// H2=false: bf16 3-pass (A hi/lo, B hi/lo). H2=true: fp16 2-pass (A hi/lo, B hi).
// epi: 0=store fp32, 1=add fp32, 2=gelu->hi/lo bf16, 3=wact, 4=silu
// =========================================================================
template<int MF, bool H2>
__device__ __forceinline__ void mma_gemm_body(
    const void* __restrict__ Ahv, const void* __restrict__ Alv,
    const void* __restrict__ Bhv, const void* __restrict__ Blv,
    float* __restrict__ C, __nv_bfloat16* __restrict__ Ch, __nv_bfloat16* __restrict__ Cl,
    int N, int K, int epi, const float* __restrict__ aux)
{
    const __nv_bfloat16* Ah = (const __nv_bfloat16*)Ahv;
    const __nv_bfloat16* Al = (const __nv_bfloat16*)Alv;
    const __nv_bfloat16* Bh = (const __nv_bfloat16*)Bhv;
    const __nv_bfloat16* Bl = (const __nv_bfloat16*)Blv;

    extern __shared__ char sm[];
    uint32_t sb = s2u(sm);
    const int BM  = MF * 32;
    const int AB  = BM * SROWB;          // bytes per A array
    const int BB  = 128 * SROWB;         // bytes per B array
    const int NB  = H2 ? 1 : 2;          // number of B arrays
    const int STG = 2 * AB + NB * BB;    // stage bytes
    const int AH_OFF = 0, AL_OFF = AB, BH_OFF = 2 * AB, BL_OFF = 2 * AB + BB;

    int tid = threadIdx.x, lane = tid & 31, wid = tid >> 5;
    int m0 = blockIdx.y * BM, n0 = blockIdx.x * 128;
    int m0w = (wid & 1) * (MF * 16), n0w = (wid >> 1) * 32;

    float acc[MF][4][4];
    #pragma unroll
    for (int a = 0; a < MF; a++)
        #pragma unroll
        for (int b = 0; b < 4; b++)
            #pragma unroll
            for (int c = 0; c < 4; c++) acc[a][b][c] = 0.0f;

    const int nt = K >> 6;               // K / 64

    // prologue: stage 0
    {
        uint32_t base = sb;
        #pragma unroll
        for (int i = 0; i < MF; i++) {
            int id = tid + i * 256;
            int row = id >> 3, c = id & 7;
            uint32_t so = row * SROWB + c * 16;
            size_t ga = (size_t)(m0 + row) * K + c * 8;
            cp16(base + AH_OFF + so, Ah + ga);
            cp16(base + AL_OFF + so, Al + ga);
        }
        #pragma unroll
        for (int i = 0; i < 4; i++) {
            int id = tid + i * 256;
            int row = id >> 3, c = id & 7;
            uint32_t so = row * SROWB + c * 16;
            size_t gb = (size_t)(n0 + row) * K + c * 8;
            cp16(base + BH_OFF + so, Bh + gb);
            if (!H2) cp16(base + BL_OFF + so, Bl + gb);
        }
        asm volatile("cp.async.commit_group;" ::: "memory");
    }

    for (int t = 0; t < nt; t++) {
        if (t + 1 < nt) {
            int k0 = (t + 1) << 6;
            uint32_t base = sb + ((t + 1) & 1) * STG;
            #pragma unroll
            for (int i = 0; i < MF; i++) {
                int id = tid + i * 256;
                int row = id >> 3, c = id & 7;
                uint32_t so = row * SROWB + c * 16;
                size_t ga = (size_t)(m0 + row) * K + k0 + c * 8;
                cp16(base + AH_OFF + so, Ah + ga);
                cp16(base + AL_OFF + so, Al + ga);
            }
            #pragma unroll
            for (int i = 0; i < 4; i++) {
                int id = tid + i * 256;
                int row = id >> 3, c = id & 7;
                uint32_t so = row * SROWB + c * 16;
                size_t gb = (size_t)(n0 + row) * K + k0 + c * 8;
                cp16(base + BH_OFF + so, Bh + gb);
                if (!H2) cp16(base + BL_OFF + so, Bl + gb);
            }
            asm volatile("cp.async.commit_group;" ::: "memory");
            asm volatile("cp.async.wait_group 1;" ::: "memory");
        } else {
            asm volatile("cp.async.wait_group 0;" ::: "memory");
        }
        __syncthreads();

        uint32_t base = sb + (t & 1) * STG;
        #pragma unroll
        for (int kk = 0; kk < 4; kk++) {
            uint32_t aoff = (uint32_t)((m0w + (lane & 15)) * SROWB
                           + kk * 32 + (lane >> 4) * 16);
            uint32_t boff = (uint32_t)((n0w + (lane & 7) + ((lane >> 4) << 3)) * SROWB
                           + kk * 32 + ((lane >> 3) & 1) * 16);
            uint32_t aH[MF][4], aL[MF][4], bH[2][4], bL[2][4];
            #pragma unroll
            for (int mf = 0; mf < MF; mf++)
                ldm_x4(aH[mf], base + AH_OFF + aoff + mf * 16 * SROWB);
            #pragma unroll
            for (int bb = 0; bb < 2; bb++)
                ldm_x4(bH[bb], base + BH_OFF + boff + bb * 16 * SROWB);
            #pragma unroll
            for (int mf = 0; mf < MF; mf++)
                #pragma unroll
                for (int nf = 0; nf < 4; nf++) {
                    if (H2) mma_f16 (acc[mf][nf], aH[mf], &bH[nf >> 1][(nf & 1) * 2]);
                    else    mma_bf16(acc[mf][nf], aH[mf], &bH[nf >> 1][(nf & 1) * 2]);
                }
            #pragma unroll
            for (int mf = 0; mf < MF; mf++)
                ldm_x4(aL[mf], base + AL_OFF + aoff + mf * 16 * SROWB);
            #pragma unroll
            for (int mf = 0; mf < MF; mf++)
                #pragma unroll
                for (int nf = 0; nf < 4; nf++) {
                    if (H2) mma_f16 (acc[mf][nf], aL[mf], &bH[nf >> 1][(nf & 1) * 2]);
                    else    mma_bf16(acc[mf][nf], aL[mf], &bH[nf >> 1][(nf & 1) * 2]);
                }
            if (!H2) {
                #pragma unroll
                for (int bb = 0; bb < 2; bb++)
                    ldm_x4(bL[bb], base + BL_OFF + boff + bb * 16 * SROWB);
                #pragma unroll
                for (int mf = 0; mf < MF; mf++)
                    #pragma unroll
                    for (int nf = 0; nf < 4; nf++)
                        mma_bf16(acc[mf][nf], aH[mf], &bL[nf >> 1][(nf & 1) * 2]);
            }
        }
        __syncthreads();
    }

    // ---- epilogue ----
    int qr = lane >> 2, qc = (lane & 3) * 2;
    #pragma unroll
    for (int mf = 0; mf < MF; mf++) {
        #pragma unroll
        for (int nf = 0; nf < 4; nf++) {
            #pragma unroll
            for (int half = 0; half < 2; half++) {
                int row = m0 + m0w + mf * 16 + qr + half * 8;
                int col = n0 + n0w + nf * 8 + qc;
                float x = acc[mf][nf][half * 2 + 0];
                float y = acc[mf][nf][half * 2 + 1];
                size_t o = (size_t)row * N + col;
                if (epi == 0) {
                    *(float2*)(C + o) = make_float2(x, y);
                } else if (epi == 1) {
                    float2 old = *(const float2*)(C + o);
                    *(float2*)(C + o) = make_float2(old.x + x, old.y + y);
                } else if (epi == 2) {
                    x = 0.5f * x * (1.0f + erff(x * 0.70710678118654752f));
                    y = 0.5f * y * (1.0f + erff(y * 0.70710678118654752f));
                    __nv_bfloat162 hv = __floats2bfloat162_rn(x, y);
                    float lx = x - __bfloat162float(__low2bfloat16(hv));
                    float ly = y - __bfloat162float(__high2bfloat16(hv));
                    *(__nv_bfloat162*)(Ch + o) = hv;
                    *(__nv_bfloat162*)(Cl + o) = __floats2bfloat162_rn(lx, ly);
                } else if (epi == 3) {
                    x = expf(-expf(x + aux[col]));
                    y = expf(-expf(y + aux[col + 1]));
                    *(float2*)(C + o) = make_float2(x, y);
                } else {
                    x = x / (1.0f + expf(-x));
                    y = y / (1.0f + expf(-y));
                    *(float2*)(C + o) = make_float2(x, y);
                }
            }
        }
    }
}

__global__ void __launch_bounds__(256, 2)
mma_gemm2(const __nv_bfloat16* __restrict__ Ah, const __nv_bfloat16* __restrict__ Al,
          const __nv_bfloat16* __restrict__ Bh, const __nv_bfloat16* __restrict__ Bl,
          float* __restrict__ C, __nv_bfloat16* __restrict__ Ch,
          __nv_bfloat16* __restrict__ Cl, int N, int K, int epi,
          const float* __restrict__ aux) {
    mma_gemm_body<2, false>(Ah, Al, Bh, Bl, C, Ch, Cl, N, K, epi, aux);
}

// fp16 2-pass GEMM (logits): A hi/lo fp16, B hi fp16
__global__ void __launch_bounds__(256, 2)
mma_gemm_h2(const __half* __restrict__ Ah, const __half* __restrict__ Al,
            const __half* __restrict__ Bh, float* __restrict__ C, int N, int K) {
    mma_gemm_body<4, true>(Ah, Al, Bh, nullptr, C, nullptr, nullptr, N, K, 0, nullptr);
}

// batched 5-projection: z selects A slice / weight / output / epilogue
__global__ void __launch_bounds__(256, 2)
proj_mma(const __nv_bfloat16* __restrict__ x5h, const __nv_bfloat16* __restrict__ x5l,
         const __nv_bfloat16* __restrict__ Ph, const __nv_bfloat16* __restrict__ Pl,
         int l, const float* __restrict__ w0,
         float* __restrict__ Cr, float* __restrict__ Ck, float* __restrict__ Cv,
         float* __restrict__ Cw, float* __restrict__ Cg) {
    int z = blockIdx.z;
    size_t wo = ((size_t)l * 5 + z) * DDm;
    float* C = (z == 0) ? Cr : (z == 1) ? Ck : (z == 2) ? Cv : (z == 3) ? Cw : Cg;
    int epi = (z == 3) ? 3 : (z == 4) ? 4 : 0;
    mma_gemm_body<2, false>(x5h + (size_t)z * ND, x5l + (size_t)z * ND,
                            Ph + wo, Pl + wo, C, nullptr, nullptr, Dd, Dd, epi, w0);
}

// =========================================================================
// weight prep: transpose [K,N] -> [N,K] with bf16 hi/lo split
// =========================================================================
__global__ void tsplit(const float* __restrict__ W, __nv_bfloat16* __restrict__ oh,
                       __nv_bfloat16* __restrict__ ol, int K, int N) {
    __shared__ float ts[32][33];
    size_t mo = (size_t)blockIdx.z * K * N;
    int n0 = blockIdx.x * 32, k0 = blockIdx.y * 32;
    int tx = threadIdx.x, ty = threadIdx.y;
    #pragma unroll
    for (int r = 0; r < 4; r++)
        ts[ty + 8 * r][tx] = W[mo + (size_t)(k0 + ty + 8 * r) * N + n0 + tx];
    __syncthreads();
    #pragma unroll
    for (int r = 0; r < 4; r++) {
        float a = ts[tx][ty + 8 * r];
        float h = __bfloat162float(__float2bfloat16(a));
        size_t o = mo + (size_t)(n0 + ty + 8 * r) * K + k0 + tx;
        oh[o] = __float2bfloat16(a);
        ol[o] = __float2bfloat16(a - h);
    }
}

// proj (z<40: 5 weights x 8 layers) + Wo (z in [40,48))
__global__ void tsplit_projWo(const float* __restrict__ Wr, const float* __restrict__ Wk,
                              const float* __restrict__ Wv, const float* __restrict__ Ww,
                              const float* __restrict__ Wg, const float* __restrict__ Wo,
                              __nv_bfloat16* __restrict__ ph, __nv_bfloat16* __restrict__ pl,
                              __nv_bfloat16* __restrict__ ohd, __nv_bfloat16* __restrict__ old_) {
    __shared__ float ts[32][33];
    int z = blockIdx.z;
    const float* W;
    __nv_bfloat16 *oh, *ol;
    size_t mo;
    if (z < 40) {
        int p = z % 5, l = z / 5;
        W = ((p == 0) ? Wr : (p == 1) ? Wk : (p == 2) ? Wv :
             (p == 3) ? Ww : Wg) + (size_t)l * DDm;
        mo = (size_t)z * DDm;
        oh = ph; ol = pl;
    } else {
        int l = z - 40;
        W = Wo + (size_t)l * DDm;
        mo = (size_t)l * DDm;
        oh = ohd; ol = old_;
    }
    int n0 = blockIdx.x * 32, k0 = blockIdx.y * 32;
    int tx = threadIdx.x, ty = threadIdx.y;
    #pragma unroll
    for (int r = 0; r < 4; r++)
        ts[ty + 8 * r][tx] = W[(size_t)(k0 + ty + 8 * r) * Dd + n0 + tx];
    __syncthreads();
    #pragma unroll
    for (int r = 0; r < 4; r++) {
        float a = ts[tx][ty + 8 * r];
        float h = __bfloat162float(__float2bfloat16(a));
        size_t o = mo + (size_t)(n0 + ty + 8 * r) * Dd + k0 + tx;
        oh[o] = __float2bfloat16(a);
        ol[o] = __float2bfloat16(a - h);
    }
}

__global__ void esplit_f16(const float* __restrict__ e, __half* __restrict__ e16) {
    int idx = blockIdx.x * blockDim.x + threadIdx.x;
    e16[idx] = __float2half(e[idx]);
}

// =========================================================================
// embedding gather
// =========================================================================
__global__ void embed_kernel(const int* __restrict__ tok,
                             const float* __restrict__ emb,
                             float* __restrict__ h) {
    int idx = blockIdx.x * blockDim.x + threadIdx.x;
    int row = idx >> 7;
    int c4  = idx & 127;
    ((float4*)h)[idx] = ((const float4*)emb)[(size_t)tok[row] * 128 + c4];
}

// =========================================================================
// fused rmsnorm + token-shift + 5-way lerp -> hi/lo bf16. Block per row.
// =========================================================================
__global__ void __launch_bounds__(128)
rms_mix5(const float* __restrict__ h, const float* __restrict__ lnw,
         const float* __restrict__ mix,
         __nv_bfloat16* __restrict__ xh, __nv_bfloat16* __restrict__ xl) {
    int row = blockIdx.x, tid = threadIdx.x;
    int t = row & (Tt - 1);
    float4 a = ((const float4*)(h + (size_t)row * Dd))[tid];
    float4 p = (t == 0) ? make_float4(0, 0, 0, 0)
                        : ((const float4*)(h + (size_t)(row - 1) * Dd))[tid];
    float sc_ = a.x*a.x + a.y*a.y + a.z*a.z + a.w*a.w;
    float sp_ = p.x*p.x + p.y*p.y + p.z*p.z + p.w*p.w;
    #pragma unroll
    for (int s = 16; s > 0; s >>= 1) {
        sc_ += __shfl_xor_sync(0xffffffffu, sc_, s);
        sp_ += __shfl_xor_sync(0xffffffffu, sp_, s);
    }
    __shared__ float rc[4], rp[4];
    if ((tid & 31) == 0) { rc[tid >> 5] = sc_; rp[tid >> 5] = sp_; }
    __syncthreads();
    float totc = rc[0] + rc[1] + rc[2] + rc[3];
    float totp = rp[0] + rp[1] + rp[2] + rp[3];
    float scc = rsqrtf(totc * (1.0f / Dd) + 1e-6f);
    float scp = (t == 0) ? 0.0f : rsqrtf(totp * (1.0f / Dd) + 1e-6f);
    float4 wv = ((const float4*)lnw)[tid];
    float cn[4] = {a.x * scc * wv.x, a.y * scc * wv.y, a.z * scc * wv.z, a.w * scc * wv.w};
    float pn[4] = {p.x * scp * wv.x, p.y * scp * wv.y, p.z * scp * wv.z, p.w * scp * wv.w};
    int c0 = tid * 4;
    size_t ro = (size_t)row * Dd + c0;
    #pragma unroll
    for (int j = 0; j < 5; j++) {
        #pragma unroll
        for (int i = 0; i < 4; i++) {
            float v = fmaf(pn[i] - cn[i], mix[j * Dd + c0 + i], cn[i]);
            float hv = __bfloat162float(__float2bfloat16(v));
            xh[(size_t)j * ND + ro + i] = __float2bfloat16(v);
            xl[(size_t)j * ND + ro + i] = __float2bfloat16(v - hv);
        }
    }
}

// hi/lo-out rmsnorm -> bf16 (feeds FFN W1)
__global__ void rmsnorm_split_kernel(const float* __restrict__ x,
                                     const float* __restrict__ w,
                                     __nv_bfloat16* __restrict__ oh,
                                     __nv_bfloat16* __restrict__ ol) {
    int row = blockIdx.x;
    int tid = threadIdx.x;
    float4 a = ((const float4*)(x + (size_t)row * Dd))[tid];
    float ss = a.x*a.x + a.y*a.y + a.z*a.z + a.w*a.w;
    #pragma unroll
    for (int s = 16; s > 0; s >>= 1) ss += __shfl_xor_sync(0xffffffffu, ss, s);
    __shared__ float sred[4];
    if ((tid & 31) == 0) sred[tid >> 5] = ss;
    __syncthreads();
    float tot = sred[0] + sred[1] + sred[2] + sred[3];
    float sc  = rsqrtf(tot * (1.0f / Dd) + 1e-6f);
    float4 wv = ((const float4*)w)[tid];
    float vv[4] = {a.x * sc * wv.x, a.y * sc * wv.y, a.z * sc * wv.z, a.w * sc * wv.w};
    size_t o = (size_t)row * Dd + tid * 4;
    #pragma unroll
    for (int i = 0; i < 4; i++) {
        float h = __bfloat162float(__float2bfloat16(vv[i]));
        oh[o + i] = __float2bfloat16(vv[i]);
        ol[o + i] = __float2bfloat16(vv[i] - h);
    }
}

// hi/lo-out rmsnorm -> fp16 (feeds logits GEMM)
__global__ void rmsnorm_split_f16(const float* __restrict__ x,
                                  const float* __restrict__ w,
                                  __half* __restrict__ oh,
                                  __half* __restrict__ ol) {
    int row = blockIdx.x;
    int tid = threadIdx.x;
    float4 a = ((const float4*)(x + (size_t)row * Dd))[tid];
    float ss = a.x*a.x + a.y*a.y + a.z*a.z + a.w*a.w;
    #pragma unroll
    for (int s = 16; s > 0; s >>= 1) ss += __shfl_xor_sync(0xffffffffu, ss, s);
    __shared__ float sred[4];
    if ((tid & 31) == 0) sred[tid >> 5] = ss;
    __syncthreads();
    float tot = sred[0] + sred[1] + sred[2] + sred[3];
    float sc  = rsqrtf(tot * (1.0f / Dd) + 1e-6f);
    float4 wv = ((const float4*)w)[tid];
    float vv[4] = {a.x * sc * wv.x, a.y * sc * wv.y, a.z * sc * wv.z, a.w * sc * wv.w};
    size_t o = (size_t)row * Dd + tid * 4;
    #pragma unroll
    for (int i = 0; i < 4; i++) {
        __half h = __float2half(vv[i]);
        oh[o + i] = h;
        ol[o + i] = __float2half(vv[i] - __half2float(h));
    }
}

// =========================================================================
// WKV phase 1: per-chunk local recurrence
// =========================================================================
__global__ void __launch_bounds__(128, 3)
wkv_chunk_kernel(float* __restrict__ r, const float* __restrict__ k,
                 const float* __restrict__ v, const float* __restrict__ w,
                 const float* __restrict__ u, float* __restrict__ y,
                 float* __restrict__ Sb, float* __restrict__ wt) {
    int blk = blockIdx.x;
    int bh  = blk / NCH;
    int ch  = blk % NCH;
    int b = bh >> 2, h = bh & 3;
    int j = threadIdx.x;
    __shared__ float4 s[Dh];
    float uj = u[h * Dh + j];
    float S[Dh];
    #pragma unroll
    for (int i = 0; i < Dh; i++) S[i] = 0.0f;
    float p = 1.0f;
    size_t off = (size_t)b * Tt * Dd + (size_t)(ch * CSZ) * Dd + h * Dh + j;
    for (int t = 0; t < CSZ; t++, off += Dd) {
        float rv = r[off], kv_ = k[off], wv = w[off], vv = v[off];
        __syncthreads();
        s[j] = make_float4(rv, kv_, wv, uj);
        __syncthreads();
        r[off] = rv * p;
        p *= wv;
        float acc = 0.0f;
        #pragma unroll
        for (int i = 0; i < Dh; i++) {
            float4 q = s[i];
            float kv = q.y * vv;
            acc  = fmaf(q.x, fmaf(q.w, kv, S[i]), acc);
            S[i] = fmaf(q.z, S[i], kv);
        }
        y[off] = acc;
    }
    wt[blk * Dh + j] = p;
    size_t base = (size_t)blk * Dh * Dh;
    #pragma unroll
    for (int i = 0; i < Dh; i++) Sb[base + (size_t)i * Dh + j] = S[i];
}

// =========================================================================
// WKV phase 2: parallel elementwise scan over chunks. One thread per (bh,i,j).
// =========================================================================
__global__ void __launch_bounds__(256)
wkv_combine_kernel(float* __restrict__ Sb, const float* __restrict__ wt) {
    int idx = blockIdx.x * blockDim.x + threadIdx.x;   // over Bb*Hh*Dh*Dh
    int bh  = idx >> 14;
    int rem = idx & 16383;
    int i   = rem >> 7;
    float run = 0.0f;
    #pragma unroll 4
    for (int ch = 0; ch < NCH; ch++) {
        int blk = bh * NCH + ch;
        size_t o = ((size_t)blk << 14) + rem;
        float m = Sb[o];
        Sb[o] = run;
        run = fmaf(run, wt[blk * Dh + i], m);
    }
}

// =========================================================================
// WKV phase 3 + GroupNorm + gate fused. Block per (bh,chunk), 128 threads.
// =========================================================================
__global__ void __launch_bounds__(128, 3)
wkv_inter_gn_kernel(const float* __restrict__ rt, const float* __restrict__ Sb,
                    const float* __restrict__ y, const float* __restrict__ g,
                    const float* __restrict__ gw, const float* __restrict__ gb,
                    __nv_bfloat16* __restrict__ oh, __nv_bfloat16* __restrict__ ol) {
    int blk = blockIdx.x;
    int bh  = blk / NCH;
    int ch  = blk % NCH;
    int b = bh >> 2, h = bh & 3;
    int j = threadIdx.x;
    int lane = j & 31, wid = j >> 5;
    float Scol[Dh];
    size_t base = (size_t)blk * Dh * Dh;
    #pragma unroll
    for (int i = 0; i < Dh; i++) Scol[i] = Sb[base + (size_t)i * Dh + j];
    __shared__ float sr[Dh];
    __shared__ float r1[4], r2[4];
    int c = h * Dh + j;
    float gwj = gw[c], gbj = gb[c];
    size_t off = (size_t)b * Tt * Dd + (size_t)(ch * CSZ) * Dd + h * Dh + j;
    for (int t = 0; t < CSZ; t++, off += Dd) {
        __syncthreads();
        sr[j] = rt[off];
        __syncthreads();
        float acc = y[off];
        #pragma unroll
        for (int i = 0; i < Dh; i++) acc = fmaf(sr[i], Scol[i], acc);
        float s1 = acc, s2 = acc * acc;
        #pragma unroll
        for (int s = 16; s > 0; s >>= 1) {
            s1 += __shfl_xor_sync(0xffffffffu, s1, s);
            s2 += __shfl_xor_sync(0xffffffffu, s2, s);
        }
        if (lane == 0) { r1[wid] = s1; r2[wid] = s2; }
        __syncthreads();
        s1 = r1[0] + r1[1] + r1[2] + r1[3];
        s2 = r2[0] + r2[1] + r2[2] + r2[3];
        float mu  = s1 * (1.0f / Dh);
        float var = s2 * (1.0f / Dh) - mu * mu;
        float nrm = (acc - mu) * rsqrtf(var + 1e-5f);
        float val = fmaf(nrm, gwj, gbj) * g[off];
        float hv = __bfloat162float(__float2bfloat16(val));
        oh[off] = __float2bfloat16(val);
        ol[off] = __float2bfloat16(val - hv);
    }
}

// =========================================================================
// host driver
// =========================================================================
extern "C" void kernel_launch(void* const* d_in, const int* in_sizes, int n_in,
                              void* d_out, int out_size) {
    const int*   tokens = (const int*)  d_in[0];
    const float* embed  = (const float*)d_in[1];
    const float* ln1    = (const float*)d_in[2];
    const float* ln2    = (const float*)d_in[3];
    const float* lno    = (const float*)d_in[4];
    const float* mix    = (const float*)d_in[5];
    const float* Wr     = (const float*)d_in[6];
    const float* Wk     = (const float*)d_in[7];
    const float* Wv     = (const float*)d_in[8];
    const float* Wg     = (const float*)d_in[9];
    const float* Ww     = (const float*)d_in[10];
    const float* w0     = (const float*)d_in[11];
    const float* Wo     = (const float*)d_in[12];
    const float* u      = (const float*)d_in[13];
    const float* gnw    = (const float*)d_in[14];
    const float* gnb    = (const float*)d_in[15];
    const float* W1     = (const float*)d_in[16];
    const float* W2     = (const float*)d_in[17];
    float* out = (float*)d_out;

    float *h, *r, *k, *v, *w, *g, *y, *Sb, *wt;
    cudaGetSymbolAddress((void**)&h,  g_h);
    cudaGetSymbolAddress((void**)&r,  g_r);
    cudaGetSymbolAddress((void**)&k,  g_k);
    cudaGetSymbolAddress((void**)&v,  g_v);
    cudaGetSymbolAddress((void**)&w,  g_w);
    cudaGetSymbolAddress((void**)&g,  g_g);
    cudaGetSymbolAddress((void**)&y,  g_y);
    cudaGetSymbolAddress((void**)&Sb, g_Sb);
    cudaGetSymbolAddress((void**)&wt, g_wt);

    __nv_bfloat16 *x5h, *x5l, *ffh, *ffl, *hnh, *hnl, *gnh, *gnl;
    __nv_bfloat16 *pTh, *pTl, *oTh, *oTl, *t1h, *t1l, *t2h, *t2l;
    __half *e16, *h16h, *h16l;
    cudaGetSymbolAddress((void**)&x5h, g_x5h);
    cudaGetSymbolAddress((void**)&x5l, g_x5l);
    cudaGetSymbolAddress((void**)&ffh, g_ffh);
    cudaGetSymbolAddress((void**)&ffl, g_ffl);
    cudaGetSymbolAddress((void**)&hnh, g_hnh);
    cudaGetSymbolAddress((void**)&hnl, g_hnl);
    cudaGetSymbolAddress((void**)&gnh, g_gnh);
    cudaGetSymbolAddress((void**)&gnl, g_gnl);
    cudaGetSymbolAddress((void**)&pTh, g_pTh);
    cudaGetSymbolAddress((void**)&pTl, g_pTl);
    cudaGetSymbolAddress((void**)&oTh, g_oTh);
    cudaGetSymbolAddress((void**)&oTl, g_oTl);
    cudaGetSymbolAddress((void**)&t1h, g_1Th);
    cudaGetSymbolAddress((void**)&t1l, g_1Tl);
    cudaGetSymbolAddress((void**)&t2h, g_2Th);
    cudaGetSymbolAddress((void**)&t2l, g_2Tl);
    cudaGetSymbolAddress((void**)&e16,  g_e16);
    cudaGetSymbolAddress((void**)&h16h, g_h16h);
    cudaGetSymbolAddress((void**)&h16l, g_h16l);

    cudaFuncSetAttribute(mma_gemm2,   cudaFuncAttributeMaxDynamicSharedMemorySize, MM_SMEM2);
    cudaFuncSetAttribute(mma_gemm_h2, cudaFuncAttributeMaxDynamicSharedMemorySize, MM_SMEMH);
    cudaFuncSetAttribute(proj_mma,    cudaFuncAttributeMaxDynamicSharedMemorySize, MM_SMEM2);

    dim3 tb(32, 8);
    // launch order matters for ncu (-s 5 -c 1 => 6th launch captured = proj_mma)
    tsplit_projWo<<<dim3(16, 16, 48), tb>>>(Wr, Wk, Wv, Ww, Wg, Wo, pTh, pTl, oTh, oTl);
    tsplit<<<dim3(Ff / 32, 16, Ll), tb>>>(W1, t1h, t1l, Dd, Ff);
    tsplit<<<dim3(16, Ff / 32, Ll), tb>>>(W2, t2h, t2l, Ff, Dd);
    embed_kernel<<<(ND / 4) / 256, 256>>>(tokens, embed, h);

    dim3 gridProj(4, 32, 5);          // 64x128 tiles, 5 projections
    dim3 grid512n(4, 32);             // 64x128 tiles for N=512 GEMMs
    dim3 gridF   (16, 32);            // W1 (N=2048), 64x128 tiles
    dim3 gridV   (250, 16);           // logits, 128x128 tiles (fp16 2-pass)

    for (int l = 0; l < Ll; l++) {
        rms_mix5<<<Nrows, 128>>>(h, ln1 + l * Dd, mix + (size_t)l * 5 * Dd, x5h, x5l);

        proj_mma<<<gridProj, 256, MM_SMEM2>>>(x5h, x5l, pTh, pTl, l, w0 + l * Dd,
                                              r, k, v, w, g);

        wkv_chunk_kernel  <<<Bb * Hh * NCH, 128>>>(r, k, v, w, u + l * Hh * Dh, y, Sb, wt);
        wkv_combine_kernel<<<(Bb * Hh * Dh * Dh) / 256, 256>>>(Sb, wt);
        wkv_inter_gn_kernel<<<Bb * Hh * NCH, 128>>>(r, Sb, y, g,
                                                    gnw + l * Dd, gnb + l * Dd, gnh, gnl);

        mma_gemm2<<<grid512n, 256, MM_SMEM2>>>(gnh, gnl, oTh + (size_t)l * DDm,
                                               oTl + (size_t)l * DDm, h, nullptr, nullptr,
                                               Dd, Dd, 1, nullptr);

        rmsnorm_split_kernel<<<Nrows, 128>>>(h, ln2 + l * Dd, hnh, hnl);
        mma_gemm2<<<gridF, 256, MM_SMEM2>>>(hnh, hnl, t1h + (size_t)l * Dd * Ff,
                                            t1l + (size_t)l * Dd * Ff, nullptr, ffh, ffl,
                                            Ff, Dd, 2, nullptr);
        mma_gemm2<<<grid512n, 256, MM_SMEM2>>>(ffh, ffl, t2h + (size_t)l * Ff * Dd,
                                               t2l + (size_t)l * Ff * Dd, h, nullptr, nullptr,
                                               Dd, Ff, 1, nullptr);
    }

    esplit_f16<<<(Vv * Dd) / 256, 256>>>(embed, e16);
    rmsnorm_split_f16<<<Nrows, 128>>>(h, lno, h16h, h16l);
    mma_gemm_h2<<<gridV, 256, MM_SMEMH>>>(h16h, h16l, e16, out, Vv, Dd);
}

// round 8
// speedup vs baseline: 6.5313x; 1.0622x over previous
#include <cuda_runtime.h>
#include <cuda_bf16.h>
#include <cuda_fp16.h>
#include <math.h>
#include <stdint.h>

// ---- model constants ----
#define Vv   32000
#define Dd   512
#define Ll   8
#define Hh   4
#define Dh   128
#define Ff   2048
#define Bb   2
#define Tt   1024
#define Nrows (Bb*Tt)          // 2048
#define ND   (Nrows*Dd)        // 1048576
#define NF   (Nrows*Ff)        // 4194304
#define DDm  (Dd*Dd)
#define CSZ  32                // wkv chunk length
#define NCH  (Tt/CSZ)          // 32 chunks

// ---- fp32 scratch ----
__device__ float g_h [ND];
__device__ float g_r [ND];
__device__ float g_k [ND];
__device__ float g_v [ND];
__device__ float g_w [ND];
__device__ float g_g [ND];
__device__ float g_y [ND];
__device__ float g_Sb[(size_t)Bb*Hh*NCH*Dh*Dh];
__device__ float g_wt[Bb*Hh*NCH*Dh];

// ---- bf16 hi/lo activation buffers ([M][K] row-major) ----
__device__ __nv_bfloat16 g_x5h[5*ND], g_x5l[5*ND];
__device__ __nv_bfloat16 g_ffh[NF],  g_ffl[NF];
__device__ __nv_bfloat16 g_hnh[ND],  g_hnl[ND];
__device__ __nv_bfloat16 g_gnh[ND],  g_gnl[ND];

// ---- fp16 buffers for the 1-pass logits GEMM ----
__device__ __half g_e16[(size_t)Vv*Dd];          // embed (fp16)
__device__ __half g_h16[ND];                     // final rmsnorm (fp16)

// ---- bf16 hi/lo transposed weight caches ([N][K] row-major) ----
__device__ __nv_bfloat16 g_pTh[(size_t)Ll*5*DDm], g_pTl[(size_t)Ll*5*DDm];
__device__ __nv_bfloat16 g_oTh[(size_t)Ll*DDm],   g_oTl[(size_t)Ll*DDm];
__device__ __nv_bfloat16 g_1Th[(size_t)Ll*Dd*Ff], g_1Tl[(size_t)Ll*Dd*Ff];
__device__ __nv_bfloat16 g_2Th[(size_t)Ll*Ff*Dd], g_2Tl[(size_t)Ll*Ff*Dd];

// =========================================================================
// PTX helpers (baseline sm_80+ — legal on compute_103)
// =========================================================================
__device__ __forceinline__ uint32_t s2u(const void* p) {
    uint32_t a;
    asm("{ .reg .u64 t; cvta.to.shared.u64 t, %1; cvt.u32.u64 %0, t; }"
        : "=r"(a) : "l"(p));
    return a;
}
__device__ __forceinline__ void cp16(uint32_t d, const void* s) {
    asm volatile("cp.async.cg.shared.global [%0], [%1], 16;" :: "r"(d), "l"(s));
}
__device__ __forceinline__ void ldm_x4(uint32_t* r, uint32_t addr) {
    asm volatile("ldmatrix.sync.aligned.m8n8.x4.shared.b16 {%0,%1,%2,%3}, [%4];"
        : "=r"(r[0]), "=r"(r[1]), "=r"(r[2]), "=r"(r[3]) : "r"(addr));
}
__device__ __forceinline__ void mma_bf16(float* d, const uint32_t* a, const uint32_t* b) {
    asm volatile(
        "mma.sync.aligned.m16n8k16.row.col.f32.bf16.bf16.f32 "
        "{%0,%1,%2,%3}, {%4,%5,%6,%7}, {%8,%9}, {%0,%1,%2,%3};"
        : "+f"(d[0]), "+f"(d[1]), "+f"(d[2]), "+f"(d[3])
        : "r"(a[0]), "r"(a[1]), "r"(a[2]), "r"(a[3]), "r"(b[0]), "r"(b[1]));
}
__device__ __forceinline__ void mma_f16(float* d, const uint32_t* a, const uint32_t* b) {
    asm volatile(
        "mma.sync.aligned.m16n8k16.row.col.f32.f16.f16.f32 "
        "{%0,%1,%2,%3}, {%4,%5,%6,%7}, {%8,%9}, {%0,%1,%2,%3};"
        : "+f"(d[0]), "+f"(d[1]), "+f"(d[2]), "+f"(d[3])
        : "r"(a[0]), "r"(a[1]), "r"(a[2]), "r"(a[3]), "r"(b[0]), "r"(b[1]));
}

#define SROWB  144          // padded row stride (64 elems * 2B = 128B + 16B pad)
#define MM_SMEM2 110592     // MF=2 3-pass: 2 stages * (2*64 + 2*128) rows * 144B
#define MM_SMEM1 73728      // MF=4 1-pass: 2 stages * (1*128 + 1*128) rows * 144B

// =========================================================================
// multi-pass mma GEMM. CTA tile (MF*32) x 128, K-step 64, 2 stages.
// NPASS=3: A hi/lo, B hi/lo (3 mma passes). NPASS=1: A hi, B hi only.
// FP16 selects f16 vs bf16 mma.
// epi: 0=store fp32, 1=add fp32, 2=gelu->hi/lo bf16, 3=wact, 4=silu
// =========================================================================
template<int MF, int NPASS, bool FP16>
__device__ __forceinline__ void mma_gemm_body(
    const void* __restrict__ Ahv, const void* __restrict__ Alv,
    const void* __restrict__ Bhv, const void* __restrict__ Blv,
    float* __restrict__ C, __nv_bfloat16* __restrict__ Ch, __nv_bfloat16* __restrict__ Cl,
    int N, int K, int epi, const float* __restrict__ aux)
{
    const __nv_bfloat16* Ah = (const __nv_bfloat16*)Ahv;
    const __nv_bfloat16* Al = (const __nv_bfloat16*)Alv;
    const __nv_bfloat16* Bh = (const __nv_bfloat16*)Bhv;
    const __nv_bfloat16* Bl = (const __nv_bfloat16*)Blv;

    extern __shared__ char sm[];
    uint32_t sb = s2u(sm);
    const int BM  = MF * 32;
    const int NA  = (NPASS >= 2) ? 2 : 1;
    const int NB  = (NPASS == 3) ? 2 : 1;
    const int AB  = BM * SROWB;          // bytes per A array
    const int BB  = 128 * SROWB;         // bytes per B array
    const int STG = NA * AB + NB * BB;   // stage bytes
    const int AH_OFF = 0, AL_OFF = AB, BH_OFF = NA * AB, BL_OFF = NA * AB + BB;

    int tid = threadIdx.x, lane = tid & 31, wid = tid >> 5;
    int m0 = blockIdx.y * BM, n0 = blockIdx.x * 128;
    int m0w = (wid & 1) * (MF * 16), n0w = (wid >> 1) * 32;

    float acc[MF][4][4];
    #pragma unroll
    for (int a = 0; a < MF; a++)
        #pragma unroll
        for (int b = 0; b < 4; b++)
            #pragma unroll
            for (int c = 0; c < 4; c++) acc[a][b][c] = 0.0f;

    const int nt = K >> 6;               // K / 64

    // prologue: stage 0
    {
        uint32_t base = sb;
        #pragma unroll
        for (int i = 0; i < MF; i++) {
            int id = tid + i * 256;
            int row = id >> 3, c = id & 7;
            uint32_t so = row * SROWB + c * 16;
            size_t ga = (size_t)(m0 + row) * K + c * 8;
            cp16(base + AH_OFF + so, Ah + ga);
            if (NPASS >= 2) cp16(base + AL_OFF + so, Al + ga);
        }
        #pragma unroll
        for (int i = 0; i < 4; i++) {
            int id = tid + i * 256;
            int row = id >> 3, c = id & 7;
            uint32_t so = row * SROWB + c * 16;
            size_t gb = (size_t)(n0 + row) * K + c * 8;
            cp16(base + BH_OFF + so, Bh + gb);
            if (NPASS == 3) cp16(base + BL_OFF + so, Bl + gb);
        }
        asm volatile("cp.async.commit_group;" ::: "memory");
    }

    for (int t = 0; t < nt; t++) {
        if (t + 1 < nt) {
            int k0 = (t + 1) << 6;
            uint32_t base = sb + ((t + 1) & 1) * STG;
            #pragma unroll
            for (int i = 0; i < MF; i++) {
                int id = tid + i * 256;
                int row = id >> 3, c = id & 7;
                uint32_t so = row * SROWB + c * 16;
                size_t ga = (size_t)(m0 + row) * K + k0 + c * 8;
                cp16(base + AH_OFF + so, Ah + ga);
                if (NPASS >= 2) cp16(base + AL_OFF + so, Al + ga);
            }
            #pragma unroll
            for (int i = 0; i < 4; i++) {
                int id = tid + i * 256;
                int row = id >> 3, c = id & 7;
                uint32_t so = row * SROWB + c * 16;
                size_t gb = (size_t)(n0 + row) * K + k0 + c * 8;
                cp16(base + BH_OFF + so, Bh + gb);
                if (NPASS == 3) cp16(base + BL_OFF + so, Bl + gb);
            }
            asm volatile("cp.async.commit_group;" ::: "memory");
            asm volatile("cp.async.wait_group 1;" ::: "memory");
        } else {
            asm volatile("cp.async.wait_group 0;" ::: "memory");
        }
        __syncthreads();

        uint32_t base = sb + (t & 1) * STG;
        #pragma unroll
        for (int kk = 0; kk < 4; kk++) {
            uint32_t aoff = (uint32_t)((m0w + (lane & 15)) * SROWB
                           + kk * 32 + (lane >> 4) * 16);
            uint32_t boff = (uint32_t)((n0w + (lane & 7) + ((lane >> 4) << 3)) * SROWB
                           + kk * 32 + ((lane >> 3) & 1) * 16);
            uint32_t aH[MF][4], aL[MF][4], bH[2][4], bL[2][4];
            #pragma unroll
            for (int mf = 0; mf < MF; mf++)
                ldm_x4(aH[mf], base + AH_OFF + aoff + mf * 16 * SROWB);
            #pragma unroll
            for (int bb = 0; bb < 2; bb++)
                ldm_x4(bH[bb], base + BH_OFF + boff + bb * 16 * SROWB);
            #pragma unroll
            for (int mf = 0; mf < MF; mf++)
                #pragma unroll
                for (int nf = 0; nf < 4; nf++) {
                    if (FP16) mma_f16 (acc[mf][nf], aH[mf], &bH[nf >> 1][(nf & 1) * 2]);
                    else      mma_bf16(acc[mf][nf], aH[mf], &bH[nf >> 1][(nf & 1) * 2]);
                }
            if (NPASS >= 2) {
                #pragma unroll
                for (int mf = 0; mf < MF; mf++)
                    ldm_x4(aL[mf], base + AL_OFF + aoff + mf * 16 * SROWB);
                #pragma unroll
                for (int mf = 0; mf < MF; mf++)
                    #pragma unroll
                    for (int nf = 0; nf < 4; nf++) {
                        if (FP16) mma_f16 (acc[mf][nf], aL[mf], &bH[nf >> 1][(nf & 1) * 2]);
                        else      mma_bf16(acc[mf][nf], aL[mf], &bH[nf >> 1][(nf & 1) * 2]);
                    }
            }
            if (NPASS == 3) {
                #pragma unroll
                for (int bb = 0; bb < 2; bb++)
                    ldm_x4(bL[bb], base + BL_OFF + boff + bb * 16 * SROWB);
                #pragma unroll
                for (int mf = 0; mf < MF; mf++)
                    #pragma unroll
                    for (int nf = 0; nf < 4; nf++) {
                        if (FP16) mma_f16 (acc[mf][nf], aH[mf], &bL[nf >> 1][(nf & 1) * 2]);
                        else      mma_bf16(acc[mf][nf], aH[mf], &bL[nf >> 1][(nf & 1) * 2]);
                    }
            }
        }
        __syncthreads();
    }

    // ---- epilogue ----
    int qr = lane >> 2, qc = (lane & 3) * 2;
    #pragma unroll
    for (int mf = 0; mf < MF; mf++) {
        #pragma unroll
        for (int nf = 0; nf < 4; nf++) {
            #pragma unroll
            for (int half = 0; half < 2; half++) {
                int row = m0 + m0w + mf * 16 + qr + half * 8;
                int col = n0 + n0w + nf * 8 + qc;
                float x = acc[mf][nf][half * 2 + 0];
                float y = acc[mf][nf][half * 2 + 1];
                size_t o = (size_t)row * N + col;
                if (epi == 0) {
                    *(float2*)(C + o) = make_float2(x, y);
                } else if (epi == 1) {
                    float2 old = *(const float2*)(C + o);
                    *(float2*)(C + o) = make_float2(old.x + x, old.y + y);
                } else if (epi == 2) {
                    x = 0.5f * x * (1.0f + erff(x * 0.70710678118654752f));
                    y = 0.5f * y * (1.0f + erff(y * 0.70710678118654752f));
                    __nv_bfloat162 hv = __floats2bfloat162_rn(x, y);
                    float lx = x - __bfloat162float(__low2bfloat16(hv));
                    float ly = y - __bfloat162float(__high2bfloat16(hv));
                    *(__nv_bfloat162*)(Ch + o) = hv;
                    *(__nv_bfloat162*)(Cl + o) = __floats2bfloat162_rn(lx, ly);
                } else if (epi == 3) {
                    x = expf(-expf(x + aux[col]));
                    y = expf(-expf(y + aux[col + 1]));
                    *(float2*)(C + o) = make_float2(x, y);
                } else {
                    x = x / (1.0f + expf(-x));
                    y = y / (1.0f + expf(-y));
                    *(float2*)(C + o) = make_float2(x, y);
                }
            }
        }
    }
}

__global__ void __launch_bounds__(256, 2)
mma_gemm2(const __nv_bfloat16* __restrict__ Ah, const __nv_bfloat16* __restrict__ Al,
          const __nv_bfloat16* __restrict__ Bh, const __nv_bfloat16* __restrict__ Bl,
          float* __restrict__ C, __nv_bfloat16* __restrict__ Ch,
          __nv_bfloat16* __restrict__ Cl, int N, int K, int epi,
          const float* __restrict__ aux) {
    mma_gemm_body<2, 3, false>(Ah, Al, Bh, Bl, C, Ch, Cl, N, K, epi, aux);
}

// fp16 1-pass GEMM (logits): A fp16, B fp16
__global__ void __launch_bounds__(256, 2)
mma_gemm_h1(const __half* __restrict__ Ah, const __half* __restrict__ Bh,
            float* __restrict__ C, int N, int K) {
    mma_gemm_body<4, 1, true>(Ah, nullptr, Bh, nullptr, C, nullptr, nullptr, N, K, 0, nullptr);
}

// batched 5-projection: z selects A slice / weight / output / epilogue
__global__ void __launch_bounds__(256, 2)
proj_mma(const __nv_bfloat16* __restrict__ x5h, const __nv_bfloat16* __restrict__ x5l,
         const __nv_bfloat16* __restrict__ Ph, const __nv_bfloat16* __restrict__ Pl,
         int l, const float* __restrict__ w0,
         float* __restrict__ Cr, float* __restrict__ Ck, float* __restrict__ Cv,
         float* __restrict__ Cw, float* __restrict__ Cg) {
    int z = blockIdx.z;
    size_t wo = ((size_t)l * 5 + z) * DDm;
    float* C = (z == 0) ? Cr : (z == 1) ? Ck : (z == 2) ? Cv : (z == 3) ? Cw : Cg;
    int epi = (z == 3) ? 3 : (z == 4) ? 4 : 0;
    mma_gemm_body<2, 3, false>(x5h + (size_t)z * ND, x5l + (size_t)z * ND,
                               Ph + wo, Pl + wo, C, nullptr, nullptr, Dd, Dd, epi, w0);
}

// =========================================================================
// weight prep: transpose [K,N] -> [N,K] with bf16 hi/lo split
// =========================================================================
__global__ void tsplit(const float* __restrict__ W, __nv_bfloat16* __restrict__ oh,
                       __nv_bfloat16* __restrict__ ol, int K, int N) {
    __shared__ float ts[32][33];
    size_t mo = (size_t)blockIdx.z * K * N;
    int n0 = blockIdx.x * 32, k0 = blockIdx.y * 32;
    int tx = threadIdx.x, ty = threadIdx.y;
    #pragma unroll
    for (int r = 0; r < 4; r++)
        ts[ty + 8 * r][tx] = W[mo + (size_t)(k0 + ty + 8 * r) * N + n0 + tx];
    __syncthreads();
    #pragma unroll
    for (int r = 0; r < 4; r++) {
        float a = ts[tx][ty + 8 * r];
        float h = __bfloat162float(__float2bfloat16(a));
        size_t o = mo + (size_t)(n0 + ty + 8 * r) * K + k0 + tx;
        oh[o] = __float2bfloat16(a);
        ol[o] = __float2bfloat16(a - h);
    }
}

// proj (z<40: 5 weights x 8 layers) + Wo (z in [40,48))
__global__ void tsplit_projWo(const float* __restrict__ Wr, const float* __restrict__ Wk,
                              const float* __restrict__ Wv, const float* __restrict__ Ww,
                              const float* __restrict__ Wg, const float* __restrict__ Wo,
                              __nv_bfloat16* __restrict__ ph, __nv_bfloat16* __restrict__ pl,
                              __nv_bfloat16* __restrict__ ohd, __nv_bfloat16* __restrict__ old_) {
    __shared__ float ts[32][33];
    int z = blockIdx.z;
    const float* W;
    __nv_bfloat16 *oh, *ol;
    size_t mo;
    if (z < 40) {
        int p = z % 5, l = z / 5;
        W = ((p == 0) ? Wr : (p == 1) ? Wk : (p == 2) ? Wv :
             (p == 3) ? Ww : Wg) + (size_t)l * DDm;
        mo = (size_t)z * DDm;
        oh = ph; ol = pl;
    } else {
        int l = z - 40;
        W = Wo + (size_t)l * DDm;
        mo = (size_t)l * DDm;
        oh = ohd; ol = old_;
    }
    int n0 = blockIdx.x * 32, k0 = blockIdx.y * 32;
    int tx = threadIdx.x, ty = threadIdx.y;
    #pragma unroll
    for (int r = 0; r < 4; r++)
        ts[ty + 8 * r][tx] = W[(size_t)(k0 + ty + 8 * r) * Dd + n0 + tx];
    __syncthreads();
    #pragma unroll
    for (int r = 0; r < 4; r++) {
        float a = ts[tx][ty + 8 * r];
        float h = __bfloat162float(__float2bfloat16(a));
        size_t o = mo + (size_t)(n0 + ty + 8 * r) * Dd + k0 + tx;
        oh[o] = __float2bfloat16(a);
        ol[o] = __float2bfloat16(a - h);
    }
}

__global__ void esplit_f16(const float* __restrict__ e, __half* __restrict__ e16) {
    int idx = blockIdx.x * blockDim.x + threadIdx.x;
    e16[idx] = __float2half(e[idx]);
}

// =========================================================================
// embedding gather
// =========================================================================
__global__ void embed_kernel(const int* __restrict__ tok,
                             const float* __restrict__ emb,
                             float* __restrict__ h) {
    int idx = blockIdx.x * blockDim.x + threadIdx.x;
    int row = idx >> 7;
    int c4  = idx & 127;
    ((float4*)h)[idx] = ((const float4*)emb)[(size_t)tok[row] * 128 + c4];
}

// =========================================================================
// fused rmsnorm + token-shift + 5-way lerp -> hi/lo bf16. Block per row.
// =========================================================================
__global__ void __launch_bounds__(128)
rms_mix5(const float* __restrict__ h, const float* __restrict__ lnw,
         const float* __restrict__ mix,
         __nv_bfloat16* __restrict__ xh, __nv_bfloat16* __restrict__ xl) {
    int row = blockIdx.x, tid = threadIdx.x;
    int t = row & (Tt - 1);
    float4 a = ((const float4*)(h + (size_t)row * Dd))[tid];
    float4 p = (t == 0) ? make_float4(0, 0, 0, 0)
                        : ((const float4*)(h + (size_t)(row - 1) * Dd))[tid];
    float sc_ = a.x*a.x + a.y*a.y + a.z*a.z + a.w*a.w;
    float sp_ = p.x*p.x + p.y*p.y + p.z*p.z + p.w*p.w;
    #pragma unroll
    for (int s = 16; s > 0; s >>= 1) {
        sc_ += __shfl_xor_sync(0xffffffffu, sc_, s);
        sp_ += __shfl_xor_sync(0xffffffffu, sp_, s);
    }
    __shared__ float rc[4], rp[4];
    if ((tid & 31) == 0) { rc[tid >> 5] = sc_; rp[tid >> 5] = sp_; }
    __syncthreads();
    float totc = rc[0] + rc[1] + rc[2] + rc[3];
    float totp = rp[0] + rp[1] + rp[2] + rp[3];
    float scc = rsqrtf(totc * (1.0f / Dd) + 1e-6f);
    float scp = (t == 0) ? 0.0f : rsqrtf(totp * (1.0f / Dd) + 1e-6f);
    float4 wv = ((const float4*)lnw)[tid];
    float cn[4] = {a.x * scc * wv.x, a.y * scc * wv.y, a.z * scc * wv.z, a.w * scc * wv.w};
    float pn[4] = {p.x * scp * wv.x, p.y * scp * wv.y, p.z * scp * wv.z, p.w * scp * wv.w};
    int c0 = tid * 4;
    size_t ro = (size_t)row * Dd + c0;
    #pragma unroll
    for (int j = 0; j < 5; j++) {
        #pragma unroll
        for (int i = 0; i < 4; i++) {
            float v = fmaf(pn[i] - cn[i], mix[j * Dd + c0 + i], cn[i]);
            float hv = __bfloat162float(__float2bfloat16(v));
            xh[(size_t)j * ND + ro + i] = __float2bfloat16(v);
            xl[(size_t)j * ND + ro + i] = __float2bfloat16(v - hv);
        }
    }
}

// hi/lo-out rmsnorm -> bf16 (feeds FFN W1)
__global__ void rmsnorm_split_kernel(const float* __restrict__ x,
                                     const float* __restrict__ w,
                                     __nv_bfloat16* __restrict__ oh,
                                     __nv_bfloat16* __restrict__ ol) {
    int row = blockIdx.x;
    int tid = threadIdx.x;
    float4 a = ((const float4*)(x + (size_t)row * Dd))[tid];
    float ss = a.x*a.x + a.y*a.y + a.z*a.z + a.w*a.w;
    #pragma unroll
    for (int s = 16; s > 0; s >>= 1) ss += __shfl_xor_sync(0xffffffffu, ss, s);
    __shared__ float sred[4];
    if ((tid & 31) == 0) sred[tid >> 5] = ss;
    __syncthreads();
    float tot = sred[0] + sred[1] + sred[2] + sred[3];
    float sc  = rsqrtf(tot * (1.0f / Dd) + 1e-6f);
    float4 wv = ((const float4*)w)[tid];
    float vv[4] = {a.x * sc * wv.x, a.y * sc * wv.y, a.z * sc * wv.z, a.w * sc * wv.w};
    size_t o = (size_t)row * Dd + tid * 4;
    #pragma unroll
    for (int i = 0; i < 4; i++) {
        float h = __bfloat162float(__float2bfloat16(vv[i]));
        oh[o + i] = __float2bfloat16(vv[i]);
        ol[o + i] = __float2bfloat16(vv[i] - h);
    }
}

// fp16-out rmsnorm (feeds 1-pass logits GEMM)
__global__ void rmsnorm_f16(const float* __restrict__ x,
                            const float* __restrict__ w,
                            __half* __restrict__ oh) {
    int row = blockIdx.x;
    int tid = threadIdx.x;
    float4 a = ((const float4*)(x + (size_t)row * Dd))[tid];
    float ss = a.x*a.x + a.y*a.y + a.z*a.z + a.w*a.w;
    #pragma unroll
    for (int s = 16; s > 0; s >>= 1) ss += __shfl_xor_sync(0xffffffffu, ss, s);
    __shared__ float sred[4];
    if ((tid & 31) == 0) sred[tid >> 5] = ss;
    __syncthreads();
    float tot = sred[0] + sred[1] + sred[2] + sred[3];
    float sc  = rsqrtf(tot * (1.0f / Dd) + 1e-6f);
    float4 wv = ((const float4*)w)[tid];
    size_t o = (size_t)row * Dd + tid * 4;
    oh[o + 0] = __float2half(a.x * sc * wv.x);
    oh[o + 1] = __float2half(a.y * sc * wv.y);
    oh[o + 2] = __float2half(a.z * sc * wv.z);
    oh[o + 3] = __float2half(a.w * sc * wv.w);
}

// =========================================================================
// WKV phase 1: per-chunk local recurrence
// =========================================================================
__global__ void __launch_bounds__(128, 3)
wkv_chunk_kernel(float* __restrict__ r, const float* __restrict__ k,
                 const float* __restrict__ v, const float* __restrict__ w,
                 const float* __restrict__ u, float* __restrict__ y,
                 float* __restrict__ Sb, float* __restrict__ wt) {
    int blk = blockIdx.x;
    int bh  = blk / NCH;
    int ch  = blk % NCH;
    int b = bh >> 2, h = bh & 3;
    int j = threadIdx.x;
    __shared__ float4 s[Dh];
    float uj = u[h * Dh + j];
    float S[Dh];
    #pragma unroll
    for (int i = 0; i < Dh; i++) S[i] = 0.0f;
    float p = 1.0f;
    size_t off = (size_t)b * Tt * Dd + (size_t)(ch * CSZ) * Dd + h * Dh + j;
    for (int t = 0; t < CSZ; t++, off += Dd) {
        float rv = r[off], kv_ = k[off], wv = w[off], vv = v[off];
        __syncthreads();
        s[j] = make_float4(rv, kv_, wv, uj);
        __syncthreads();
        r[off] = rv * p;
        p *= wv;
        float acc = 0.0f;
        #pragma unroll
        for (int i = 0; i < Dh; i++) {
            float4 q = s[i];
            float kv = q.y * vv;
            acc  = fmaf(q.x, fmaf(q.w, kv, S[i]), acc);
            S[i] = fmaf(q.z, S[i], kv);
        }
        y[off] = acc;
    }
    wt[blk * Dh + j] = p;
    size_t base = (size_t)blk * Dh * Dh;
    #pragma unroll
    for (int i = 0; i < Dh; i++) Sb[base + (size_t)i * Dh + j] = S[i];
}

// =========================================================================
// WKV phase 2: parallel elementwise scan over chunks. One thread per (bh,i,j).
// =========================================================================
__global__ void __launch_bounds__(256)
wkv_combine_kernel(float* __restrict__ Sb, const float* __restrict__ wt) {
    int idx = blockIdx.x * blockDim.x + threadIdx.x;   // over Bb*Hh*Dh*Dh
    int bh  = idx >> 14;
    int rem = idx & 16383;
    int i   = rem >> 7;
    float run = 0.0f;
    #pragma unroll 4
    for (int ch = 0; ch < NCH; ch++) {
        int blk = bh * NCH + ch;
        size_t o = ((size_t)blk << 14) + rem;
        float m = Sb[o];
        Sb[o] = run;
        run = fmaf(run, wt[blk * Dh + i], m);
    }
}

// =========================================================================
// WKV phase 3 + GroupNorm + gate fused. Block per (bh,chunk), 128 threads.
// =========================================================================
__global__ void __launch_bounds__(128, 3)
wkv_inter_gn_kernel(const float* __restrict__ rt, const float* __restrict__ Sb,
                    const float* __restrict__ y, const float* __restrict__ g,
                    const float* __restrict__ gw, const float* __restrict__ gb,
                    __nv_bfloat16* __restrict__ oh, __nv_bfloat16* __restrict__ ol) {
    int blk = blockIdx.x;
    int bh  = blk / NCH;
    int ch  = blk % NCH;
    int b = bh >> 2, h = bh & 3;
    int j = threadIdx.x;
    int lane = j & 31, wid = j >> 5;
    float Scol[Dh];
    size_t base = (size_t)blk * Dh * Dh;
    #pragma unroll
    for (int i = 0; i < Dh; i++) Scol[i] = Sb[base + (size_t)i * Dh + j];
    __shared__ float sr[Dh];
    __shared__ float r1[4], r2[4];
    int c = h * Dh + j;
    float gwj = gw[c], gbj = gb[c];
    size_t off = (size_t)b * Tt * Dd + (size_t)(ch * CSZ) * Dd + h * Dh + j;
    for (int t = 0; t < CSZ; t++, off += Dd) {
        __syncthreads();
        sr[j] = rt[off];
        __syncthreads();
        float acc = y[off];
        #pragma unroll
        for (int i = 0; i < Dh; i++) acc = fmaf(sr[i], Scol[i], acc);
        float s1 = acc, s2 = acc * acc;
        #pragma unroll
        for (int s = 16; s > 0; s >>= 1) {
            s1 += __shfl_xor_sync(0xffffffffu, s1, s);
            s2 += __shfl_xor_sync(0xffffffffu, s2, s);
        }
        if (lane == 0) { r1[wid] = s1; r2[wid] = s2; }
        __syncthreads();
        s1 = r1[0] + r1[1] + r1[2] + r1[3];
        s2 = r2[0] + r2[1] + r2[2] + r2[3];
        float mu  = s1 * (1.0f / Dh);
        float var = s2 * (1.0f / Dh) - mu * mu;
        float nrm = (acc - mu) * rsqrtf(var + 1e-5f);
        float val = fmaf(nrm, gwj, gbj) * g[off];
        float hv = __bfloat162float(__float2bfloat16(val));
        oh[off] = __float2bfloat16(val);
        ol[off] = __float2bfloat16(val - hv);
    }
}

// =========================================================================
// host driver
// =========================================================================
extern "C" void kernel_launch(void* const* d_in, const int* in_sizes, int n_in,
                              void* d_out, int out_size) {
    const int*   tokens = (const int*)  d_in[0];
    const float* embed  = (const float*)d_in[1];
    const float* ln1    = (const float*)d_in[2];
    const float* ln2    = (const float*)d_in[3];
    const float* lno    = (const float*)d_in[4];
    const float* mix    = (const float*)d_in[5];
    const float* Wr     = (const float*)d_in[6];
    const float* Wk     = (const float*)d_in[7];
    const float* Wv     = (const float*)d_in[8];
    const float* Wg     = (const float*)d_in[9];
    const float* Ww     = (const float*)d_in[10];
    const float* w0     = (const float*)d_in[11];
    const float* Wo     = (const float*)d_in[12];
    const float* u      = (const float*)d_in[13];
    const float* gnw    = (const float*)d_in[14];
    const float* gnb    = (const float*)d_in[15];
    const float* W1     = (const float*)d_in[16];
    const float* W2     = (const float*)d_in[17];
    float* out = (float*)d_out;

    float *h, *r, *k, *v, *w, *g, *y, *Sb, *wt;
    cudaGetSymbolAddress((void**)&h,  g_h);
    cudaGetSymbolAddress((void**)&r,  g_r);
    cudaGetSymbolAddress((void**)&k,  g_k);
    cudaGetSymbolAddress((void**)&v,  g_v);
    cudaGetSymbolAddress((void**)&w,  g_w);
    cudaGetSymbolAddress((void**)&g,  g_g);
    cudaGetSymbolAddress((void**)&y,  g_y);
    cudaGetSymbolAddress((void**)&Sb, g_Sb);
    cudaGetSymbolAddress((void**)&wt, g_wt);

    __nv_bfloat16 *x5h, *x5l, *ffh, *ffl, *hnh, *hnl, *gnh, *gnl;
    __nv_bfloat16 *pTh, *pTl, *oTh, *oTl, *t1h, *t1l, *t2h, *t2l;
    __half *e16, *h16;
    cudaGetSymbolAddress((void**)&x5h, g_x5h);
    cudaGetSymbolAddress((void**)&x5l, g_x5l);
    cudaGetSymbolAddress((void**)&ffh, g_ffh);
    cudaGetSymbolAddress((void**)&ffl, g_ffl);
    cudaGetSymbolAddress((void**)&hnh, g_hnh);
    cudaGetSymbolAddress((void**)&hnl, g_hnl);
    cudaGetSymbolAddress((void**)&gnh, g_gnh);
    cudaGetSymbolAddress((void**)&gnl, g_gnl);
    cudaGetSymbolAddress((void**)&pTh, g_pTh);
    cudaGetSymbolAddress((void**)&pTl, g_pTl);
    cudaGetSymbolAddress((void**)&oTh, g_oTh);
    cudaGetSymbolAddress((void**)&oTl, g_oTl);
    cudaGetSymbolAddress((void**)&t1h, g_1Th);
    cudaGetSymbolAddress((void**)&t1l, g_1Tl);
    cudaGetSymbolAddress((void**)&t2h, g_2Th);
    cudaGetSymbolAddress((void**)&t2l, g_2Tl);
    cudaGetSymbolAddress((void**)&e16, g_e16);
    cudaGetSymbolAddress((void**)&h16, g_h16);

    cudaFuncSetAttribute(mma_gemm2,   cudaFuncAttributeMaxDynamicSharedMemorySize, MM_SMEM2);
    cudaFuncSetAttribute(mma_gemm_h1, cudaFuncAttributeMaxDynamicSharedMemorySize, MM_SMEM1);
    cudaFuncSetAttribute(proj_mma,    cudaFuncAttributeMaxDynamicSharedMemorySize, MM_SMEM2);

    dim3 tb(32, 8);
    dim3 gridProj(4, 32, 5);          // 64x128 tiles, 5 projections
    dim3 grid512n(4, 32);             // 64x128 tiles for N=512 GEMMs
    dim3 gridF   (16, 32);            // W1 (N=2048), 64x128 tiles
    dim3 gridV   (250, 16);           // logits, 128x128 tiles (fp16 1-pass)

    // launch order: harness prepends 2 launches; ncu -s 5 -c 1 captures
    // global #6 = our #4 = proj_mma(l=0).
    tsplit_projWo<<<dim3(16, 16, 48), tb>>>(Wr, Wk, Wv, Ww, Wg, Wo, pTh, pTl, oTh, oTl);
    embed_kernel<<<(ND / 4) / 256, 256>>>(tokens, embed, h);
    rms_mix5<<<Nrows, 128>>>(h, ln1, mix, x5h, x5l);
    proj_mma<<<gridProj, 256, MM_SMEM2>>>(x5h, x5l, pTh, pTl, 0, w0, r, k, v, w, g);

    tsplit<<<dim3(Ff / 32, 16, Ll), tb>>>(W1, t1h, t1l, Dd, Ff);
    tsplit<<<dim3(16, Ff / 32, Ll), tb>>>(W2, t2h, t2l, Ff, Dd);
    esplit_f16<<<(Vv * Dd) / 256, 256>>>(embed, e16);

    for (int l = 0; l < Ll; l++) {
        if (l > 0) {
            rms_mix5<<<Nrows, 128>>>(h, ln1 + l * Dd, mix + (size_t)l * 5 * Dd, x5h, x5l);
            proj_mma<<<gridProj, 256, MM_SMEM2>>>(x5h, x5l, pTh, pTl, l, w0 + l * Dd,
                                                  r, k, v, w, g);
        }

        wkv_chunk_kernel  <<<Bb * Hh * NCH, 128>>>(r, k, v, w, u + l * Hh * Dh, y, Sb, wt);
        wkv_combine_kernel<<<(Bb * Hh * Dh * Dh) / 256, 256>>>(Sb, wt);
        wkv_inter_gn_kernel<<<Bb * Hh * NCH, 128>>>(r, Sb, y, g,
                                                    gnw + l * Dd, gnb + l * Dd, gnh, gnl);

        mma_gemm2<<<grid512n, 256, MM_SMEM2>>>(gnh, gnl, oTh + (size_t)l * DDm,
                                               oTl + (size_t)l * DDm, h, nullptr, nullptr,
                                               Dd, Dd, 1, nullptr);

        rmsnorm_split_kernel<<<Nrows, 128>>>(h, ln2 + l * Dd, hnh, hnl);
        mma_gemm2<<<gridF, 256, MM_SMEM2>>>(hnh, hnl, t1h + (size_t)l * Dd * Ff,
                                            t1l + (size_t)l * Dd * Ff, nullptr, ffh, ffl,
                                            Ff, Dd, 2, nullptr);
        mma_gemm2<<<grid512n, 256, MM_SMEM2>>>(ffh, ffl, t2h + (size_t)l * Ff * Dd,
                                               t2l + (size_t)l * Ff * Dd, h, nullptr, nullptr,
                                               Dd, Ff, 1, nullptr);
    }

    rmsnorm_f16<<<Nrows, 128>>>(h, lno, h16);
    mma_gemm_h1<<<gridV, 256, MM_SMEM1>>>(h16, e16, out, Vv, Dd);
}